// round 1
// baseline (speedup 1.0000x reference)
#include <cuda_runtime.h>
#include <cuda_bf16.h>
#include <math.h>
#include <stddef.h>

// Problem constants
#define B_  8
#define S_  1024
#define C_  1024
#define H_  16
#define D_  64
#define M_TOT (B_ * S_)          // 8192
#define KV_N  (2 * C_)           // 2048 (only k,v slices of qkv)

// Scratch (device globals; no runtime allocation allowed)
__device__ float g_K[(size_t)B_ * H_ * S_ * D_];   // [b][h][s][d]
__device__ float g_V[(size_t)B_ * H_ * S_ * D_];   // [b][h][s][d]
__device__ float g_A[(size_t)B_ * S_ * C_];        // attention out, [b][s][h*64+d]

// ---------------------------------------------------------------------------
// SGEMM: C = A @ B + bias.  BM=BN=128, BK=8, 256 threads, 8x8 per thread.
// mode 0: A = x [8192 x 1024], B = Wqkv+1024 (ldb=3072), N=2048,
//         epilogue scatters to g_K / g_V ([b][h][s][d]).
// mode 1: A = g_A [8192 x 1024], B = Wproj (ldb=1024), N=1024, C = d_out.
// ---------------------------------------------------------------------------
__global__ __launch_bounds__(256) void sgemm_kernel(
    const float* __restrict__ A, const float* __restrict__ Bm,
    const float* __restrict__ bias, float* __restrict__ C,
    int lda, int ldb, int mode)
{
    __shared__ float As[8][128];
    __shared__ float Bs[8][128];

    const int bm = blockIdx.y;
    const int bn = blockIdx.x;
    const int tid = threadIdx.x;
    const int tx = tid & 15;
    const int ty = tid >> 4;

    const float* Ap = (mode == 1) ? g_A : A;

    const int arow = tid >> 1;          // 0..127
    const int acol = (tid & 1) * 4;     // 0 or 4
    const int brow = tid >> 5;          // 0..7
    const int bcol = (tid & 31) * 4;    // 0..124

    const float* Aptr = Ap + (size_t)(bm * 128 + arow) * lda + acol;
    const float* Bptr = Bm + (size_t)brow * ldb + bn * 128 + bcol;

    float acc[8][8];
#pragma unroll
    for (int i = 0; i < 8; i++)
#pragma unroll
        for (int j = 0; j < 8; j++) acc[i][j] = 0.0f;

    for (int k0 = 0; k0 < 1024; k0 += 8) {
        float4 av = *(const float4*)(Aptr + k0);
        float4 bv = *(const float4*)(Bptr + (size_t)k0 * ldb);

        As[acol + 0][arow] = av.x;
        As[acol + 1][arow] = av.y;
        As[acol + 2][arow] = av.z;
        As[acol + 3][arow] = av.w;
        *(float4*)&Bs[brow][bcol] = bv;
        __syncthreads();

#pragma unroll
        for (int kk = 0; kk < 8; kk++) {
            float a[8], b[8];
            *(float4*)(a)     = *(const float4*)&As[kk][ty * 4];
            *(float4*)(a + 4) = *(const float4*)&As[kk][64 + ty * 4];
            *(float4*)(b)     = *(const float4*)&Bs[kk][tx * 4];
            *(float4*)(b + 4) = *(const float4*)&Bs[kk][64 + tx * 4];
#pragma unroll
            for (int i = 0; i < 8; i++)
#pragma unroll
                for (int j = 0; j < 8; j++) acc[i][j] += a[i] * b[j];
        }
        __syncthreads();
    }

    // epilogue
#pragma unroll
    for (int gi = 0; gi < 2; gi++) {
#pragma unroll
        for (int i = 0; i < 4; i++) {
            const int row = bm * 128 + gi * 64 + ty * 4 + i;
#pragma unroll
            for (int gj = 0; gj < 2; gj++) {
#pragma unroll
                for (int j = 0; j < 4; j++) {
                    const int col = bn * 128 + gj * 64 + tx * 4 + j;
                    float v = acc[gi * 4 + i][gj * 4 + j] + bias[col];
                    if (mode == 0) {
                        const int np = (col < C_) ? col : col - C_;
                        float* dst = (col < C_) ? g_K : g_V;
                        const int b = row >> 10, s = row & 1023;
                        const int h = np >> 6,  d = np & 63;
                        dst[(((size_t)(b * H_ + h) * S_) + s) * D_ + d] = v;
                    } else {
                        C[(size_t)row * C_ + col] = v;
                    }
                }
            }
        }
    }
}

// ---------------------------------------------------------------------------
// Flash attention (fp32). One block = one (b,h) and a 64-row query tile.
// q = k (reference quirk). Causal: key tiles 0..qt only.
// smem: Qs[64][64], Kts[64][68] (K transposed, padded), Vs[64][64], Ps[64][64]
// ---------------------------------------------------------------------------
#define ATT_SMEM_FLOATS (64*64 + 64*68 + 64*64 + 64*64)   // 16640
#define ATT_SMEM_BYTES  (ATT_SMEM_FLOATS * 4)             // 66560

__global__ __launch_bounds__(256) void attn_kernel()
{
    extern __shared__ float sm[];
    float* Qs  = sm;                    // [64][64]
    float* Kts = sm + 4096;             // [64][68]
    float* Vs  = Kts + 64 * 68;         // [64][64]
    float* Ps  = Vs + 4096;             // [64][64]

    const int qt = blockIdx.x;          // query tile 0..15
    const int bh = blockIdx.y;          // 0..127
    const int tid = threadIdx.x;
    const int tx = tid & 15;
    const int ty = tid >> 4;

    const float* Kb = g_K + (size_t)bh * S_ * D_;
    const float* Vb = g_V + (size_t)bh * S_ * D_;

    // Load Q tile (= K rows qt*64..) into smem
#pragma unroll
    for (int f = tid; f < 1024; f += 256) {
        const int r = f >> 4, c4 = (f & 15) << 2;
        *(float4*)&Qs[r * 64 + c4] =
            *(const float4*)&Kb[(size_t)(qt * 64 + r) * D_ + c4];
    }

    float m[4], l[4], o[4][4];
#pragma unroll
    for (int i = 0; i < 4; i++) {
        m[i] = -1e30f; l[i] = 0.0f;
#pragma unroll
        for (int j = 0; j < 4; j++) o[i][j] = 0.0f;
    }

    for (int jt = 0; jt <= qt; jt++) {
        __syncthreads();   // protect Kts/Vs/Ps from previous iteration readers

        // Load K tile transposed + V tile
#pragma unroll
        for (int f = tid; f < 1024; f += 256) {
            const int c = f >> 4, d4 = (f & 15) << 2;
            const float4 kv = *(const float4*)&Kb[(size_t)(jt * 64 + c) * D_ + d4];
            Kts[(d4 + 0) * 68 + c] = kv.x;
            Kts[(d4 + 1) * 68 + c] = kv.y;
            Kts[(d4 + 2) * 68 + c] = kv.z;
            Kts[(d4 + 3) * 68 + c] = kv.w;
            *(float4*)&Vs[c * 64 + d4] =
                *(const float4*)&Vb[(size_t)(jt * 64 + c) * D_ + d4];
        }
        __syncthreads();

        // S = Q @ K^T  (4x4 per thread: rows ty*4+i, cols tx*4+j)
        float s0[4][4];
#pragma unroll
        for (int i = 0; i < 4; i++)
#pragma unroll
            for (int j = 0; j < 4; j++) s0[i][j] = 0.0f;

#pragma unroll 8
        for (int k = 0; k < 64; k++) {
            const float4 kt = *(const float4*)&Kts[k * 68 + tx * 4];
#pragma unroll
            for (int i = 0; i < 4; i++) {
                const float q = Qs[(ty * 4 + i) * 64 + k];
                s0[i][0] += q * kt.x;
                s0[i][1] += q * kt.y;
                s0[i][2] += q * kt.z;
                s0[i][3] += q * kt.w;
            }
        }

        const float scale = 0.125f;   // 1/sqrt(64)
        const bool diag = (jt == qt);
#pragma unroll
        for (int i = 0; i < 4; i++) {
#pragma unroll
            for (int j = 0; j < 4; j++) {
                float v = s0[i][j] * scale;
                if (diag && (tx * 4 + j) > (ty * 4 + i)) v = -1e30f;
                s0[i][j] = v;
            }
        }

        // Online softmax per row (16 lanes of same ty hold the 64 cols)
#pragma unroll
        for (int i = 0; i < 4; i++) {
            float tm = fmaxf(fmaxf(s0[i][0], s0[i][1]), fmaxf(s0[i][2], s0[i][3]));
#pragma unroll
            for (int off = 8; off > 0; off >>= 1)
                tm = fmaxf(tm, __shfl_xor_sync(0xffffffffu, tm, off));
            const float mn = fmaxf(m[i], tm);
            const float p0 = __expf(s0[i][0] - mn);
            const float p1 = __expf(s0[i][1] - mn);
            const float p2 = __expf(s0[i][2] - mn);
            const float p3 = __expf(s0[i][3] - mn);
            float ts = p0 + p1 + p2 + p3;
#pragma unroll
            for (int off = 8; off > 0; off >>= 1)
                ts += __shfl_xor_sync(0xffffffffu, ts, off);
            const float alpha = __expf(m[i] - mn);
            l[i] = l[i] * alpha + ts;
            m[i] = mn;
            o[i][0] *= alpha; o[i][1] *= alpha; o[i][2] *= alpha; o[i][3] *= alpha;
            float4 pv = make_float4(p0, p1, p2, p3);
            *(float4*)&Ps[(ty * 4 + i) * 64 + tx * 4] = pv;
        }
        __syncthreads();

        // O += P @ V  (thread cols are d = tx*4+j)
#pragma unroll 8
        for (int c = 0; c < 64; c++) {
            const float4 v = *(const float4*)&Vs[c * 64 + tx * 4];
#pragma unroll
            for (int i = 0; i < 4; i++) {
                const float p = Ps[(ty * 4 + i) * 64 + c];
                o[i][0] += p * v.x;
                o[i][1] += p * v.y;
                o[i][2] += p * v.z;
                o[i][3] += p * v.w;
            }
        }
    }

    // Write normalized output directly in [B, S, C] layout
    const int b = bh >> 4, h = bh & 15;
#pragma unroll
    for (int i = 0; i < 4; i++) {
        const float inv = 1.0f / l[i];
        const int srow = qt * 64 + ty * 4 + i;
        float4 ov = make_float4(o[i][0] * inv, o[i][1] * inv,
                                o[i][2] * inv, o[i][3] * inv);
        *(float4*)&g_A[((size_t)(b * S_ + srow)) * C_ + h * 64 + tx * 4] = ov;
    }
}

// ---------------------------------------------------------------------------
extern "C" void kernel_launch(void* const* d_in, const int* in_sizes, int n_in,
                              void* d_out, int out_size)
{
    const float* x     = (const float*)d_in[0];   // [8,1024,1024]
    const float* Wqkv  = (const float*)d_in[1];   // [1024,3072]
    const float* bqkv  = (const float*)d_in[2];   // [3072]
    const float* Wproj = (const float*)d_in[3];   // [1024,1024]
    const float* bproj = (const float*)d_in[4];   // [1024]
    float* out = (float*)d_out;

    // Phase 1: KV projection (skip dead q slice): N = 2048 cols of Wqkv[:,1024:]
    {
        dim3 grid(KV_N / 128, M_TOT / 128);   // (16, 64)
        sgemm_kernel<<<grid, 256>>>(x, Wqkv + C_, bqkv + C_, nullptr,
                                    C_, 3 * C_, 0);
    }

    // Phase 2: causal attention (q = k)
    {
        cudaFuncSetAttribute(attn_kernel,
                             cudaFuncAttributeMaxDynamicSharedMemorySize,
                             ATT_SMEM_BYTES);
        dim3 grid(S_ / 64, B_ * H_);          // (16, 128)
        attn_kernel<<<grid, 256, ATT_SMEM_BYTES>>>();
    }

    // Phase 3: output projection
    {
        dim3 grid(C_ / 128, M_TOT / 128);     // (8, 64)
        sgemm_kernel<<<grid, 256>>>(nullptr, Wproj, bproj, out,
                                    C_, C_, 1);
    }
}

// round 3
// speedup vs baseline: 1.6618x; 1.6618x over previous
#include <cuda_runtime.h>
#include <cuda_bf16.h>
#include <math.h>
#include <stddef.h>
#include <stdint.h>

// Problem constants
#define B_  8
#define S_  1024
#define C_  1024
#define H_  16
#define D_  64
#define M_TOT (B_ * S_)          // 8192
#define KV_N  (2 * C_)           // 2048
#define K3    (3 * C_)           // 3072 (tripled-K for bf16x3 split GEMM)

// Scratch (device globals; no runtime allocation allowed)
__device__ float g_K[(size_t)B_ * H_ * S_ * D_];            // [b][h][s][d]
__device__ float g_V[(size_t)B_ * H_ * S_ * D_];            // [b][h][s][d]
__device__ __nv_bfloat16 g_A3 [(size_t)M_TOT * K3];         // x split   [hi|lo|hi]
__device__ __nv_bfloat16 g_B3 [(size_t)KV_N  * K3];         // Wqkv_kv^T [hi|hi|lo]
__device__ __nv_bfloat16 g_A3p[(size_t)M_TOT * K3];         // attn out  [hi|lo|hi]
__device__ __nv_bfloat16 g_B3p[(size_t)C_    * K3];         // Wproj^T   [hi|hi|lo]

// ---------------------------------------------------------------------------
// PTX helpers (all base-sm_100-legal: cp.async / ldmatrix / mma.sync)
// ---------------------------------------------------------------------------
__device__ __forceinline__ uint32_t smem_u32(const void* p) {
    uint32_t a;
    asm("{ .reg .u64 t; cvta.to.shared.u64 t, %1; cvt.u32.u64 %0, t; }" : "=r"(a) : "l"(p));
    return a;
}
__device__ __forceinline__ void cpasync16(uint32_t saddr, const void* g) {
    asm volatile("cp.async.cg.shared.global [%0], [%1], 16;" :: "r"(saddr), "l"(g) : "memory");
}
#define CP_COMMIT() asm volatile("cp.async.commit_group;" ::: "memory")
#define CP_WAIT(n)  asm volatile("cp.async.wait_group %0;" :: "n"(n) : "memory")

__device__ __forceinline__ void ldsm4(uint32_t* r, uint32_t addr) {
    asm volatile("ldmatrix.sync.aligned.m8n8.x4.shared.b16 {%0,%1,%2,%3}, [%4];"
                 : "=r"(r[0]), "=r"(r[1]), "=r"(r[2]), "=r"(r[3]) : "r"(addr));
}
__device__ __forceinline__ void mma16816(float* c, const uint32_t* a, const uint32_t* b) {
    asm volatile(
        "mma.sync.aligned.m16n8k16.row.col.f32.bf16.bf16.f32 "
        "{%0,%1,%2,%3}, {%4,%5,%6,%7}, {%8,%9}, {%0,%1,%2,%3};"
        : "+f"(c[0]), "+f"(c[1]), "+f"(c[2]), "+f"(c[3])
        : "r"(a[0]), "r"(a[1]), "r"(a[2]), "r"(a[3]), "r"(b[0]), "r"(b[1]));
}

// Swizzled smem offset for a 16B chunk of a [128 rows][64B] tile.
// Two m-rows share a 128B line; chunk index within line XOR'd with line id.
__device__ __forceinline__ uint32_t sw_off(int row, int c) {
    return (uint32_t)(((row >> 1) << 7) +
                      ((((((row & 1) << 2) | c)) ^ ((row >> 1) & 7)) << 4));
}

// ---------------------------------------------------------------------------
// bf16x3 GEMM:  C[m][n] = sum_{k'} A3[m][k'] * B3[n][k'] + bias[n]
// A3: [M][3072] bf16 (hi|lo|hi), B3: [N][3072] bf16 (hi|hi|lo).
// CTA 128x128, BK=32, 8 warps of 64x32, cp.async double buffer.
// mode 0: scatter to g_K/g_V.  mode 1: write out[m*1024+n].
// ---------------------------------------------------------------------------
#define NSTAGE (K3 / 32)          // 96

__device__ __forceinline__ void gemm_load_stage(
    const __nv_bfloat16* __restrict__ Ag, const __nv_bfloat16* __restrict__ Bg,
    int kb, uint32_t Ab, uint32_t Bb, int tid)
{
#pragma unroll
    for (int i = 0; i < 2; i++) {
        const int idx = tid + i * 256;           // 0..511
        const int r = idx >> 2, c = idx & 3;     // row 0..127, 16B chunk 0..3
        const size_t g = (size_t)r * K3 + kb * 32 + c * 8;
        cpasync16(Ab + sw_off(r, c), Ag + g);
        cpasync16(Bb + sw_off(r, c), Bg + g);
    }
}

__global__ __launch_bounds__(256, 2) void gemm_bf16x3_kernel(
    const __nv_bfloat16* __restrict__ Ag, const __nv_bfloat16* __restrict__ Bg,
    const float* __restrict__ bias, float* __restrict__ out, int mode)
{
    __shared__ __align__(1024) uint8_t smem_raw[2 * 16384];  // 2 stages x (A 8K + B 8K)
    const uint32_t smb = smem_u32(smem_raw);

    const int tid  = threadIdx.x;
    const int lane = tid & 31;
    const int wid  = tid >> 5;
    const int wm = (wid >> 2) * 64;     // warp m offset in CTA tile
    const int wn = (wid & 3) * 32;      // warp n offset
    const int bn = blockIdx.x, bm = blockIdx.y;

    const __nv_bfloat16* Arow = Ag + (size_t)(bm * 128) * K3;
    const __nv_bfloat16* Brow = Bg + (size_t)(bn * 128) * K3;

    float acc[4][4][4];
#pragma unroll
    for (int f = 0; f < 4; f++)
#pragma unroll
        for (int g = 0; g < 4; g++)
#pragma unroll
            for (int r = 0; r < 4; r++) acc[f][g][r] = 0.0f;

    gemm_load_stage(Arow, Brow, 0, smb, smb + 8192, tid);
    CP_COMMIT();

    for (int kb = 0; kb < NSTAGE; kb++) {
        const int buf = kb & 1;
        if (kb + 1 < NSTAGE) {
            const int nb = buf ^ 1;
            gemm_load_stage(Arow, Brow, kb + 1,
                            smb + nb * 16384, smb + nb * 16384 + 8192, tid);
            CP_COMMIT();
            CP_WAIT(1);
        } else {
            CP_WAIT(0);
        }
        __syncthreads();

        const uint32_t Ab = smb + buf * 16384;
        const uint32_t Bb = Ab + 8192;
#pragma unroll
        for (int ks = 0; ks < 2; ks++) {
            uint32_t a[4][4], b[4][2];
            const int ar = lane & 15;
            const int ac = ks * 2 + (lane >> 4);
#pragma unroll
            for (int f = 0; f < 4; f++)
                ldsm4(a[f], Ab + sw_off(wm + f * 16 + ar, ac));

            const int br = (lane & 7) + ((lane >> 4) << 3);
            const int bc = ks * 2 + ((lane >> 3) & 1);
#pragma unroll
            for (int p = 0; p < 2; p++) {
                uint32_t r4[4];
                ldsm4(r4, Bb + sw_off(wn + p * 16 + br, bc));
                b[2 * p][0] = r4[0]; b[2 * p][1] = r4[1];
                b[2 * p + 1][0] = r4[2]; b[2 * p + 1][1] = r4[3];
            }
#pragma unroll
            for (int f = 0; f < 4; f++)
#pragma unroll
                for (int g = 0; g < 4; g++)
                    mma16816(acc[f][g], a[f], b[g]);
        }
        __syncthreads();
    }

    // Epilogue: thread (lane) owns rows gr, gr+8 and cols 2t, 2t+1 per fragment
    const int gr = lane >> 2;
    const int tcol = (lane & 3) * 2;
#pragma unroll
    for (int f = 0; f < 4; f++) {
        const int r0 = bm * 128 + wm + f * 16 + gr;
        const int b_ = r0 >> 10, s_ = r0 & 1023;
        const int r1 = r0 + 8;
        const int b1_ = r1 >> 10, s1_ = r1 & 1023;
#pragma unroll
        for (int g = 0; g < 4; g++) {
            const int cc = wn + g * 8 + tcol;
            const int n = bn * 128 + cc;
            const float bx = bias[n], by = bias[n + 1];
            float2 v0 = make_float2(acc[f][g][0] + bx, acc[f][g][1] + by);
            float2 v1 = make_float2(acc[f][g][2] + bx, acc[f][g][3] + by);
            if (mode == 0) {
                float* dstb = (n < C_) ? g_K : g_V;
                const int np = n & (C_ - 1);
                const int h = np >> 6, d = np & 63;
                *(float2*)&dstb[(((size_t)(b_ * H_ + h) * S_) + s_) * D_ + d]  = v0;
                *(float2*)&dstb[(((size_t)(b1_ * H_ + h) * S_) + s1_) * D_ + d] = v1;
            } else {
                *(float2*)&out[(size_t)r0 * C_ + n] = v0;
                *(float2*)&out[(size_t)r1 * C_ + n] = v1;
            }
        }
    }
}

// ---------------------------------------------------------------------------
// split_x: x fp32 [8192][1024] -> g_A3 bf16 [8192][3072] as [hi | lo | hi]
// ---------------------------------------------------------------------------
__global__ __launch_bounds__(256) void split_x_kernel(const float* __restrict__ x)
{
    const int idx = blockIdx.x * 256 + threadIdx.x;   // one per 4 elements
    const int m = idx >> 8;
    const int k = (idx & 255) << 2;
    const float4 v = *(const float4*)&x[(size_t)m * C_ + k];

    __nv_bfloat162 h01 = __floats2bfloat162_rn(v.x, v.y);
    __nv_bfloat162 h23 = __floats2bfloat162_rn(v.z, v.w);
    float lx = v.x - __bfloat162float(h01.x);
    float ly = v.y - __bfloat162float(h01.y);
    float lz = v.z - __bfloat162float(h23.x);
    float lw = v.w - __bfloat162float(h23.y);
    __nv_bfloat162 l01 = __floats2bfloat162_rn(lx, ly);
    __nv_bfloat162 l23 = __floats2bfloat162_rn(lz, lw);

    __nv_bfloat16* row = g_A3 + (size_t)m * K3;
    *(__nv_bfloat162*)(row + k)            = h01;
    *(__nv_bfloat162*)(row + k + 2)        = h23;
    *(__nv_bfloat162*)(row + C_ + k)       = l01;
    *(__nv_bfloat162*)(row + C_ + k + 2)   = l23;
    *(__nv_bfloat162*)(row + 2 * C_ + k)     = h01;
    *(__nv_bfloat162*)(row + 2 * C_ + k + 2) = h23;
}

// ---------------------------------------------------------------------------
// tsplit: W fp32 [1024][srcld] column block -> dst bf16 [n][3072] as [hi|hi|lo]
// ---------------------------------------------------------------------------
__global__ __launch_bounds__(256) void tsplit_kernel(
    const float* __restrict__ src, __nv_bfloat16* __restrict__ dst, int srcld)
{
    __shared__ float t[32][33];
    const int n0 = blockIdx.x * 32, k0 = blockIdx.y * 32;
    const int tx = threadIdx.x & 31, ty = threadIdx.x >> 5;
#pragma unroll
    for (int i = 0; i < 4; i++)
        t[ty + i * 8][tx] = src[(size_t)(k0 + ty + i * 8) * srcld + n0 + tx];
    __syncthreads();
#pragma unroll
    for (int i = 0; i < 4; i++) {
        const int n = n0 + ty + i * 8;
        const int k = k0 + tx;
        const float v = t[tx][ty + i * 8];
        __nv_bfloat16 h = __float2bfloat16(v);
        __nv_bfloat16 l = __float2bfloat16(v - __bfloat162float(h));
        __nv_bfloat16* row = dst + (size_t)n * K3;
        row[k] = h;
        row[C_ + k] = h;
        row[2 * C_ + k] = l;
    }
}

// ---------------------------------------------------------------------------
// Flash attention (fp32), epilogue writes pre-split bf16x3 rows into g_A3p.
// ---------------------------------------------------------------------------
#define ATT_SMEM_FLOATS (64*64 + 64*68 + 64*64 + 64*64)
#define ATT_SMEM_BYTES  (ATT_SMEM_FLOATS * 4)

__global__ __launch_bounds__(256) void attn_kernel()
{
    extern __shared__ float smf[];
    float* Qs  = smf;
    float* Kts = smf + 4096;
    float* Vs  = Kts + 64 * 68;
    float* Ps  = Vs + 4096;

    const int qt = blockIdx.x;
    const int bh = blockIdx.y;
    const int tid = threadIdx.x;
    const int tx = tid & 15;
    const int ty = tid >> 4;

    const float* Kb = g_K + (size_t)bh * S_ * D_;
    const float* Vb = g_V + (size_t)bh * S_ * D_;

#pragma unroll
    for (int f = tid; f < 1024; f += 256) {
        const int r = f >> 4, c4 = (f & 15) << 2;
        *(float4*)&Qs[r * 64 + c4] =
            *(const float4*)&Kb[(size_t)(qt * 64 + r) * D_ + c4];
    }

    float m[4], l[4], o[4][4];
#pragma unroll
    for (int i = 0; i < 4; i++) {
        m[i] = -1e30f; l[i] = 0.0f;
#pragma unroll
        for (int j = 0; j < 4; j++) o[i][j] = 0.0f;
    }

    for (int jt = 0; jt <= qt; jt++) {
        __syncthreads();
#pragma unroll
        for (int f = tid; f < 1024; f += 256) {
            const int c = f >> 4, d4 = (f & 15) << 2;
            const float4 kv = *(const float4*)&Kb[(size_t)(jt * 64 + c) * D_ + d4];
            Kts[(d4 + 0) * 68 + c] = kv.x;
            Kts[(d4 + 1) * 68 + c] = kv.y;
            Kts[(d4 + 2) * 68 + c] = kv.z;
            Kts[(d4 + 3) * 68 + c] = kv.w;
            *(float4*)&Vs[c * 64 + d4] =
                *(const float4*)&Vb[(size_t)(jt * 64 + c) * D_ + d4];
        }
        __syncthreads();

        float s0[4][4];
#pragma unroll
        for (int i = 0; i < 4; i++)
#pragma unroll
            for (int j = 0; j < 4; j++) s0[i][j] = 0.0f;

#pragma unroll 8
        for (int k = 0; k < 64; k++) {
            const float4 kt = *(const float4*)&Kts[k * 68 + tx * 4];
#pragma unroll
            for (int i = 0; i < 4; i++) {
                const float q = Qs[(ty * 4 + i) * 64 + k];
                s0[i][0] += q * kt.x;
                s0[i][1] += q * kt.y;
                s0[i][2] += q * kt.z;
                s0[i][3] += q * kt.w;
            }
        }

        const float scale = 0.125f;
        const bool diag = (jt == qt);
#pragma unroll
        for (int i = 0; i < 4; i++) {
#pragma unroll
            for (int j = 0; j < 4; j++) {
                float v = s0[i][j] * scale;
                if (diag && (tx * 4 + j) > (ty * 4 + i)) v = -1e30f;
                s0[i][j] = v;
            }
        }

#pragma unroll
        for (int i = 0; i < 4; i++) {
            float tm = fmaxf(fmaxf(s0[i][0], s0[i][1]), fmaxf(s0[i][2], s0[i][3]));
#pragma unroll
            for (int off = 8; off > 0; off >>= 1)
                tm = fmaxf(tm, __shfl_xor_sync(0xffffffffu, tm, off));
            const float mn = fmaxf(m[i], tm);
            const float p0 = __expf(s0[i][0] - mn);
            const float p1 = __expf(s0[i][1] - mn);
            const float p2 = __expf(s0[i][2] - mn);
            const float p3 = __expf(s0[i][3] - mn);
            float ts = p0 + p1 + p2 + p3;
#pragma unroll
            for (int off = 8; off > 0; off >>= 1)
                ts += __shfl_xor_sync(0xffffffffu, ts, off);
            const float alpha = __expf(m[i] - mn);
            l[i] = l[i] * alpha + ts;
            m[i] = mn;
            o[i][0] *= alpha; o[i][1] *= alpha; o[i][2] *= alpha; o[i][3] *= alpha;
            float4 pv = make_float4(p0, p1, p2, p3);
            *(float4*)&Ps[(ty * 4 + i) * 64 + tx * 4] = pv;
        }
        __syncthreads();

#pragma unroll 8
        for (int c = 0; c < 64; c++) {
            const float4 v = *(const float4*)&Vs[c * 64 + tx * 4];
#pragma unroll
            for (int i = 0; i < 4; i++) {
                const float p = Ps[(ty * 4 + i) * 64 + c];
                o[i][0] += p * v.x;
                o[i][1] += p * v.y;
                o[i][2] += p * v.z;
                o[i][3] += p * v.w;
            }
        }
    }

    // Epilogue: write pre-split bf16x3 rows [hi | lo | hi] into g_A3p
    const int b = bh >> 4, h = bh & 15;
#pragma unroll
    for (int i = 0; i < 4; i++) {
        const float inv = 1.0f / l[i];
        const float v0 = o[i][0] * inv, v1 = o[i][1] * inv;
        const float v2 = o[i][2] * inv, v3 = o[i][3] * inv;
        __nv_bfloat162 h01 = __floats2bfloat162_rn(v0, v1);
        __nv_bfloat162 h23 = __floats2bfloat162_rn(v2, v3);
        __nv_bfloat162 l01 = __floats2bfloat162_rn(v0 - __bfloat162float(h01.x),
                                                   v1 - __bfloat162float(h01.y));
        __nv_bfloat162 l23 = __floats2bfloat162_rn(v2 - __bfloat162float(h23.x),
                                                   v3 - __bfloat162float(h23.y));
        const int srow = qt * 64 + ty * 4 + i;
        __nv_bfloat16* row = g_A3p + (size_t)(b * S_ + srow) * K3 + h * 64 + tx * 4;
        *(__nv_bfloat162*)(row)              = h01;
        *(__nv_bfloat162*)(row + 2)          = h23;
        *(__nv_bfloat162*)(row + C_)         = l01;
        *(__nv_bfloat162*)(row + C_ + 2)     = l23;
        *(__nv_bfloat162*)(row + 2 * C_)     = h01;
        *(__nv_bfloat162*)(row + 2 * C_ + 2) = h23;
    }
}

// ---------------------------------------------------------------------------
extern "C" void kernel_launch(void* const* d_in, const int* in_sizes, int n_in,
                              void* d_out, int out_size)
{
    const float* x     = (const float*)d_in[0];
    const float* Wqkv  = (const float*)d_in[1];
    const float* bqkv  = (const float*)d_in[2];
    const float* Wproj = (const float*)d_in[3];
    const float* bproj = (const float*)d_in[4];
    float* out = (float*)d_out;

    __nv_bfloat16 *a3, *b3, *a3p, *b3p;
    cudaGetSymbolAddress((void**)&a3,  g_A3);
    cudaGetSymbolAddress((void**)&b3,  g_B3);
    cudaGetSymbolAddress((void**)&a3p, g_A3p);
    cudaGetSymbolAddress((void**)&b3p, g_B3p);

    // Phase 0: operand splitting / transposes
    split_x_kernel<<<M_TOT * 256 / 256, 256>>>(x);                       // 8192 blocks
    tsplit_kernel<<<dim3(KV_N / 32, C_ / 32), 256>>>(Wqkv + C_, b3, 3 * C_);
    tsplit_kernel<<<dim3(C_ / 32, C_ / 32), 256>>>(Wproj, b3p, C_);

    // Phase 1: KV projection (bf16x3 tensor GEMM, M=8192 N=2048 K'=3072)
    {
        dim3 grid(KV_N / 128, M_TOT / 128);   // (16, 64)
        gemm_bf16x3_kernel<<<grid, 256>>>(a3, b3, bqkv + C_, nullptr, 0);
    }

    // Phase 2: causal attention (q = k)
    {
        cudaFuncSetAttribute(attn_kernel,
                             cudaFuncAttributeMaxDynamicSharedMemorySize,
                             ATT_SMEM_BYTES);
        dim3 grid(S_ / 64, B_ * H_);
        attn_kernel<<<grid, 256, ATT_SMEM_BYTES>>>();
    }

    // Phase 3: output projection (bf16x3 tensor GEMM, M=8192 N=1024 K'=3072)
    {
        dim3 grid(C_ / 128, M_TOT / 128);     // (8, 64)
        gemm_bf16x3_kernel<<<grid, 256>>>(a3p, b3p, bproj, out, 1);
    }
}

// round 4
// speedup vs baseline: 2.7267x; 1.6408x over previous
#include <cuda_runtime.h>
#include <cuda_bf16.h>
#include <math.h>
#include <stddef.h>
#include <stdint.h>

// Problem constants
#define B_  8
#define S_  1024
#define C_  1024
#define H_  16
#define D_  64
#define M_TOT (B_ * S_)          // 8192
#define KV_N  (2 * C_)           // 2048
#define K3    (3 * C_)           // 3072

// sqrt(0.125 * log2(e)) — folded into K so S-MMA yields exp2-domain scores
#define KSCALE 0.42466089f

// Scratch (device globals; no runtime allocation allowed)
__device__ __nv_bfloat16 g_Kh[(size_t)B_ * H_ * S_ * D_];   // K hi (pre-scaled)
__device__ __nv_bfloat16 g_Kl[(size_t)B_ * H_ * S_ * D_];   // K lo
__device__ __nv_bfloat16 g_Vh[(size_t)B_ * H_ * S_ * D_];   // V hi
__device__ __nv_bfloat16 g_Vl[(size_t)B_ * H_ * S_ * D_];   // V lo
__device__ __nv_bfloat16 g_A3 [(size_t)M_TOT * K3];         // x split   [hi|lo|hi]
__device__ __nv_bfloat16 g_B3 [(size_t)KV_N  * K3];         // Wqkv_kv^T [hi|hi|lo]
__device__ __nv_bfloat16 g_A3p[(size_t)M_TOT * K3];         // attn out  [hi|lo|hi]
__device__ __nv_bfloat16 g_B3p[(size_t)C_    * K3];         // Wproj^T   [hi|hi|lo]

// ---------------------------------------------------------------------------
// PTX helpers (base-sm_100-legal)
// ---------------------------------------------------------------------------
__device__ __forceinline__ uint32_t smem_u32(const void* p) {
    uint32_t a;
    asm("{ .reg .u64 t; cvta.to.shared.u64 t, %1; cvt.u32.u64 %0, t; }" : "=r"(a) : "l"(p));
    return a;
}
__device__ __forceinline__ void cpasync16(uint32_t saddr, const void* g) {
    asm volatile("cp.async.cg.shared.global [%0], [%1], 16;" :: "r"(saddr), "l"(g) : "memory");
}
#define CP_COMMIT() asm volatile("cp.async.commit_group;" ::: "memory")
#define CP_WAIT(n)  asm volatile("cp.async.wait_group %0;" :: "n"(n) : "memory")

__device__ __forceinline__ void ldsm4(uint32_t* r, uint32_t addr) {
    asm volatile("ldmatrix.sync.aligned.m8n8.x4.shared.b16 {%0,%1,%2,%3}, [%4];"
                 : "=r"(r[0]), "=r"(r[1]), "=r"(r[2]), "=r"(r[3]) : "r"(addr));
}
__device__ __forceinline__ void ldsm4t(uint32_t* r, uint32_t addr) {
    asm volatile("ldmatrix.sync.aligned.m8n8.x4.trans.shared.b16 {%0,%1,%2,%3}, [%4];"
                 : "=r"(r[0]), "=r"(r[1]), "=r"(r[2]), "=r"(r[3]) : "r"(addr));
}
__device__ __forceinline__ void mma16816(float* c, const uint32_t* a, const uint32_t* b) {
    asm volatile(
        "mma.sync.aligned.m16n8k16.row.col.f32.bf16.bf16.f32 "
        "{%0,%1,%2,%3}, {%4,%5,%6,%7}, {%8,%9}, {%0,%1,%2,%3};"
        : "+f"(c[0]), "+f"(c[1]), "+f"(c[2]), "+f"(c[3])
        : "r"(a[0]), "r"(a[1]), "r"(a[2]), "r"(a[3]), "r"(b[0]), "r"(b[1]));
}

// Swizzled smem offset for a 16B chunk of a [rows][64B] tile (GEMM tiles).
__device__ __forceinline__ uint32_t sw_off(int row, int c) {
    return (uint32_t)(((row >> 1) << 7) +
                      ((((((row & 1) << 2) | c)) ^ ((row >> 1) & 7)) << 4));
}
// Swizzled smem offset for [64 rows][128B] attention tiles: chunk c (0..7).
__device__ __forceinline__ uint32_t toff(int r, int c) {
    return (uint32_t)(r * 128 + (((c) ^ (r & 7)) << 4));
}
// split a,b fp32 -> packed bf16x2 hi and lo
__device__ __forceinline__ void split2(float a, float b, uint32_t& hi, uint32_t& lo) {
    __nv_bfloat162 h = __floats2bfloat162_rn(a, b);
    __nv_bfloat162 l = __floats2bfloat162_rn(a - __bfloat162float(h.x),
                                             b - __bfloat162float(h.y));
    hi = *(uint32_t*)&h; lo = *(uint32_t*)&l;
}

// ---------------------------------------------------------------------------
// bf16x3 GEMM (unchanged core from R3):  C = A3 @ B3^T + bias
// mode 0: epilogue splits+scatters to g_Kh/g_Kl (scaled) and g_Vh/g_Vl.
// mode 1: writes fp32 out[m*1024+n].
// ---------------------------------------------------------------------------
#define NSTAGE (K3 / 32)          // 96

__device__ __forceinline__ void gemm_load_stage(
    const __nv_bfloat16* __restrict__ Ag, const __nv_bfloat16* __restrict__ Bg,
    int kb, uint32_t Ab, uint32_t Bb, int tid)
{
#pragma unroll
    for (int i = 0; i < 2; i++) {
        const int idx = tid + i * 256;
        const int r = idx >> 2, c = idx & 3;
        const size_t g = (size_t)r * K3 + kb * 32 + c * 8;
        cpasync16(Ab + sw_off(r, c), Ag + g);
        cpasync16(Bb + sw_off(r, c), Bg + g);
    }
}

__global__ __launch_bounds__(256, 2) void gemm_bf16x3_kernel(
    const __nv_bfloat16* __restrict__ Ag, const __nv_bfloat16* __restrict__ Bg,
    const float* __restrict__ bias, float* __restrict__ out, int mode)
{
    __shared__ __align__(1024) uint8_t smem_raw[2 * 16384];
    const uint32_t smb = smem_u32(smem_raw);

    const int tid  = threadIdx.x;
    const int lane = tid & 31;
    const int wid  = tid >> 5;
    const int wm = (wid >> 2) * 64;
    const int wn = (wid & 3) * 32;
    const int bn = blockIdx.x, bm = blockIdx.y;

    const __nv_bfloat16* Arow = Ag + (size_t)(bm * 128) * K3;
    const __nv_bfloat16* Brow = Bg + (size_t)(bn * 128) * K3;

    float acc[4][4][4];
#pragma unroll
    for (int f = 0; f < 4; f++)
#pragma unroll
        for (int g = 0; g < 4; g++)
#pragma unroll
            for (int r = 0; r < 4; r++) acc[f][g][r] = 0.0f;

    gemm_load_stage(Arow, Brow, 0, smb, smb + 8192, tid);
    CP_COMMIT();

    for (int kb = 0; kb < NSTAGE; kb++) {
        const int buf = kb & 1;
        if (kb + 1 < NSTAGE) {
            const int nb = buf ^ 1;
            gemm_load_stage(Arow, Brow, kb + 1,
                            smb + nb * 16384, smb + nb * 16384 + 8192, tid);
            CP_COMMIT();
            CP_WAIT(1);
        } else {
            CP_WAIT(0);
        }
        __syncthreads();

        const uint32_t Ab = smb + buf * 16384;
        const uint32_t Bb = Ab + 8192;
#pragma unroll
        for (int ks = 0; ks < 2; ks++) {
            uint32_t a[4][4], b[4][2];
            const int ar = lane & 15;
            const int ac = ks * 2 + (lane >> 4);
#pragma unroll
            for (int f = 0; f < 4; f++)
                ldsm4(a[f], Ab + sw_off(wm + f * 16 + ar, ac));

            const int br = (lane & 7) + ((lane >> 4) << 3);
            const int bc = ks * 2 + ((lane >> 3) & 1);
#pragma unroll
            for (int p = 0; p < 2; p++) {
                uint32_t r4[4];
                ldsm4(r4, Bb + sw_off(wn + p * 16 + br, bc));
                b[2 * p][0] = r4[0]; b[2 * p][1] = r4[1];
                b[2 * p + 1][0] = r4[2]; b[2 * p + 1][1] = r4[3];
            }
#pragma unroll
            for (int f = 0; f < 4; f++)
#pragma unroll
                for (int g = 0; g < 4; g++)
                    mma16816(acc[f][g], a[f], b[g]);
        }
        __syncthreads();
    }

    const int gr = lane >> 2;
    const int tcol = (lane & 3) * 2;
#pragma unroll
    for (int f = 0; f < 4; f++) {
        const int r0 = bm * 128 + wm + f * 16 + gr;
        const int b_ = r0 >> 10, s_ = r0 & 1023;
        const int r1 = r0 + 8;
        const int b1_ = r1 >> 10, s1_ = r1 & 1023;
#pragma unroll
        for (int g = 0; g < 4; g++) {
            const int cc = wn + g * 8 + tcol;
            const int n = bn * 128 + cc;
            const float bx = bias[n], by = bias[n + 1];
            float2 v0 = make_float2(acc[f][g][0] + bx, acc[f][g][1] + by);
            float2 v1 = make_float2(acc[f][g][2] + bx, acc[f][g][3] + by);
            if (mode == 0) {
                const int np = n & (C_ - 1);
                const int hh = np >> 6, dd = np & 63;
                const size_t o0 = (((size_t)(b_  * H_ + hh)) * S_ + s_ ) * D_ + dd;
                const size_t o1 = (((size_t)(b1_ * H_ + hh)) * S_ + s1_) * D_ + dd;
                if (n < C_) {   // K: scale then split
                    v0.x *= KSCALE; v0.y *= KSCALE; v1.x *= KSCALE; v1.y *= KSCALE;
                    uint32_t h0, l0, h1, l1;
                    split2(v0.x, v0.y, h0, l0);
                    split2(v1.x, v1.y, h1, l1);
                    *(uint32_t*)&g_Kh[o0] = h0; *(uint32_t*)&g_Kl[o0] = l0;
                    *(uint32_t*)&g_Kh[o1] = h1; *(uint32_t*)&g_Kl[o1] = l1;
                } else {        // V: split
                    uint32_t h0, l0, h1, l1;
                    split2(v0.x, v0.y, h0, l0);
                    split2(v1.x, v1.y, h1, l1);
                    *(uint32_t*)&g_Vh[o0] = h0; *(uint32_t*)&g_Vl[o0] = l0;
                    *(uint32_t*)&g_Vh[o1] = h1; *(uint32_t*)&g_Vl[o1] = l1;
                }
            } else {
                *(float2*)&out[(size_t)r0 * C_ + n] = v0;
                *(float2*)&out[(size_t)r1 * C_ + n] = v1;
            }
        }
    }
}

// ---------------------------------------------------------------------------
// split_x: x fp32 [8192][1024] -> g_A3 bf16 [8192][3072] as [hi | lo | hi]
// ---------------------------------------------------------------------------
__global__ __launch_bounds__(256) void split_x_kernel(const float* __restrict__ x)
{
    const int idx = blockIdx.x * 256 + threadIdx.x;
    const int m = idx >> 8;
    const int k = (idx & 255) << 2;
    const float4 v = *(const float4*)&x[(size_t)m * C_ + k];

    __nv_bfloat162 h01 = __floats2bfloat162_rn(v.x, v.y);
    __nv_bfloat162 h23 = __floats2bfloat162_rn(v.z, v.w);
    __nv_bfloat162 l01 = __floats2bfloat162_rn(v.x - __bfloat162float(h01.x),
                                               v.y - __bfloat162float(h01.y));
    __nv_bfloat162 l23 = __floats2bfloat162_rn(v.z - __bfloat162float(h23.x),
                                               v.w - __bfloat162float(h23.y));

    __nv_bfloat16* row = g_A3 + (size_t)m * K3;
    *(__nv_bfloat162*)(row + k)            = h01;
    *(__nv_bfloat162*)(row + k + 2)        = h23;
    *(__nv_bfloat162*)(row + C_ + k)       = l01;
    *(__nv_bfloat162*)(row + C_ + k + 2)   = l23;
    *(__nv_bfloat162*)(row + 2 * C_ + k)     = h01;
    *(__nv_bfloat162*)(row + 2 * C_ + k + 2) = h23;
}

// ---------------------------------------------------------------------------
// tsplit: W fp32 [1024][srcld] column block -> dst bf16 [n][3072] as [hi|hi|lo]
// ---------------------------------------------------------------------------
__global__ __launch_bounds__(256) void tsplit_kernel(
    const float* __restrict__ src, __nv_bfloat16* __restrict__ dst, int srcld)
{
    __shared__ float t[32][33];
    const int n0 = blockIdx.x * 32, k0 = blockIdx.y * 32;
    const int tx = threadIdx.x & 31, ty = threadIdx.x >> 5;
#pragma unroll
    for (int i = 0; i < 4; i++)
        t[ty + i * 8][tx] = src[(size_t)(k0 + ty + i * 8) * srcld + n0 + tx];
    __syncthreads();
#pragma unroll
    for (int i = 0; i < 4; i++) {
        const int n = n0 + ty + i * 8;
        const int k = k0 + tx;
        const float v = t[tx][ty + i * 8];
        __nv_bfloat16 h = __float2bfloat16(v);
        __nv_bfloat16 l = __float2bfloat16(v - __bfloat162float(h));
        __nv_bfloat16* row = dst + (size_t)n * K3;
        row[k] = h;
        row[C_ + k] = h;
        row[2 * C_ + k] = l;
    }
}

// ---------------------------------------------------------------------------
// MMA flash attention. CTA = 64-query tile x (b,h). 4 warps x 16 rows.
// Scores come out of the MMA already in the exp2 domain (K pre-scaled).
// smem: Q region (Qh 8K + Ql 8K) + 2 stages x (Kh|Kl|Vh|Vl, 8K each).
// ---------------------------------------------------------------------------
#define STAGE_B 32768
#define SM_Q    0
#define SM_STG  16384
#define ATT_SMEM (16384 + 2 * STAGE_B)     // 81920

__device__ __forceinline__ void att_load_tile(
    uint32_t dst, const __nv_bfloat16* Kh, const __nv_bfloat16* Kl,
    const __nv_bfloat16* Vh, const __nv_bfloat16* Vl, int jt, int tid)
{
    const size_t gb = (size_t)jt * 8192;   // byte offset (64 rows x 128B)
#pragma unroll
    for (int i = 0; i < 4; i++) {
        const int idx = tid + i * 128;
        const int r = idx >> 3, c = idx & 7;
        const uint32_t so = toff(r, c);
        const size_t go = gb + (size_t)r * 128 + c * 16;
        cpasync16(dst +         so, (const char*)Kh + go);
        cpasync16(dst +  8192 + so, (const char*)Kl + go);
        cpasync16(dst + 16384 + so, (const char*)Vh + go);
        cpasync16(dst + 24576 + so, (const char*)Vl + go);
    }
}

__global__ __launch_bounds__(128) void attn_mma_kernel()
{
    extern __shared__ uint8_t asmem[];
    const uint32_t smb = smem_u32(asmem);
    const int tid = threadIdx.x, lane = tid & 31, w = tid >> 5;
    const int qt = blockIdx.x, bh = blockIdx.y;
    const int gr = lane >> 2, tq = lane & 3;

    const __nv_bfloat16* Kh = g_Kh + (size_t)bh * S_ * D_;
    const __nv_bfloat16* Kl = g_Kl + (size_t)bh * S_ * D_;
    const __nv_bfloat16* Vh = g_Vh + (size_t)bh * S_ * D_;
    const __nv_bfloat16* Vl = g_Vl + (size_t)bh * S_ * D_;

    // Prologue: Q rows (= K rows, q=k quirk) and key-tile 0
    {
        const size_t gb = (size_t)qt * 8192;
#pragma unroll
        for (int i = 0; i < 4; i++) {
            const int idx = tid + i * 128;
            const int r = idx >> 3, c = idx & 7;
            const uint32_t so = toff(r, c);
            const size_t go = gb + (size_t)r * 128 + c * 16;
            cpasync16(smb + SM_Q +        so, (const char*)Kh + go);
            cpasync16(smb + SM_Q + 8192 + so, (const char*)Kl + go);
        }
        CP_COMMIT();
        att_load_tile(smb + SM_STG, Kh, Kl, Vh, Vl, 0, tid);
        CP_COMMIT();
    }

    uint32_t qh[4][4], ql[4][4];
    float o[8][4];
#pragma unroll
    for (int g = 0; g < 8; g++)
#pragma unroll
        for (int r = 0; r < 4; r++) o[g][r] = 0.0f;
    float mrow0 = -1e30f, mrow1 = -1e30f, lrow0 = 0.0f, lrow1 = 0.0f;

    const int ar = lane & 15, hc = lane >> 4;
    const int br = (lane & 7) + ((lane >> 4) << 3);
    const int bcs = (lane >> 3) & 1;
    const int vr = (lane & 7) + (((lane >> 3) & 1) << 3);
    const int vcs = lane >> 4;

    for (int jt = 0; jt <= qt; jt++) {
        const uint32_t Kb = smb + SM_STG + (jt & 1) * STAGE_B;
        if (jt < qt) {
            att_load_tile(smb + SM_STG + ((jt + 1) & 1) * STAGE_B,
                          Kh, Kl, Vh, Vl, jt + 1, tid);
            CP_COMMIT();
            CP_WAIT(1);
        } else {
            CP_WAIT(0);
        }
        __syncthreads();

        if (jt == 0) {
#pragma unroll
            for (int ks = 0; ks < 4; ks++) {
                ldsm4(qh[ks], smb + SM_Q +        toff(16 * w + ar, 2 * ks + hc));
                ldsm4(ql[ks], smb + SM_Q + 8192 + toff(16 * w + ar, 2 * ks + hc));
            }
        }

        // S = Q K^T (3-term split)
        float s[8][4];
#pragma unroll
        for (int g = 0; g < 8; g++)
#pragma unroll
            for (int r = 0; r < 4; r++) s[g][r] = 0.0f;
#pragma unroll
        for (int ks = 0; ks < 4; ks++) {
#pragma unroll
            for (int p = 0; p < 4; p++) {
                uint32_t kh4[4], kl4[4];
                ldsm4(kh4, Kb +        toff(16 * p + br, 2 * ks + bcs));
                ldsm4(kl4, Kb + 8192 + toff(16 * p + br, 2 * ks + bcs));
                mma16816(s[2 * p],     qh[ks], kh4);
                mma16816(s[2 * p + 1], qh[ks], kh4 + 2);
                mma16816(s[2 * p],     qh[ks], kl4);
                mma16816(s[2 * p + 1], qh[ks], kl4 + 2);
                mma16816(s[2 * p],     ql[ks], kh4);
                mma16816(s[2 * p + 1], ql[ks], kh4 + 2);
            }
        }

        // causal mask (only diagonal tile)
        if (jt == qt) {
            const int rb = 16 * w + gr;
#pragma unroll
            for (int g = 0; g < 8; g++) {
                const int c0 = 8 * g + 2 * tq;
                if (c0     > rb)     s[g][0] = -1e30f;
                if (c0 + 1 > rb)     s[g][1] = -1e30f;
                if (c0     > rb + 8) s[g][2] = -1e30f;
                if (c0 + 1 > rb + 8) s[g][3] = -1e30f;
            }
        }

        // online softmax (scores already in exp2 domain)
        float mx0 = -1e30f, mx1 = -1e30f;
#pragma unroll
        for (int g = 0; g < 8; g++) {
            mx0 = fmaxf(mx0, fmaxf(s[g][0], s[g][1]));
            mx1 = fmaxf(mx1, fmaxf(s[g][2], s[g][3]));
        }
        mx0 = fmaxf(mx0, __shfl_xor_sync(0xffffffffu, mx0, 1));
        mx0 = fmaxf(mx0, __shfl_xor_sync(0xffffffffu, mx0, 2));
        mx1 = fmaxf(mx1, __shfl_xor_sync(0xffffffffu, mx1, 1));
        mx1 = fmaxf(mx1, __shfl_xor_sync(0xffffffffu, mx1, 2));
        const float mn0 = fmaxf(mrow0, mx0), mn1 = fmaxf(mrow1, mx1);
        const float a0 = exp2f(mrow0 - mn0), a1 = exp2f(mrow1 - mn1);
        mrow0 = mn0; mrow1 = mn1;
        float sum0 = 0.0f, sum1 = 0.0f;
#pragma unroll
        for (int g = 0; g < 8; g++) {
            s[g][0] = exp2f(s[g][0] - mn0); sum0 += s[g][0];
            s[g][1] = exp2f(s[g][1] - mn0); sum0 += s[g][1];
            s[g][2] = exp2f(s[g][2] - mn1); sum1 += s[g][2];
            s[g][3] = exp2f(s[g][3] - mn1); sum1 += s[g][3];
        }
        sum0 += __shfl_xor_sync(0xffffffffu, sum0, 1);
        sum0 += __shfl_xor_sync(0xffffffffu, sum0, 2);
        sum1 += __shfl_xor_sync(0xffffffffu, sum1, 1);
        sum1 += __shfl_xor_sync(0xffffffffu, sum1, 2);
        lrow0 = lrow0 * a0 + sum0;
        lrow1 = lrow1 * a1 + sum1;
#pragma unroll
        for (int g = 0; g < 8; g++) {
            o[g][0] *= a0; o[g][1] *= a0; o[g][2] *= a1; o[g][3] *= a1;
        }

        // O += P V (3-term split); P frags built in-register from s
#pragma unroll
        for (int ks = 0; ks < 4; ks++) {
            uint32_t ph[4], pl[4];
            split2(s[2 * ks][0],     s[2 * ks][1],     ph[0], pl[0]);
            split2(s[2 * ks][2],     s[2 * ks][3],     ph[1], pl[1]);
            split2(s[2 * ks + 1][0], s[2 * ks + 1][1], ph[2], pl[2]);
            split2(s[2 * ks + 1][2], s[2 * ks + 1][3], ph[3], pl[3]);
#pragma unroll
            for (int p2 = 0; p2 < 4; p2++) {
                uint32_t vh4[4], vl4[4];
                ldsm4t(vh4, Kb + 16384 + toff(16 * ks + vr, 2 * p2 + vcs));
                ldsm4t(vl4, Kb + 24576 + toff(16 * ks + vr, 2 * p2 + vcs));
                mma16816(o[2 * p2],     ph, vh4);
                mma16816(o[2 * p2 + 1], ph, vh4 + 2);
                mma16816(o[2 * p2],     ph, vl4);
                mma16816(o[2 * p2 + 1], ph, vl4 + 2);
                mma16816(o[2 * p2],     pl, vh4);
                mma16816(o[2 * p2 + 1], pl, vh4 + 2);
            }
        }
        __syncthreads();
    }

    // Epilogue: normalize, split, write [hi | lo | hi] rows into g_A3p
    const float i0 = 1.0f / lrow0, i1 = 1.0f / lrow1;
    const int b = bh >> 4, h = bh & 15;
    const int r0 = qt * 64 + 16 * w + gr;
    const int r1 = r0 + 8;
    __nv_bfloat16* row0 = g_A3p + (size_t)(b * S_ + r0) * K3 + h * 64;
    __nv_bfloat16* row1 = g_A3p + (size_t)(b * S_ + r1) * K3 + h * 64;
#pragma unroll
    for (int g = 0; g < 8; g++) {
        const int d = 8 * g + 2 * tq;
        uint32_t h0, l0, h1, l1;
        split2(o[g][0] * i0, o[g][1] * i0, h0, l0);
        split2(o[g][2] * i1, o[g][3] * i1, h1, l1);
        *(uint32_t*)(row0 + d)          = h0;
        *(uint32_t*)(row0 + C_ + d)     = l0;
        *(uint32_t*)(row0 + 2 * C_ + d) = h0;
        *(uint32_t*)(row1 + d)          = h1;
        *(uint32_t*)(row1 + C_ + d)     = l1;
        *(uint32_t*)(row1 + 2 * C_ + d) = h1;
    }
}

// ---------------------------------------------------------------------------
extern "C" void kernel_launch(void* const* d_in, const int* in_sizes, int n_in,
                              void* d_out, int out_size)
{
    const float* x     = (const float*)d_in[0];
    const float* Wqkv  = (const float*)d_in[1];
    const float* bqkv  = (const float*)d_in[2];
    const float* Wproj = (const float*)d_in[3];
    const float* bproj = (const float*)d_in[4];
    float* out = (float*)d_out;

    __nv_bfloat16 *a3, *b3, *a3p, *b3p;
    cudaGetSymbolAddress((void**)&a3,  g_A3);
    cudaGetSymbolAddress((void**)&b3,  g_B3);
    cudaGetSymbolAddress((void**)&a3p, g_A3p);
    cudaGetSymbolAddress((void**)&b3p, g_B3p);

    // Phase 0: operand splitting / transposes
    split_x_kernel<<<M_TOT, 256>>>(x);
    tsplit_kernel<<<dim3(KV_N / 32, C_ / 32), 256>>>(Wqkv + C_, b3, 3 * C_);
    tsplit_kernel<<<dim3(C_ / 32, C_ / 32), 256>>>(Wproj, b3p, C_);

    // Phase 1: KV projection (bf16x3 tensor GEMM) -> split K(scaled)/V
    {
        dim3 grid(KV_N / 128, M_TOT / 128);   // (16, 64)
        gemm_bf16x3_kernel<<<grid, 256>>>(a3, b3, bqkv + C_, nullptr, 0);
    }

    // Phase 2: causal attention on mma.sync (q = k)
    {
        cudaFuncSetAttribute(attn_mma_kernel,
                             cudaFuncAttributeMaxDynamicSharedMemorySize,
                             ATT_SMEM);
        dim3 grid(S_ / 64, B_ * H_);          // (16, 128)
        attn_mma_kernel<<<grid, 128, ATT_SMEM>>>();
    }

    // Phase 3: output projection (bf16x3 tensor GEMM)
    {
        dim3 grid(C_ / 128, M_TOT / 128);     // (8, 64)
        gemm_bf16x3_kernel<<<grid, 256>>>(a3p, b3p, bproj, out, 1);
    }
}

// round 5
// speedup vs baseline: 2.7611x; 1.0126x over previous
#include <cuda_runtime.h>
#include <cuda_bf16.h>
#include <math.h>
#include <stddef.h>
#include <stdint.h>

// Problem constants
#define B_  8
#define S_  1024
#define C_  1024
#define H_  16
#define D_  64
#define M_TOT (B_ * S_)          // 8192
#define KV_N  (2 * C_)           // 2048
#define K3    (3 * C_)           // 3072

// sqrt(0.125 * log2(e)) — folded into K so S-MMA yields exp2-domain scores
#define KSCALE 0.42466089f

// Scratch (device globals; no runtime allocation allowed)
__device__ __nv_bfloat16 g_Kh[(size_t)B_ * H_ * S_ * D_];   // K hi (pre-scaled)
__device__ __nv_bfloat16 g_Kl[(size_t)B_ * H_ * S_ * D_];   // K lo
__device__ __nv_bfloat16 g_Vh[(size_t)B_ * H_ * S_ * D_];   // V hi
__device__ __nv_bfloat16 g_Vl[(size_t)B_ * H_ * S_ * D_];   // V lo
__device__ __nv_bfloat16 g_A3 [(size_t)M_TOT * K3];         // x split   [hi|lo|hi]
__device__ __nv_bfloat16 g_B3 [(size_t)KV_N  * K3];         // Wqkv_kv^T [hi|hi|lo]
__device__ __nv_bfloat16 g_A3p[(size_t)M_TOT * K3];         // attn out  [hi|lo|hi]
__device__ __nv_bfloat16 g_B3p[(size_t)C_    * K3];         // Wproj^T   [hi|hi|lo]

// ---------------------------------------------------------------------------
// PTX helpers (base-sm_100-legal)
// ---------------------------------------------------------------------------
__device__ __forceinline__ uint32_t smem_u32(const void* p) {
    uint32_t a;
    asm("{ .reg .u64 t; cvta.to.shared.u64 t, %1; cvt.u32.u64 %0, t; }" : "=r"(a) : "l"(p));
    return a;
}
__device__ __forceinline__ void cpasync16(uint32_t saddr, const void* g) {
    asm volatile("cp.async.cg.shared.global [%0], [%1], 16;" :: "r"(saddr), "l"(g) : "memory");
}
#define CP_COMMIT() asm volatile("cp.async.commit_group;" ::: "memory")
#define CP_WAIT(n)  asm volatile("cp.async.wait_group %0;" :: "n"(n) : "memory")

__device__ __forceinline__ void ldsm4(uint32_t* r, uint32_t addr) {
    asm volatile("ldmatrix.sync.aligned.m8n8.x4.shared.b16 {%0,%1,%2,%3}, [%4];"
                 : "=r"(r[0]), "=r"(r[1]), "=r"(r[2]), "=r"(r[3]) : "r"(addr));
}
__device__ __forceinline__ void ldsm4t(uint32_t* r, uint32_t addr) {
    asm volatile("ldmatrix.sync.aligned.m8n8.x4.trans.shared.b16 {%0,%1,%2,%3}, [%4];"
                 : "=r"(r[0]), "=r"(r[1]), "=r"(r[2]), "=r"(r[3]) : "r"(addr));
}
__device__ __forceinline__ void mma16816(float* c, const uint32_t* a, const uint32_t* b) {
    asm volatile(
        "mma.sync.aligned.m16n8k16.row.col.f32.bf16.bf16.f32 "
        "{%0,%1,%2,%3}, {%4,%5,%6,%7}, {%8,%9}, {%0,%1,%2,%3};"
        : "+f"(c[0]), "+f"(c[1]), "+f"(c[2]), "+f"(c[3])
        : "r"(a[0]), "r"(a[1]), "r"(a[2]), "r"(a[3]), "r"(b[0]), "r"(b[1]));
}

// Swizzled smem offset for a 16B chunk of a [rows][64B] tile (GEMM tiles).
__device__ __forceinline__ uint32_t sw_off(int row, int c) {
    return (uint32_t)(((row >> 1) << 7) +
                      ((((((row & 1) << 2) | c)) ^ ((row >> 1) & 7)) << 4));
}
// Swizzled smem offset for [64 rows][128B] attention tiles: chunk c (0..7).
__device__ __forceinline__ uint32_t toff(int r, int c) {
    return (uint32_t)(r * 128 + (((c) ^ (r & 7)) << 4));
}
// split a,b fp32 -> packed bf16x2 hi and lo
__device__ __forceinline__ void split2(float a, float b, uint32_t& hi, uint32_t& lo) {
    __nv_bfloat162 h = __floats2bfloat162_rn(a, b);
    __nv_bfloat162 l = __floats2bfloat162_rn(a - __bfloat162float(h.x),
                                             b - __bfloat162float(h.y));
    hi = *(uint32_t*)&h; lo = *(uint32_t*)&l;
}

// ---------------------------------------------------------------------------
// bf16x3 GEMM:  C = A3 @ B3^T + bias.  3-stage cp.async pipeline, 1 sync/stage.
// mode 0: epilogue splits+scatters to g_Kh/g_Kl (scaled) and g_Vh/g_Vl.
// mode 1: writes fp32 out[m*1024+n].
// ---------------------------------------------------------------------------
#define NSTAGE (K3 / 32)          // 96
#define GSTAGE_B 16384            // A 8K + B 8K per stage
#define GEMM_SMEM (3 * GSTAGE_B)  // 49152

__device__ __forceinline__ void gemm_load_stage(
    const __nv_bfloat16* __restrict__ Ag, const __nv_bfloat16* __restrict__ Bg,
    int kb, uint32_t Ab, uint32_t Bb, int tid)
{
#pragma unroll
    for (int i = 0; i < 2; i++) {
        const int idx = tid + i * 256;
        const int r = idx >> 2, c = idx & 3;
        const size_t g = (size_t)r * K3 + kb * 32 + c * 8;
        cpasync16(Ab + sw_off(r, c), Ag + g);
        cpasync16(Bb + sw_off(r, c), Bg + g);
    }
}

__global__ __launch_bounds__(256) void gemm_bf16x3_kernel(
    const __nv_bfloat16* __restrict__ Ag, const __nv_bfloat16* __restrict__ Bg,
    const float* __restrict__ bias, float* __restrict__ out, int mode)
{
    extern __shared__ __align__(1024) uint8_t gsm[];
    const uint32_t smb = smem_u32(gsm);

    const int tid  = threadIdx.x;
    const int lane = tid & 31;
    const int wid  = tid >> 5;
    const int wm = (wid >> 2) * 64;
    const int wn = (wid & 3) * 32;
    const int bn = blockIdx.x, bm = blockIdx.y;

    const __nv_bfloat16* Arow = Ag + (size_t)(bm * 128) * K3;
    const __nv_bfloat16* Brow = Bg + (size_t)(bn * 128) * K3;

    float acc[4][4][4];
#pragma unroll
    for (int f = 0; f < 4; f++)
#pragma unroll
        for (int g = 0; g < 4; g++)
#pragma unroll
            for (int r = 0; r < 4; r++) acc[f][g][r] = 0.0f;

    // prologue: prefetch stages 0 and 1
    gemm_load_stage(Arow, Brow, 0, smb, smb + 8192, tid);
    CP_COMMIT();
    gemm_load_stage(Arow, Brow, 1, smb + GSTAGE_B, smb + GSTAGE_B + 8192, tid);
    CP_COMMIT();

    int buf = 0, pbuf = 2;   // buf = stage kb's buffer, pbuf = prefetch target
    for (int kb = 0; kb < NSTAGE; kb++) {
        CP_WAIT(1);          // stage kb landed (only stage kb+1 may be in flight)
        __syncthreads();     // one barrier per stage

        const uint32_t Ab = smb + buf * GSTAGE_B;
        const uint32_t Bb = Ab + 8192;
#pragma unroll
        for (int ks = 0; ks < 2; ks++) {
            uint32_t a[4][4], b[4][2];
            const int ar = lane & 15;
            const int ac = ks * 2 + (lane >> 4);
#pragma unroll
            for (int f = 0; f < 4; f++)
                ldsm4(a[f], Ab + sw_off(wm + f * 16 + ar, ac));

            const int br = (lane & 7) + ((lane >> 4) << 3);
            const int bc = ks * 2 + ((lane >> 3) & 1);
#pragma unroll
            for (int p = 0; p < 2; p++) {
                uint32_t r4[4];
                ldsm4(r4, Bb + sw_off(wn + p * 16 + br, bc));
                b[2 * p][0] = r4[0]; b[2 * p][1] = r4[1];
                b[2 * p + 1][0] = r4[2]; b[2 * p + 1][1] = r4[3];
            }
#pragma unroll
            for (int f = 0; f < 4; f++)
#pragma unroll
                for (int g = 0; g < 4; g++)
                    mma16816(acc[f][g], a[f], b[g]);
        }

        // prefetch stage kb+2 into pbuf (distinct from both live buffers)
        if (kb + 2 < NSTAGE) {
            gemm_load_stage(Arow, Brow, kb + 2,
                            smb + pbuf * GSTAGE_B, smb + pbuf * GSTAGE_B + 8192, tid);
        }
        CP_COMMIT();         // commit every stage so wait-group depth stays uniform

        buf = (buf == 2) ? 0 : buf + 1;
        pbuf = (pbuf == 2) ? 0 : pbuf + 1;
    }

    const int gr = lane >> 2;
    const int tcol = (lane & 3) * 2;
#pragma unroll
    for (int f = 0; f < 4; f++) {
        const int r0 = bm * 128 + wm + f * 16 + gr;
        const int b_ = r0 >> 10, s_ = r0 & 1023;
        const int r1 = r0 + 8;
        const int b1_ = r1 >> 10, s1_ = r1 & 1023;
#pragma unroll
        for (int g = 0; g < 4; g++) {
            const int cc = wn + g * 8 + tcol;
            const int n = bn * 128 + cc;
            const float bx = bias[n], by = bias[n + 1];
            float2 v0 = make_float2(acc[f][g][0] + bx, acc[f][g][1] + by);
            float2 v1 = make_float2(acc[f][g][2] + bx, acc[f][g][3] + by);
            if (mode == 0) {
                const int np = n & (C_ - 1);
                const int hh = np >> 6, dd = np & 63;
                const size_t o0 = (((size_t)(b_  * H_ + hh)) * S_ + s_ ) * D_ + dd;
                const size_t o1 = (((size_t)(b1_ * H_ + hh)) * S_ + s1_) * D_ + dd;
                if (n < C_) {   // K: scale then split
                    v0.x *= KSCALE; v0.y *= KSCALE; v1.x *= KSCALE; v1.y *= KSCALE;
                    uint32_t h0, l0, h1, l1;
                    split2(v0.x, v0.y, h0, l0);
                    split2(v1.x, v1.y, h1, l1);
                    *(uint32_t*)&g_Kh[o0] = h0; *(uint32_t*)&g_Kl[o0] = l0;
                    *(uint32_t*)&g_Kh[o1] = h1; *(uint32_t*)&g_Kl[o1] = l1;
                } else {        // V: split
                    uint32_t h0, l0, h1, l1;
                    split2(v0.x, v0.y, h0, l0);
                    split2(v1.x, v1.y, h1, l1);
                    *(uint32_t*)&g_Vh[o0] = h0; *(uint32_t*)&g_Vl[o0] = l0;
                    *(uint32_t*)&g_Vh[o1] = h1; *(uint32_t*)&g_Vl[o1] = l1;
                }
            } else {
                *(float2*)&out[(size_t)r0 * C_ + n] = v0;
                *(float2*)&out[(size_t)r1 * C_ + n] = v1;
            }
        }
    }
}

// ---------------------------------------------------------------------------
// split_x: x fp32 [8192][1024] -> g_A3 bf16 [8192][3072] as [hi | lo | hi]
// ---------------------------------------------------------------------------
__global__ __launch_bounds__(256) void split_x_kernel(const float* __restrict__ x)
{
    const int idx = blockIdx.x * 256 + threadIdx.x;
    const int m = idx >> 8;
    const int k = (idx & 255) << 2;
    const float4 v = *(const float4*)&x[(size_t)m * C_ + k];

    __nv_bfloat162 h01 = __floats2bfloat162_rn(v.x, v.y);
    __nv_bfloat162 h23 = __floats2bfloat162_rn(v.z, v.w);
    __nv_bfloat162 l01 = __floats2bfloat162_rn(v.x - __bfloat162float(h01.x),
                                               v.y - __bfloat162float(h01.y));
    __nv_bfloat162 l23 = __floats2bfloat162_rn(v.z - __bfloat162float(h23.x),
                                               v.w - __bfloat162float(h23.y));

    __nv_bfloat16* row = g_A3 + (size_t)m * K3;
    *(__nv_bfloat162*)(row + k)            = h01;
    *(__nv_bfloat162*)(row + k + 2)        = h23;
    *(__nv_bfloat162*)(row + C_ + k)       = l01;
    *(__nv_bfloat162*)(row + C_ + k + 2)   = l23;
    *(__nv_bfloat162*)(row + 2 * C_ + k)     = h01;
    *(__nv_bfloat162*)(row + 2 * C_ + k + 2) = h23;
}

// ---------------------------------------------------------------------------
// tsplit: W fp32 [1024][srcld] column block -> dst bf16 [n][3072] as [hi|hi|lo]
// ---------------------------------------------------------------------------
__global__ __launch_bounds__(256) void tsplit_kernel(
    const float* __restrict__ src, __nv_bfloat16* __restrict__ dst, int srcld)
{
    __shared__ float t[32][33];
    const int n0 = blockIdx.x * 32, k0 = blockIdx.y * 32;
    const int tx = threadIdx.x & 31, ty = threadIdx.x >> 5;
#pragma unroll
    for (int i = 0; i < 4; i++)
        t[ty + i * 8][tx] = src[(size_t)(k0 + ty + i * 8) * srcld + n0 + tx];
    __syncthreads();
#pragma unroll
    for (int i = 0; i < 4; i++) {
        const int n = n0 + ty + i * 8;
        const int k = k0 + tx;
        const float v = t[tx][ty + i * 8];
        __nv_bfloat16 h = __float2bfloat16(v);
        __nv_bfloat16 l = __float2bfloat16(v - __bfloat162float(h));
        __nv_bfloat16* row = dst + (size_t)n * K3;
        row[k] = h;
        row[C_ + k] = h;
        row[2 * C_ + k] = l;
    }
}

// ---------------------------------------------------------------------------
// MMA flash attention (unchanged from R4, passing at ~180us).
// ---------------------------------------------------------------------------
#define STAGE_B 32768
#define SM_Q    0
#define SM_STG  16384
#define ATT_SMEM (16384 + 2 * STAGE_B)     // 81920

__device__ __forceinline__ void att_load_tile(
    uint32_t dst, const __nv_bfloat16* Kh, const __nv_bfloat16* Kl,
    const __nv_bfloat16* Vh, const __nv_bfloat16* Vl, int jt, int tid)
{
    const size_t gb = (size_t)jt * 8192;
#pragma unroll
    for (int i = 0; i < 4; i++) {
        const int idx = tid + i * 128;
        const int r = idx >> 3, c = idx & 7;
        const uint32_t so = toff(r, c);
        const size_t go = gb + (size_t)r * 128 + c * 16;
        cpasync16(dst +         so, (const char*)Kh + go);
        cpasync16(dst +  8192 + so, (const char*)Kl + go);
        cpasync16(dst + 16384 + so, (const char*)Vh + go);
        cpasync16(dst + 24576 + so, (const char*)Vl + go);
    }
}

__global__ __launch_bounds__(128) void attn_mma_kernel()
{
    extern __shared__ uint8_t asmem[];
    const uint32_t smb = smem_u32(asmem);
    const int tid = threadIdx.x, lane = tid & 31, w = tid >> 5;
    const int qt = blockIdx.x, bh = blockIdx.y;
    const int gr = lane >> 2, tq = lane & 3;

    const __nv_bfloat16* Kh = g_Kh + (size_t)bh * S_ * D_;
    const __nv_bfloat16* Kl = g_Kl + (size_t)bh * S_ * D_;
    const __nv_bfloat16* Vh = g_Vh + (size_t)bh * S_ * D_;
    const __nv_bfloat16* Vl = g_Vl + (size_t)bh * S_ * D_;

    {
        const size_t gb = (size_t)qt * 8192;
#pragma unroll
        for (int i = 0; i < 4; i++) {
            const int idx = tid + i * 128;
            const int r = idx >> 3, c = idx & 7;
            const uint32_t so = toff(r, c);
            const size_t go = gb + (size_t)r * 128 + c * 16;
            cpasync16(smb + SM_Q +        so, (const char*)Kh + go);
            cpasync16(smb + SM_Q + 8192 + so, (const char*)Kl + go);
        }
        CP_COMMIT();
        att_load_tile(smb + SM_STG, Kh, Kl, Vh, Vl, 0, tid);
        CP_COMMIT();
    }

    uint32_t qh[4][4], ql[4][4];
    float o[8][4];
#pragma unroll
    for (int g = 0; g < 8; g++)
#pragma unroll
        for (int r = 0; r < 4; r++) o[g][r] = 0.0f;
    float mrow0 = -1e30f, mrow1 = -1e30f, lrow0 = 0.0f, lrow1 = 0.0f;

    const int ar = lane & 15, hc = lane >> 4;
    const int br = (lane & 7) + ((lane >> 4) << 3);
    const int bcs = (lane >> 3) & 1;
    const int vr = (lane & 7) + (((lane >> 3) & 1) << 3);
    const int vcs = lane >> 4;

    for (int jt = 0; jt <= qt; jt++) {
        const uint32_t Kb = smb + SM_STG + (jt & 1) * STAGE_B;
        if (jt < qt) {
            att_load_tile(smb + SM_STG + ((jt + 1) & 1) * STAGE_B,
                          Kh, Kl, Vh, Vl, jt + 1, tid);
            CP_COMMIT();
            CP_WAIT(1);
        } else {
            CP_WAIT(0);
        }
        __syncthreads();

        if (jt == 0) {
#pragma unroll
            for (int ks = 0; ks < 4; ks++) {
                ldsm4(qh[ks], smb + SM_Q +        toff(16 * w + ar, 2 * ks + hc));
                ldsm4(ql[ks], smb + SM_Q + 8192 + toff(16 * w + ar, 2 * ks + hc));
            }
        }

        float s[8][4];
#pragma unroll
        for (int g = 0; g < 8; g++)
#pragma unroll
            for (int r = 0; r < 4; r++) s[g][r] = 0.0f;
#pragma unroll
        for (int ks = 0; ks < 4; ks++) {
#pragma unroll
            for (int p = 0; p < 4; p++) {
                uint32_t kh4[4], kl4[4];
                ldsm4(kh4, Kb +        toff(16 * p + br, 2 * ks + bcs));
                ldsm4(kl4, Kb + 8192 + toff(16 * p + br, 2 * ks + bcs));
                mma16816(s[2 * p],     qh[ks], kh4);
                mma16816(s[2 * p + 1], qh[ks], kh4 + 2);
                mma16816(s[2 * p],     qh[ks], kl4);
                mma16816(s[2 * p + 1], qh[ks], kl4 + 2);
                mma16816(s[2 * p],     ql[ks], kh4);
                mma16816(s[2 * p + 1], ql[ks], kh4 + 2);
            }
        }

        if (jt == qt) {
            const int rb = 16 * w + gr;
#pragma unroll
            for (int g = 0; g < 8; g++) {
                const int c0 = 8 * g + 2 * tq;
                if (c0     > rb)     s[g][0] = -1e30f;
                if (c0 + 1 > rb)     s[g][1] = -1e30f;
                if (c0     > rb + 8) s[g][2] = -1e30f;
                if (c0 + 1 > rb + 8) s[g][3] = -1e30f;
            }
        }

        float mx0 = -1e30f, mx1 = -1e30f;
#pragma unroll
        for (int g = 0; g < 8; g++) {
            mx0 = fmaxf(mx0, fmaxf(s[g][0], s[g][1]));
            mx1 = fmaxf(mx1, fmaxf(s[g][2], s[g][3]));
        }
        mx0 = fmaxf(mx0, __shfl_xor_sync(0xffffffffu, mx0, 1));
        mx0 = fmaxf(mx0, __shfl_xor_sync(0xffffffffu, mx0, 2));
        mx1 = fmaxf(mx1, __shfl_xor_sync(0xffffffffu, mx1, 1));
        mx1 = fmaxf(mx1, __shfl_xor_sync(0xffffffffu, mx1, 2));
        const float mn0 = fmaxf(mrow0, mx0), mn1 = fmaxf(mrow1, mx1);
        const float a0 = exp2f(mrow0 - mn0), a1 = exp2f(mrow1 - mn1);
        mrow0 = mn0; mrow1 = mn1;
        float sum0 = 0.0f, sum1 = 0.0f;
#pragma unroll
        for (int g = 0; g < 8; g++) {
            s[g][0] = exp2f(s[g][0] - mn0); sum0 += s[g][0];
            s[g][1] = exp2f(s[g][1] - mn0); sum0 += s[g][1];
            s[g][2] = exp2f(s[g][2] - mn1); sum1 += s[g][2];
            s[g][3] = exp2f(s[g][3] - mn1); sum1 += s[g][3];
        }
        sum0 += __shfl_xor_sync(0xffffffffu, sum0, 1);
        sum0 += __shfl_xor_sync(0xffffffffu, sum0, 2);
        sum1 += __shfl_xor_sync(0xffffffffu, sum1, 1);
        sum1 += __shfl_xor_sync(0xffffffffu, sum1, 2);
        lrow0 = lrow0 * a0 + sum0;
        lrow1 = lrow1 * a1 + sum1;
#pragma unroll
        for (int g = 0; g < 8; g++) {
            o[g][0] *= a0; o[g][1] *= a0; o[g][2] *= a1; o[g][3] *= a1;
        }

#pragma unroll
        for (int ks = 0; ks < 4; ks++) {
            uint32_t ph[4], pl[4];
            split2(s[2 * ks][0],     s[2 * ks][1],     ph[0], pl[0]);
            split2(s[2 * ks][2],     s[2 * ks][3],     ph[1], pl[1]);
            split2(s[2 * ks + 1][0], s[2 * ks + 1][1], ph[2], pl[2]);
            split2(s[2 * ks + 1][2], s[2 * ks + 1][3], ph[3], pl[3]);
#pragma unroll
            for (int p2 = 0; p2 < 4; p2++) {
                uint32_t vh4[4], vl4[4];
                ldsm4t(vh4, Kb + 16384 + toff(16 * ks + vr, 2 * p2 + vcs));
                ldsm4t(vl4, Kb + 24576 + toff(16 * ks + vr, 2 * p2 + vcs));
                mma16816(o[2 * p2],     ph, vh4);
                mma16816(o[2 * p2 + 1], ph, vh4 + 2);
                mma16816(o[2 * p2],     ph, vl4);
                mma16816(o[2 * p2 + 1], ph, vl4 + 2);
                mma16816(o[2 * p2],     pl, vh4);
                mma16816(o[2 * p2 + 1], pl, vh4 + 2);
            }
        }
        __syncthreads();
    }

    const float i0 = 1.0f / lrow0, i1 = 1.0f / lrow1;
    const int b = bh >> 4, h = bh & 15;
    const int r0 = qt * 64 + 16 * w + gr;
    const int r1 = r0 + 8;
    __nv_bfloat16* row0 = g_A3p + (size_t)(b * S_ + r0) * K3 + h * 64;
    __nv_bfloat16* row1 = g_A3p + (size_t)(b * S_ + r1) * K3 + h * 64;
#pragma unroll
    for (int g = 0; g < 8; g++) {
        const int d = 8 * g + 2 * tq;
        uint32_t h0, l0, h1, l1;
        split2(o[g][0] * i0, o[g][1] * i0, h0, l0);
        split2(o[g][2] * i1, o[g][3] * i1, h1, l1);
        *(uint32_t*)(row0 + d)          = h0;
        *(uint32_t*)(row0 + C_ + d)     = l0;
        *(uint32_t*)(row0 + 2 * C_ + d) = h0;
        *(uint32_t*)(row1 + d)          = h1;
        *(uint32_t*)(row1 + C_ + d)     = l1;
        *(uint32_t*)(row1 + 2 * C_ + d) = h1;
    }
}

// ---------------------------------------------------------------------------
extern "C" void kernel_launch(void* const* d_in, const int* in_sizes, int n_in,
                              void* d_out, int out_size)
{
    const float* x     = (const float*)d_in[0];
    const float* Wqkv  = (const float*)d_in[1];
    const float* bqkv  = (const float*)d_in[2];
    const float* Wproj = (const float*)d_in[3];
    const float* bproj = (const float*)d_in[4];
    float* out = (float*)d_out;

    __nv_bfloat16 *a3, *b3, *a3p, *b3p;
    cudaGetSymbolAddress((void**)&a3,  g_A3);
    cudaGetSymbolAddress((void**)&b3,  g_B3);
    cudaGetSymbolAddress((void**)&a3p, g_A3p);
    cudaGetSymbolAddress((void**)&b3p, g_B3p);

    // Phase 0: operand splitting / transposes
    split_x_kernel<<<M_TOT, 256>>>(x);
    tsplit_kernel<<<dim3(KV_N / 32, C_ / 32), 256>>>(Wqkv + C_, b3, 3 * C_);
    tsplit_kernel<<<dim3(C_ / 32, C_ / 32), 256>>>(Wproj, b3p, C_);

    cudaFuncSetAttribute(gemm_bf16x3_kernel,
                         cudaFuncAttributeMaxDynamicSharedMemorySize,
                         GEMM_SMEM);

    // Phase 1: KV projection (bf16x3 tensor GEMM) -> split K(scaled)/V
    {
        dim3 grid(KV_N / 128, M_TOT / 128);   // (16, 64)
        gemm_bf16x3_kernel<<<grid, 256, GEMM_SMEM>>>(a3, b3, bqkv + C_, nullptr, 0);
    }

    // Phase 2: causal attention on mma.sync (q = k)
    {
        cudaFuncSetAttribute(attn_mma_kernel,
                             cudaFuncAttributeMaxDynamicSharedMemorySize,
                             ATT_SMEM);
        dim3 grid(S_ / 64, B_ * H_);          // (16, 128)
        attn_mma_kernel<<<grid, 128, ATT_SMEM>>>();
    }

    // Phase 3: output projection (bf16x3 tensor GEMM)
    {
        dim3 grid(C_ / 128, M_TOT / 128);     // (8, 64)
        gemm_bf16x3_kernel<<<grid, 256, GEMM_SMEM>>>(a3p, b3p, bproj, out, 1);
    }
}

// round 7
// speedup vs baseline: 3.5993x; 1.3036x over previous
#include <cuda_runtime.h>
#include <cuda_bf16.h>
#include <cuda_fp16.h>
#include <math.h>
#include <stddef.h>
#include <stdint.h>

// Problem constants
#define B_  8
#define S_  1024
#define C_  1024
#define H_  16
#define D_  64
#define M_TOT (B_ * S_)          // 8192
#define KV_N  (2 * C_)           // 2048
#define K2    (2 * C_)           // 2048 (doubled-K for fp16 2-term split GEMM)

// sqrt(0.125 * log2(e)) — folded into K so S-MMA yields exp2-domain scores
#define KSCALE 0.42466089f

// Scratch (device globals; no runtime allocation allowed)
__device__ __nv_bfloat16 g_Kh[(size_t)B_ * H_ * S_ * D_];   // K hi (pre-scaled)
__device__ __nv_bfloat16 g_Kl[(size_t)B_ * H_ * S_ * D_];   // K lo
__device__ __nv_bfloat16 g_Vh[(size_t)B_ * H_ * S_ * D_];   // V hi
__device__ __nv_bfloat16 g_Vl[(size_t)B_ * H_ * S_ * D_];   // V lo
__device__ __half g_A2 [(size_t)M_TOT * K2];                // x split    [hi|lo]
__device__ __half g_B2 [(size_t)KV_N  * K2];                // Wqkv_kv^T  [hi|hi]
__device__ __half g_A2p[(size_t)M_TOT * K2];                // attn out   [hi|lo]
__device__ __half g_B2p[(size_t)C_    * K2];                // Wproj^T    [hi|hi]

// ---------------------------------------------------------------------------
// PTX helpers (base-sm_100-legal)
// ---------------------------------------------------------------------------
__device__ __forceinline__ uint32_t smem_u32(const void* p) {
    uint32_t a;
    asm("{ .reg .u64 t; cvta.to.shared.u64 t, %1; cvt.u32.u64 %0, t; }" : "=r"(a) : "l"(p));
    return a;
}
__device__ __forceinline__ void cpasync16(uint32_t saddr, const void* g) {
    asm volatile("cp.async.cg.shared.global [%0], [%1], 16;" :: "r"(saddr), "l"(g) : "memory");
}
#define CP_COMMIT() asm volatile("cp.async.commit_group;" ::: "memory")
#define CP_WAIT(n)  asm volatile("cp.async.wait_group %0;" :: "n"(n) : "memory")

__device__ __forceinline__ void ldsm4(uint32_t* r, uint32_t addr) {
    asm volatile("ldmatrix.sync.aligned.m8n8.x4.shared.b16 {%0,%1,%2,%3}, [%4];"
                 : "=r"(r[0]), "=r"(r[1]), "=r"(r[2]), "=r"(r[3]) : "r"(addr));
}
__device__ __forceinline__ void ldsm4t(uint32_t* r, uint32_t addr) {
    asm volatile("ldmatrix.sync.aligned.m8n8.x4.trans.shared.b16 {%0,%1,%2,%3}, [%4];"
                 : "=r"(r[0]), "=r"(r[1]), "=r"(r[2]), "=r"(r[3]) : "r"(addr));
}
// bf16 MMA (attention)
__device__ __forceinline__ void mma16816(float* c, const uint32_t* a, const uint32_t* b) {
    asm volatile(
        "mma.sync.aligned.m16n8k16.row.col.f32.bf16.bf16.f32 "
        "{%0,%1,%2,%3}, {%4,%5,%6,%7}, {%8,%9}, {%0,%1,%2,%3};"
        : "+f"(c[0]), "+f"(c[1]), "+f"(c[2]), "+f"(c[3])
        : "r"(a[0]), "r"(a[1]), "r"(a[2]), "r"(a[3]), "r"(b[0]), "r"(b[1]));
}
// fp16 MMA (GEMMs)
__device__ __forceinline__ void mma16816h(float* c, const uint32_t* a, const uint32_t* b) {
    asm volatile(
        "mma.sync.aligned.m16n8k16.row.col.f32.f16.f16.f32 "
        "{%0,%1,%2,%3}, {%4,%5,%6,%7}, {%8,%9}, {%0,%1,%2,%3};"
        : "+f"(c[0]), "+f"(c[1]), "+f"(c[2]), "+f"(c[3])
        : "r"(a[0]), "r"(a[1]), "r"(a[2]), "r"(a[3]), "r"(b[0]), "r"(b[1]));
}

// Swizzled smem offset for a 16B chunk of a [rows][64B] tile (GEMM tiles).
__device__ __forceinline__ uint32_t sw_off(int row, int c) {
    return (uint32_t)(((row >> 1) << 7) +
                      ((((((row & 1) << 2) | c)) ^ ((row >> 1) & 7)) << 4));
}
// Swizzled smem offset for [64 rows][128B] attention tiles: chunk c (0..7).
__device__ __forceinline__ uint32_t toff(int r, int c) {
    return (uint32_t)(r * 128 + (((c) ^ (r & 7)) << 4));
}
// split a,b fp32 -> packed bf16x2 hi and lo
__device__ __forceinline__ void split2(float a, float b, uint32_t& hi, uint32_t& lo) {
    __nv_bfloat162 h = __floats2bfloat162_rn(a, b);
    __nv_bfloat162 l = __floats2bfloat162_rn(a - __bfloat162float(h.x),
                                             b - __bfloat162float(h.y));
    hi = *(uint32_t*)&h; lo = *(uint32_t*)&l;
}
// split a,b fp32 -> packed half2 hi and lo
__device__ __forceinline__ void split2h(float a, float b, uint32_t& hi, uint32_t& lo) {
    __half2 h = __floats2half2_rn(a, b);
    __half2 l = __floats2half2_rn(a - __half2float(__low2half(h)),
                                  b - __half2float(__high2half(h)));
    hi = *(uint32_t*)&h; lo = *(uint32_t*)&l;
}

// ---------------------------------------------------------------------------
// fp16 2-term GEMM:  C = A2 @ B2^T + bias.  A2=[Ah|Al], B2=[Bh|Bh], K'=2048.
// 3-stage cp.async pipeline, 1 sync/stage.
// mode 0: epilogue splits+scatters to g_Kh/g_Kl (scaled) and g_Vh/g_Vl (bf16).
// mode 1: writes fp32 out[m*1024+n].
// ---------------------------------------------------------------------------
#define NSTAGE (K2 / 32)          // 64
#define GSTAGE_B 16384            // A 8K + B 8K per stage
#define GEMM_SMEM (3 * GSTAGE_B)  // 49152

__device__ __forceinline__ void gemm_load_stage(
    const __half* __restrict__ Ag, const __half* __restrict__ Bg,
    int kb, uint32_t Ab, uint32_t Bb, int tid)
{
#pragma unroll
    for (int i = 0; i < 2; i++) {
        const int idx = tid + i * 256;
        const int r = idx >> 2, c = idx & 3;
        const size_t g = (size_t)r * K2 + kb * 32 + c * 8;
        cpasync16(Ab + sw_off(r, c), Ag + g);
        cpasync16(Bb + sw_off(r, c), Bg + g);
    }
}

__global__ __launch_bounds__(256) void gemm_fp16x2_kernel(
    const __half* __restrict__ Ag, const __half* __restrict__ Bg,
    const float* __restrict__ bias, float* __restrict__ out, int mode)
{
    extern __shared__ __align__(1024) uint8_t gsm[];
    const uint32_t smb = smem_u32(gsm);

    const int tid  = threadIdx.x;
    const int lane = tid & 31;
    const int wid  = tid >> 5;
    const int wm = (wid >> 2) * 64;
    const int wn = (wid & 3) * 32;
    const int bn = blockIdx.x, bm = blockIdx.y;

    const __half* Arow = Ag + (size_t)(bm * 128) * K2;
    const __half* Brow = Bg + (size_t)(bn * 128) * K2;

    float acc[4][4][4];
#pragma unroll
    for (int f = 0; f < 4; f++)
#pragma unroll
        for (int g = 0; g < 4; g++)
#pragma unroll
            for (int r = 0; r < 4; r++) acc[f][g][r] = 0.0f;

    // prologue: prefetch stages 0 and 1
    gemm_load_stage(Arow, Brow, 0, smb, smb + 8192, tid);
    CP_COMMIT();
    gemm_load_stage(Arow, Brow, 1, smb + GSTAGE_B, smb + GSTAGE_B + 8192, tid);
    CP_COMMIT();

    int buf = 0, pbuf = 2;
    for (int kb = 0; kb < NSTAGE; kb++) {
        CP_WAIT(1);
        __syncthreads();

        const uint32_t Ab = smb + buf * GSTAGE_B;
        const uint32_t Bb = Ab + 8192;
#pragma unroll
        for (int ks = 0; ks < 2; ks++) {
            uint32_t a[4][4], b[4][2];
            const int ar = lane & 15;
            const int ac = ks * 2 + (lane >> 4);
#pragma unroll
            for (int f = 0; f < 4; f++)
                ldsm4(a[f], Ab + sw_off(wm + f * 16 + ar, ac));

            const int br = (lane & 7) + ((lane >> 4) << 3);
            const int bc = ks * 2 + ((lane >> 3) & 1);
#pragma unroll
            for (int p = 0; p < 2; p++) {
                uint32_t r4[4];
                ldsm4(r4, Bb + sw_off(wn + p * 16 + br, bc));
                b[2 * p][0] = r4[0]; b[2 * p][1] = r4[1];
                b[2 * p + 1][0] = r4[2]; b[2 * p + 1][1] = r4[3];
            }
#pragma unroll
            for (int f = 0; f < 4; f++)
#pragma unroll
                for (int g = 0; g < 4; g++)
                    mma16816h(acc[f][g], a[f], b[g]);
        }

        if (kb + 2 < NSTAGE) {
            gemm_load_stage(Arow, Brow, kb + 2,
                            smb + pbuf * GSTAGE_B, smb + pbuf * GSTAGE_B + 8192, tid);
        }
        CP_COMMIT();

        buf = (buf == 2) ? 0 : buf + 1;
        pbuf = (pbuf == 2) ? 0 : pbuf + 1;
    }

    const int gr = lane >> 2;
    const int tcol = (lane & 3) * 2;
#pragma unroll
    for (int f = 0; f < 4; f++) {
        const int r0 = bm * 128 + wm + f * 16 + gr;
        const int b_ = r0 >> 10, s_ = r0 & 1023;
        const int r1 = r0 + 8;
        const int b1_ = r1 >> 10, s1_ = r1 & 1023;
#pragma unroll
        for (int g = 0; g < 4; g++) {
            const int cc = wn + g * 8 + tcol;
            const int n = bn * 128 + cc;
            const float bx = bias[n], by = bias[n + 1];
            float2 v0 = make_float2(acc[f][g][0] + bx, acc[f][g][1] + by);
            float2 v1 = make_float2(acc[f][g][2] + bx, acc[f][g][3] + by);
            if (mode == 0) {
                const int np = n & (C_ - 1);
                const int hh = np >> 6, dd = np & 63;
                const size_t o0 = (((size_t)(b_  * H_ + hh)) * S_ + s_ ) * D_ + dd;
                const size_t o1 = (((size_t)(b1_ * H_ + hh)) * S_ + s1_) * D_ + dd;
                if (n < C_) {   // K: scale then split (bf16 for attention)
                    v0.x *= KSCALE; v0.y *= KSCALE; v1.x *= KSCALE; v1.y *= KSCALE;
                    uint32_t h0, l0, h1, l1;
                    split2(v0.x, v0.y, h0, l0);
                    split2(v1.x, v1.y, h1, l1);
                    *(uint32_t*)&g_Kh[o0] = h0; *(uint32_t*)&g_Kl[o0] = l0;
                    *(uint32_t*)&g_Kh[o1] = h1; *(uint32_t*)&g_Kl[o1] = l1;
                } else {        // V: split (bf16)
                    uint32_t h0, l0, h1, l1;
                    split2(v0.x, v0.y, h0, l0);
                    split2(v1.x, v1.y, h1, l1);
                    *(uint32_t*)&g_Vh[o0] = h0; *(uint32_t*)&g_Vl[o0] = l0;
                    *(uint32_t*)&g_Vh[o1] = h1; *(uint32_t*)&g_Vl[o1] = l1;
                }
            } else {
                *(float2*)&out[(size_t)r0 * C_ + n] = v0;
                *(float2*)&out[(size_t)r1 * C_ + n] = v1;
            }
        }
    }
}

// ---------------------------------------------------------------------------
// split_x: x fp32 [8192][1024] -> g_A2 fp16 [8192][2048] as [hi | lo]
// ---------------------------------------------------------------------------
__global__ __launch_bounds__(256) void split_x_kernel(const float* __restrict__ x)
{
    const int idx = blockIdx.x * 256 + threadIdx.x;
    const int m = idx >> 8;
    const int k = (idx & 255) << 2;
    const float4 v = *(const float4*)&x[(size_t)m * C_ + k];

    uint32_t h01, l01, h23, l23;
    split2h(v.x, v.y, h01, l01);
    split2h(v.z, v.w, h23, l23);

    __half* row = g_A2 + (size_t)m * K2;
    *(uint32_t*)(row + k)          = h01;
    *(uint32_t*)(row + k + 2)      = h23;
    *(uint32_t*)(row + C_ + k)     = l01;
    *(uint32_t*)(row + C_ + k + 2) = l23;
}

// ---------------------------------------------------------------------------
// tsplit: W fp32 [1024][srcld] col block -> dst fp16 [n][2048] as [hi | hi]
// ---------------------------------------------------------------------------
__global__ __launch_bounds__(256) void tsplit_kernel(
    const float* __restrict__ src, __half* __restrict__ dst, int srcld)
{
    __shared__ float t[32][33];
    const int n0 = blockIdx.x * 32, k0 = blockIdx.y * 32;
    const int tx = threadIdx.x & 31, ty = threadIdx.x >> 5;
#pragma unroll
    for (int i = 0; i < 4; i++)
        t[ty + i * 8][tx] = src[(size_t)(k0 + ty + i * 8) * srcld + n0 + tx];
    __syncthreads();
#pragma unroll
    for (int i = 0; i < 4; i++) {
        const int n = n0 + ty + i * 8;
        const int k = k0 + tx;
        const __half h = __float2half_rn(t[tx][ty + i * 8]);
        __half* row = dst + (size_t)n * K2;
        row[k] = h;
        row[C_ + k] = h;
    }
}

// ---------------------------------------------------------------------------
// MMA flash attention (bf16 3-term, unchanged except fp16 [hi|lo] epilogue).
// ---------------------------------------------------------------------------
#define STAGE_B 32768
#define SM_Q    0
#define SM_STG  16384
#define ATT_SMEM (16384 + 2 * STAGE_B)     // 81920

__device__ __forceinline__ void att_load_tile(
    uint32_t dst, const __nv_bfloat16* Kh, const __nv_bfloat16* Kl,
    const __nv_bfloat16* Vh, const __nv_bfloat16* Vl, int jt, int tid)
{
    const size_t gb = (size_t)jt * 8192;
#pragma unroll
    for (int i = 0; i < 4; i++) {
        const int idx = tid + i * 128;
        const int r = idx >> 3, c = idx & 7;
        const uint32_t so = toff(r, c);
        const size_t go = gb + (size_t)r * 128 + c * 16;
        cpasync16(dst +         so, (const char*)Kh + go);
        cpasync16(dst +  8192 + so, (const char*)Kl + go);
        cpasync16(dst + 16384 + so, (const char*)Vh + go);
        cpasync16(dst + 24576 + so, (const char*)Vl + go);
    }
}

__global__ __launch_bounds__(128) void attn_mma_kernel()
{
    extern __shared__ uint8_t asmem[];
    const uint32_t smb = smem_u32(asmem);
    const int tid = threadIdx.x, lane = tid & 31, w = tid >> 5;
    const int qt = blockIdx.x, bh = blockIdx.y;
    const int gr = lane >> 2, tq = lane & 3;

    const __nv_bfloat16* Kh = g_Kh + (size_t)bh * S_ * D_;
    const __nv_bfloat16* Kl = g_Kl + (size_t)bh * S_ * D_;
    const __nv_bfloat16* Vh = g_Vh + (size_t)bh * S_ * D_;
    const __nv_bfloat16* Vl = g_Vl + (size_t)bh * S_ * D_;

    {
        const size_t gb = (size_t)qt * 8192;
#pragma unroll
        for (int i = 0; i < 4; i++) {
            const int idx = tid + i * 128;
            const int r = idx >> 3, c = idx & 7;
            const uint32_t so = toff(r, c);
            const size_t go = gb + (size_t)r * 128 + c * 16;
            cpasync16(smb + SM_Q +        so, (const char*)Kh + go);
            cpasync16(smb + SM_Q + 8192 + so, (const char*)Kl + go);
        }
        CP_COMMIT();
        att_load_tile(smb + SM_STG, Kh, Kl, Vh, Vl, 0, tid);
        CP_COMMIT();
    }

    uint32_t qh[4][4], ql[4][4];
    float o[8][4];
#pragma unroll
    for (int g = 0; g < 8; g++)
#pragma unroll
        for (int r = 0; r < 4; r++) o[g][r] = 0.0f;
    float mrow0 = -1e30f, mrow1 = -1e30f, lrow0 = 0.0f, lrow1 = 0.0f;

    const int ar = lane & 15, hc = lane >> 4;
    const int br = (lane & 7) + ((lane >> 4) << 3);
    const int bcs = (lane >> 3) & 1;
    const int vr = (lane & 7) + (((lane >> 3) & 1) << 3);
    const int vcs = lane >> 4;

    for (int jt = 0; jt <= qt; jt++) {
        const uint32_t Kb = smb + SM_STG + (jt & 1) * STAGE_B;
        if (jt < qt) {
            att_load_tile(smb + SM_STG + ((jt + 1) & 1) * STAGE_B,
                          Kh, Kl, Vh, Vl, jt + 1, tid);
            CP_COMMIT();
            CP_WAIT(1);
        } else {
            CP_WAIT(0);
        }
        __syncthreads();

        if (jt == 0) {
#pragma unroll
            for (int ks = 0; ks < 4; ks++) {
                ldsm4(qh[ks], smb + SM_Q +        toff(16 * w + ar, 2 * ks + hc));
                ldsm4(ql[ks], smb + SM_Q + 8192 + toff(16 * w + ar, 2 * ks + hc));
            }
        }

        float s[8][4];
#pragma unroll
        for (int g = 0; g < 8; g++)
#pragma unroll
            for (int r = 0; r < 4; r++) s[g][r] = 0.0f;
#pragma unroll
        for (int ks = 0; ks < 4; ks++) {
#pragma unroll
            for (int p = 0; p < 4; p++) {
                uint32_t kh4[4], kl4[4];
                ldsm4(kh4, Kb +        toff(16 * p + br, 2 * ks + bcs));
                ldsm4(kl4, Kb + 8192 + toff(16 * p + br, 2 * ks + bcs));
                mma16816(s[2 * p],     qh[ks], kh4);
                mma16816(s[2 * p + 1], qh[ks], kh4 + 2);
                mma16816(s[2 * p],     qh[ks], kl4);
                mma16816(s[2 * p + 1], qh[ks], kl4 + 2);
                mma16816(s[2 * p],     ql[ks], kh4);
                mma16816(s[2 * p + 1], ql[ks], kh4 + 2);
            }
        }

        if (jt == qt) {
            const int rb = 16 * w + gr;
#pragma unroll
            for (int g = 0; g < 8; g++) {
                const int c0 = 8 * g + 2 * tq;
                if (c0     > rb)     s[g][0] = -1e30f;
                if (c0 + 1 > rb)     s[g][1] = -1e30f;
                if (c0     > rb + 8) s[g][2] = -1e30f;
                if (c0 + 1 > rb + 8) s[g][3] = -1e30f;
            }
        }

        float mx0 = -1e30f, mx1 = -1e30f;
#pragma unroll
        for (int g = 0; g < 8; g++) {
            mx0 = fmaxf(mx0, fmaxf(s[g][0], s[g][1]));
            mx1 = fmaxf(mx1, fmaxf(s[g][2], s[g][3]));
        }
        mx0 = fmaxf(mx0, __shfl_xor_sync(0xffffffffu, mx0, 1));
        mx0 = fmaxf(mx0, __shfl_xor_sync(0xffffffffu, mx0, 2));
        mx1 = fmaxf(mx1, __shfl_xor_sync(0xffffffffu, mx1, 1));
        mx1 = fmaxf(mx1, __shfl_xor_sync(0xffffffffu, mx1, 2));
        const float mn0 = fmaxf(mrow0, mx0), mn1 = fmaxf(mrow1, mx1);
        const float a0 = exp2f(mrow0 - mn0), a1 = exp2f(mrow1 - mn1);
        mrow0 = mn0; mrow1 = mn1;
        float sum0 = 0.0f, sum1 = 0.0f;
#pragma unroll
        for (int g = 0; g < 8; g++) {
            s[g][0] = exp2f(s[g][0] - mn0); sum0 += s[g][0];
            s[g][1] = exp2f(s[g][1] - mn0); sum0 += s[g][1];
            s[g][2] = exp2f(s[g][2] - mn1); sum1 += s[g][2];
            s[g][3] = exp2f(s[g][3] - mn1); sum1 += s[g][3];
        }
        sum0 += __shfl_xor_sync(0xffffffffu, sum0, 1);
        sum0 += __shfl_xor_sync(0xffffffffu, sum0, 2);
        sum1 += __shfl_xor_sync(0xffffffffu, sum1, 1);
        sum1 += __shfl_xor_sync(0xffffffffu, sum1, 2);
        lrow0 = lrow0 * a0 + sum0;
        lrow1 = lrow1 * a1 + sum1;
#pragma unroll
        for (int g = 0; g < 8; g++) {
            o[g][0] *= a0; o[g][1] *= a0; o[g][2] *= a1; o[g][3] *= a1;
        }

#pragma unroll
        for (int ks = 0; ks < 4; ks++) {
            uint32_t ph[4], pl[4];
            split2(s[2 * ks][0],     s[2 * ks][1],     ph[0], pl[0]);
            split2(s[2 * ks][2],     s[2 * ks][3],     ph[1], pl[1]);
            split2(s[2 * ks + 1][0], s[2 * ks + 1][1], ph[2], pl[2]);
            split2(s[2 * ks + 1][2], s[2 * ks + 1][3], ph[3], pl[3]);
#pragma unroll
            for (int p2 = 0; p2 < 4; p2++) {
                uint32_t vh4[4], vl4[4];
                ldsm4t(vh4, Kb + 16384 + toff(16 * ks + vr, 2 * p2 + vcs));
                ldsm4t(vl4, Kb + 24576 + toff(16 * ks + vr, 2 * p2 + vcs));
                mma16816(o[2 * p2],     ph, vh4);
                mma16816(o[2 * p2 + 1], ph, vh4 + 2);
                mma16816(o[2 * p2],     ph, vl4);
                mma16816(o[2 * p2 + 1], ph, vl4 + 2);
                mma16816(o[2 * p2],     pl, vh4);
                mma16816(o[2 * p2 + 1], pl, vh4 + 2);
            }
        }
        __syncthreads();
    }

    // Epilogue: normalize, split fp16, write [hi | lo] rows into g_A2p
    const float i0 = 1.0f / lrow0, i1 = 1.0f / lrow1;
    const int b = bh >> 4, h = bh & 15;
    const int r0 = qt * 64 + 16 * w + gr;
    const int r1 = r0 + 8;
    __half* row0 = g_A2p + (size_t)(b * S_ + r0) * K2 + h * 64;
    __half* row1 = g_A2p + (size_t)(b * S_ + r1) * K2 + h * 64;
#pragma unroll
    for (int g = 0; g < 8; g++) {
        const int d = 8 * g + 2 * tq;
        uint32_t h0, l0, h1, l1;
        split2h(o[g][0] * i0, o[g][1] * i0, h0, l0);
        split2h(o[g][2] * i1, o[g][3] * i1, h1, l1);
        *(uint32_t*)(row0 + d)      = h0;
        *(uint32_t*)(row0 + C_ + d) = l0;
        *(uint32_t*)(row1 + d)      = h1;
        *(uint32_t*)(row1 + C_ + d) = l1;
    }
}

// ---------------------------------------------------------------------------
extern "C" void kernel_launch(void* const* d_in, const int* in_sizes, int n_in,
                              void* d_out, int out_size)
{
    const float* x     = (const float*)d_in[0];
    const float* Wqkv  = (const float*)d_in[1];
    const float* bqkv  = (const float*)d_in[2];
    const float* Wproj = (const float*)d_in[3];
    const float* bproj = (const float*)d_in[4];
    float* out = (float*)d_out;

    __half *a2, *b2, *a2p, *b2p;
    cudaGetSymbolAddress((void**)&a2,  g_A2);
    cudaGetSymbolAddress((void**)&b2,  g_B2);
    cudaGetSymbolAddress((void**)&a2p, g_A2p);
    cudaGetSymbolAddress((void**)&b2p, g_B2p);

    // Phase 0: operand splitting / transposes
    split_x_kernel<<<M_TOT, 256>>>(x);
    tsplit_kernel<<<dim3(KV_N / 32, C_ / 32), 256>>>(Wqkv + C_, b2, 3 * C_);
    tsplit_kernel<<<dim3(C_ / 32, C_ / 32), 256>>>(Wproj, b2p, C_);

    cudaFuncSetAttribute(gemm_fp16x2_kernel,
                         cudaFuncAttributeMaxDynamicSharedMemorySize,
                         GEMM_SMEM);

    // Phase 1: KV projection (fp16 2-term tensor GEMM) -> split K(scaled)/V
    {
        dim3 grid(KV_N / 128, M_TOT / 128);   // (16, 64)
        gemm_fp16x2_kernel<<<grid, 256, GEMM_SMEM>>>(a2, b2, bqkv + C_, nullptr, 0);
    }

    // Phase 2: causal attention on mma.sync (q = k)
    {
        cudaFuncSetAttribute(attn_mma_kernel,
                             cudaFuncAttributeMaxDynamicSharedMemorySize,
                             ATT_SMEM);
        dim3 grid(S_ / 64, B_ * H_);          // (16, 128)
        attn_mma_kernel<<<grid, 128, ATT_SMEM>>>();
    }

    // Phase 3: output projection (fp16 2-term tensor GEMM)
    {
        dim3 grid(C_ / 128, M_TOT / 128);     // (8, 64)
        gemm_fp16x2_kernel<<<grid, 256, GEMM_SMEM>>>(a2p, b2p, bproj, out, 1);
    }
}

// round 8
// speedup vs baseline: 5.0738x; 1.4097x over previous
#include <cuda_runtime.h>
#include <cuda_bf16.h>
#include <cuda_fp16.h>
#include <math.h>
#include <stddef.h>
#include <stdint.h>

// Problem constants
#define B_  8
#define S_  1024
#define C_  1024
#define H_  16
#define D_  64
#define M_TOT (B_ * S_)          // 8192
#define KV_N  (2 * C_)           // 2048
#define KC    C_                 // 1024 (plain fp16 1-term GEMM K)

// sqrt(0.125 * log2(e)) — folded into K so S-MMA yields exp2-domain scores
#define KSCALE 0.42466089f

// Scratch (device globals; no runtime allocation allowed)
__device__ __nv_bfloat16 g_Kh[(size_t)B_ * H_ * S_ * D_];   // K hi (pre-scaled)
__device__ __nv_bfloat16 g_Kl[(size_t)B_ * H_ * S_ * D_];   // K lo
__device__ __nv_bfloat16 g_Vh[(size_t)B_ * H_ * S_ * D_];   // V hi
__device__ __nv_bfloat16 g_Vl[(size_t)B_ * H_ * S_ * D_];   // V lo
__device__ __half g_A2 [(size_t)M_TOT * KC];                // x fp16
__device__ __half g_B2 [(size_t)KV_N  * KC];                // Wqkv_kv^T fp16
__device__ __half g_A2p[(size_t)M_TOT * KC];                // attn out fp16
__device__ __half g_B2p[(size_t)C_    * KC];                // Wproj^T fp16

// ---------------------------------------------------------------------------
// PTX helpers (base-sm_100-legal)
// ---------------------------------------------------------------------------
__device__ __forceinline__ uint32_t smem_u32(const void* p) {
    uint32_t a;
    asm("{ .reg .u64 t; cvta.to.shared.u64 t, %1; cvt.u32.u64 %0, t; }" : "=r"(a) : "l"(p));
    return a;
}
__device__ __forceinline__ void cpasync16(uint32_t saddr, const void* g) {
    asm volatile("cp.async.cg.shared.global [%0], [%1], 16;" :: "r"(saddr), "l"(g) : "memory");
}
#define CP_COMMIT() asm volatile("cp.async.commit_group;" ::: "memory")
#define CP_WAIT(n)  asm volatile("cp.async.wait_group %0;" :: "n"(n) : "memory")

__device__ __forceinline__ void ldsm4(uint32_t* r, uint32_t addr) {
    asm volatile("ldmatrix.sync.aligned.m8n8.x4.shared.b16 {%0,%1,%2,%3}, [%4];"
                 : "=r"(r[0]), "=r"(r[1]), "=r"(r[2]), "=r"(r[3]) : "r"(addr));
}
__device__ __forceinline__ void ldsm4t(uint32_t* r, uint32_t addr) {
    asm volatile("ldmatrix.sync.aligned.m8n8.x4.trans.shared.b16 {%0,%1,%2,%3}, [%4];"
                 : "=r"(r[0]), "=r"(r[1]), "=r"(r[2]), "=r"(r[3]) : "r"(addr));
}
// bf16 MMA (attention)
__device__ __forceinline__ void mma16816(float* c, const uint32_t* a, const uint32_t* b) {
    asm volatile(
        "mma.sync.aligned.m16n8k16.row.col.f32.bf16.bf16.f32 "
        "{%0,%1,%2,%3}, {%4,%5,%6,%7}, {%8,%9}, {%0,%1,%2,%3};"
        : "+f"(c[0]), "+f"(c[1]), "+f"(c[2]), "+f"(c[3])
        : "r"(a[0]), "r"(a[1]), "r"(a[2]), "r"(a[3]), "r"(b[0]), "r"(b[1]));
}
// fp16 MMA (GEMMs)
__device__ __forceinline__ void mma16816h(float* c, const uint32_t* a, const uint32_t* b) {
    asm volatile(
        "mma.sync.aligned.m16n8k16.row.col.f32.f16.f16.f32 "
        "{%0,%1,%2,%3}, {%4,%5,%6,%7}, {%8,%9}, {%0,%1,%2,%3};"
        : "+f"(c[0]), "+f"(c[1]), "+f"(c[2]), "+f"(c[3])
        : "r"(a[0]), "r"(a[1]), "r"(a[2]), "r"(a[3]), "r"(b[0]), "r"(b[1]));
}

// Swizzled smem offset for a 16B chunk of a [rows][64B] tile (GEMM tiles).
__device__ __forceinline__ uint32_t sw_off(int row, int c) {
    return (uint32_t)(((row >> 1) << 7) +
                      ((((((row & 1) << 2) | c)) ^ ((row >> 1) & 7)) << 4));
}
// Swizzled smem offset for [64 rows][128B] attention tiles: chunk c (0..7).
__device__ __forceinline__ uint32_t toff(int r, int c) {
    return (uint32_t)(r * 128 + (((c) ^ (r & 7)) << 4));
}
// split a,b fp32 -> packed bf16x2 hi and lo
__device__ __forceinline__ void split2(float a, float b, uint32_t& hi, uint32_t& lo) {
    __nv_bfloat162 h = __floats2bfloat162_rn(a, b);
    __nv_bfloat162 l = __floats2bfloat162_rn(a - __bfloat162float(h.x),
                                             b - __bfloat162float(h.y));
    hi = *(uint32_t*)&h; lo = *(uint32_t*)&l;
}
__device__ __forceinline__ uint32_t pack_h2(float a, float b) {
    __half2 h = __floats2half2_rn(a, b);
    return *(uint32_t*)&h;
}

// ---------------------------------------------------------------------------
// fp16 1-term GEMM:  C = A2 @ B2^T + bias.  K=1024.
// 3-stage cp.async pipeline, 1 sync/stage.
// mode 0: epilogue splits+scatters to g_Kh/g_Kl (scaled) and g_Vh/g_Vl (bf16).
// mode 1: writes fp32 out[m*1024+n].
// ---------------------------------------------------------------------------
#define NSTAGE (KC / 32)          // 32
#define GSTAGE_B 16384            // A 8K + B 8K per stage
#define GEMM_SMEM (3 * GSTAGE_B)  // 49152

__device__ __forceinline__ void gemm_load_stage(
    const __half* __restrict__ Ag, const __half* __restrict__ Bg,
    int kb, uint32_t Ab, uint32_t Bb, int tid)
{
#pragma unroll
    for (int i = 0; i < 2; i++) {
        const int idx = tid + i * 256;
        const int r = idx >> 2, c = idx & 3;
        const size_t g = (size_t)r * KC + kb * 32 + c * 8;
        cpasync16(Ab + sw_off(r, c), Ag + g);
        cpasync16(Bb + sw_off(r, c), Bg + g);
    }
}

__global__ __launch_bounds__(256) void gemm_fp16_kernel(
    const __half* __restrict__ Ag, const __half* __restrict__ Bg,
    const float* __restrict__ bias, float* __restrict__ out, int mode)
{
    extern __shared__ __align__(1024) uint8_t gsm[];
    const uint32_t smb = smem_u32(gsm);

    const int tid  = threadIdx.x;
    const int lane = tid & 31;
    const int wid  = tid >> 5;
    const int wm = (wid >> 2) * 64;
    const int wn = (wid & 3) * 32;
    const int bn = blockIdx.x, bm = blockIdx.y;

    const __half* Arow = Ag + (size_t)(bm * 128) * KC;
    const __half* Brow = Bg + (size_t)(bn * 128) * KC;

    float acc[4][4][4];
#pragma unroll
    for (int f = 0; f < 4; f++)
#pragma unroll
        for (int g = 0; g < 4; g++)
#pragma unroll
            for (int r = 0; r < 4; r++) acc[f][g][r] = 0.0f;

    // prologue: prefetch stages 0 and 1
    gemm_load_stage(Arow, Brow, 0, smb, smb + 8192, tid);
    CP_COMMIT();
    gemm_load_stage(Arow, Brow, 1, smb + GSTAGE_B, smb + GSTAGE_B + 8192, tid);
    CP_COMMIT();

    int buf = 0, pbuf = 2;
    for (int kb = 0; kb < NSTAGE; kb++) {
        CP_WAIT(1);
        __syncthreads();

        const uint32_t Ab = smb + buf * GSTAGE_B;
        const uint32_t Bb = Ab + 8192;
#pragma unroll
        for (int ks = 0; ks < 2; ks++) {
            uint32_t a[4][4], b[4][2];
            const int ar = lane & 15;
            const int ac = ks * 2 + (lane >> 4);
#pragma unroll
            for (int f = 0; f < 4; f++)
                ldsm4(a[f], Ab + sw_off(wm + f * 16 + ar, ac));

            const int br = (lane & 7) + ((lane >> 4) << 3);
            const int bc = ks * 2 + ((lane >> 3) & 1);
#pragma unroll
            for (int p = 0; p < 2; p++) {
                uint32_t r4[4];
                ldsm4(r4, Bb + sw_off(wn + p * 16 + br, bc));
                b[2 * p][0] = r4[0]; b[2 * p][1] = r4[1];
                b[2 * p + 1][0] = r4[2]; b[2 * p + 1][1] = r4[3];
            }
#pragma unroll
            for (int f = 0; f < 4; f++)
#pragma unroll
                for (int g = 0; g < 4; g++)
                    mma16816h(acc[f][g], a[f], b[g]);
        }

        if (kb + 2 < NSTAGE) {
            gemm_load_stage(Arow, Brow, kb + 2,
                            smb + pbuf * GSTAGE_B, smb + pbuf * GSTAGE_B + 8192, tid);
        }
        CP_COMMIT();

        buf = (buf == 2) ? 0 : buf + 1;
        pbuf = (pbuf == 2) ? 0 : pbuf + 1;
    }

    const int gr = lane >> 2;
    const int tcol = (lane & 3) * 2;
#pragma unroll
    for (int f = 0; f < 4; f++) {
        const int r0 = bm * 128 + wm + f * 16 + gr;
        const int b_ = r0 >> 10, s_ = r0 & 1023;
        const int r1 = r0 + 8;
        const int b1_ = r1 >> 10, s1_ = r1 & 1023;
#pragma unroll
        for (int g = 0; g < 4; g++) {
            const int cc = wn + g * 8 + tcol;
            const int n = bn * 128 + cc;
            const float bx = bias[n], by = bias[n + 1];
            float2 v0 = make_float2(acc[f][g][0] + bx, acc[f][g][1] + by);
            float2 v1 = make_float2(acc[f][g][2] + bx, acc[f][g][3] + by);
            if (mode == 0) {
                const int np = n & (C_ - 1);
                const int hh = np >> 6, dd = np & 63;
                const size_t o0 = (((size_t)(b_  * H_ + hh)) * S_ + s_ ) * D_ + dd;
                const size_t o1 = (((size_t)(b1_ * H_ + hh)) * S_ + s1_) * D_ + dd;
                if (n < C_) {   // K: scale then split (bf16 for attention)
                    v0.x *= KSCALE; v0.y *= KSCALE; v1.x *= KSCALE; v1.y *= KSCALE;
                    uint32_t h0, l0, h1, l1;
                    split2(v0.x, v0.y, h0, l0);
                    split2(v1.x, v1.y, h1, l1);
                    *(uint32_t*)&g_Kh[o0] = h0; *(uint32_t*)&g_Kl[o0] = l0;
                    *(uint32_t*)&g_Kh[o1] = h1; *(uint32_t*)&g_Kl[o1] = l1;
                } else {        // V: split (bf16)
                    uint32_t h0, l0, h1, l1;
                    split2(v0.x, v0.y, h0, l0);
                    split2(v1.x, v1.y, h1, l1);
                    *(uint32_t*)&g_Vh[o0] = h0; *(uint32_t*)&g_Vl[o0] = l0;
                    *(uint32_t*)&g_Vh[o1] = h1; *(uint32_t*)&g_Vl[o1] = l1;
                }
            } else {
                *(float2*)&out[(size_t)r0 * C_ + n] = v0;
                *(float2*)&out[(size_t)r1 * C_ + n] = v1;
            }
        }
    }
}

// ---------------------------------------------------------------------------
// cvt_x: x fp32 [8192][1024] -> g_A2 fp16 [8192][1024]
// ---------------------------------------------------------------------------
__global__ __launch_bounds__(256) void cvt_x_kernel(const float* __restrict__ x)
{
    const int idx = blockIdx.x * 256 + threadIdx.x;
    const int m = idx >> 8;
    const int k = (idx & 255) << 2;
    const float4 v = *(const float4*)&x[(size_t)m * C_ + k];
    __half* row = g_A2 + (size_t)m * KC;
    *(uint32_t*)(row + k)     = pack_h2(v.x, v.y);
    *(uint32_t*)(row + k + 2) = pack_h2(v.z, v.w);
}

// ---------------------------------------------------------------------------
// tcvt: W fp32 [1024][srcld] col block -> dst fp16 [n][1024] transposed
// ---------------------------------------------------------------------------
__global__ __launch_bounds__(256) void tcvt_kernel(
    const float* __restrict__ src, __half* __restrict__ dst, int srcld)
{
    __shared__ float t[32][33];
    const int n0 = blockIdx.x * 32, k0 = blockIdx.y * 32;
    const int tx = threadIdx.x & 31, ty = threadIdx.x >> 5;
#pragma unroll
    for (int i = 0; i < 4; i++)
        t[ty + i * 8][tx] = src[(size_t)(k0 + ty + i * 8) * srcld + n0 + tx];
    __syncthreads();
#pragma unroll
    for (int i = 0; i < 4; i++) {
        const int n = n0 + ty + i * 8;
        const int k = k0 + tx;
        dst[(size_t)n * KC + k] = __float2half_rn(t[tx][ty + i * 8]);
    }
}

// ---------------------------------------------------------------------------
// MMA flash attention (bf16 3-term, unchanged; epilogue writes plain fp16).
// ---------------------------------------------------------------------------
#define STAGE_B 32768
#define SM_Q    0
#define SM_STG  16384
#define ATT_SMEM (16384 + 2 * STAGE_B)     // 81920

__device__ __forceinline__ void att_load_tile(
    uint32_t dst, const __nv_bfloat16* Kh, const __nv_bfloat16* Kl,
    const __nv_bfloat16* Vh, const __nv_bfloat16* Vl, int jt, int tid)
{
    const size_t gb = (size_t)jt * 8192;
#pragma unroll
    for (int i = 0; i < 4; i++) {
        const int idx = tid + i * 128;
        const int r = idx >> 3, c = idx & 7;
        const uint32_t so = toff(r, c);
        const size_t go = gb + (size_t)r * 128 + c * 16;
        cpasync16(dst +         so, (const char*)Kh + go);
        cpasync16(dst +  8192 + so, (const char*)Kl + go);
        cpasync16(dst + 16384 + so, (const char*)Vh + go);
        cpasync16(dst + 24576 + so, (const char*)Vl + go);
    }
}

__global__ __launch_bounds__(128) void attn_mma_kernel()
{
    extern __shared__ uint8_t asmem[];
    const uint32_t smb = smem_u32(asmem);
    const int tid = threadIdx.x, lane = tid & 31, w = tid >> 5;
    const int qt = blockIdx.x, bh = blockIdx.y;
    const int gr = lane >> 2, tq = lane & 3;

    const __nv_bfloat16* Kh = g_Kh + (size_t)bh * S_ * D_;
    const __nv_bfloat16* Kl = g_Kl + (size_t)bh * S_ * D_;
    const __nv_bfloat16* Vh = g_Vh + (size_t)bh * S_ * D_;
    const __nv_bfloat16* Vl = g_Vl + (size_t)bh * S_ * D_;

    {
        const size_t gb = (size_t)qt * 8192;
#pragma unroll
        for (int i = 0; i < 4; i++) {
            const int idx = tid + i * 128;
            const int r = idx >> 3, c = idx & 7;
            const uint32_t so = toff(r, c);
            const size_t go = gb + (size_t)r * 128 + c * 16;
            cpasync16(smb + SM_Q +        so, (const char*)Kh + go);
            cpasync16(smb + SM_Q + 8192 + so, (const char*)Kl + go);
        }
        CP_COMMIT();
        att_load_tile(smb + SM_STG, Kh, Kl, Vh, Vl, 0, tid);
        CP_COMMIT();
    }

    uint32_t qh[4][4], ql[4][4];
    float o[8][4];
#pragma unroll
    for (int g = 0; g < 8; g++)
#pragma unroll
        for (int r = 0; r < 4; r++) o[g][r] = 0.0f;
    float mrow0 = -1e30f, mrow1 = -1e30f, lrow0 = 0.0f, lrow1 = 0.0f;

    const int ar = lane & 15, hc = lane >> 4;
    const int br = (lane & 7) + ((lane >> 4) << 3);
    const int bcs = (lane >> 3) & 1;
    const int vr = (lane & 7) + (((lane >> 3) & 1) << 3);
    const int vcs = lane >> 4;

    for (int jt = 0; jt <= qt; jt++) {
        const uint32_t Kb = smb + SM_STG + (jt & 1) * STAGE_B;
        if (jt < qt) {
            att_load_tile(smb + SM_STG + ((jt + 1) & 1) * STAGE_B,
                          Kh, Kl, Vh, Vl, jt + 1, tid);
            CP_COMMIT();
            CP_WAIT(1);
        } else {
            CP_WAIT(0);
        }
        __syncthreads();

        if (jt == 0) {
#pragma unroll
            for (int ks = 0; ks < 4; ks++) {
                ldsm4(qh[ks], smb + SM_Q +        toff(16 * w + ar, 2 * ks + hc));
                ldsm4(ql[ks], smb + SM_Q + 8192 + toff(16 * w + ar, 2 * ks + hc));
            }
        }

        float s[8][4];
#pragma unroll
        for (int g = 0; g < 8; g++)
#pragma unroll
            for (int r = 0; r < 4; r++) s[g][r] = 0.0f;
#pragma unroll
        for (int ks = 0; ks < 4; ks++) {
#pragma unroll
            for (int p = 0; p < 4; p++) {
                uint32_t kh4[4], kl4[4];
                ldsm4(kh4, Kb +        toff(16 * p + br, 2 * ks + bcs));
                ldsm4(kl4, Kb + 8192 + toff(16 * p + br, 2 * ks + bcs));
                mma16816(s[2 * p],     qh[ks], kh4);
                mma16816(s[2 * p + 1], qh[ks], kh4 + 2);
                mma16816(s[2 * p],     qh[ks], kl4);
                mma16816(s[2 * p + 1], qh[ks], kl4 + 2);
                mma16816(s[2 * p],     ql[ks], kh4);
                mma16816(s[2 * p + 1], ql[ks], kh4 + 2);
            }
        }

        if (jt == qt) {
            const int rb = 16 * w + gr;
#pragma unroll
            for (int g = 0; g < 8; g++) {
                const int c0 = 8 * g + 2 * tq;
                if (c0     > rb)     s[g][0] = -1e30f;
                if (c0 + 1 > rb)     s[g][1] = -1e30f;
                if (c0     > rb + 8) s[g][2] = -1e30f;
                if (c0 + 1 > rb + 8) s[g][3] = -1e30f;
            }
        }

        float mx0 = -1e30f, mx1 = -1e30f;
#pragma unroll
        for (int g = 0; g < 8; g++) {
            mx0 = fmaxf(mx0, fmaxf(s[g][0], s[g][1]));
            mx1 = fmaxf(mx1, fmaxf(s[g][2], s[g][3]));
        }
        mx0 = fmaxf(mx0, __shfl_xor_sync(0xffffffffu, mx0, 1));
        mx0 = fmaxf(mx0, __shfl_xor_sync(0xffffffffu, mx0, 2));
        mx1 = fmaxf(mx1, __shfl_xor_sync(0xffffffffu, mx1, 1));
        mx1 = fmaxf(mx1, __shfl_xor_sync(0xffffffffu, mx1, 2));
        const float mn0 = fmaxf(mrow0, mx0), mn1 = fmaxf(mrow1, mx1);
        const float a0 = exp2f(mrow0 - mn0), a1 = exp2f(mrow1 - mn1);
        mrow0 = mn0; mrow1 = mn1;
        float sum0 = 0.0f, sum1 = 0.0f;
#pragma unroll
        for (int g = 0; g < 8; g++) {
            s[g][0] = exp2f(s[g][0] - mn0); sum0 += s[g][0];
            s[g][1] = exp2f(s[g][1] - mn0); sum0 += s[g][1];
            s[g][2] = exp2f(s[g][2] - mn1); sum1 += s[g][2];
            s[g][3] = exp2f(s[g][3] - mn1); sum1 += s[g][3];
        }
        sum0 += __shfl_xor_sync(0xffffffffu, sum0, 1);
        sum0 += __shfl_xor_sync(0xffffffffu, sum0, 2);
        sum1 += __shfl_xor_sync(0xffffffffu, sum1, 1);
        sum1 += __shfl_xor_sync(0xffffffffu, sum1, 2);
        lrow0 = lrow0 * a0 + sum0;
        lrow1 = lrow1 * a1 + sum1;
#pragma unroll
        for (int g = 0; g < 8; g++) {
            o[g][0] *= a0; o[g][1] *= a0; o[g][2] *= a1; o[g][3] *= a1;
        }

#pragma unroll
        for (int ks = 0; ks < 4; ks++) {
            uint32_t ph[4], pl[4];
            split2(s[2 * ks][0],     s[2 * ks][1],     ph[0], pl[0]);
            split2(s[2 * ks][2],     s[2 * ks][3],     ph[1], pl[1]);
            split2(s[2 * ks + 1][0], s[2 * ks + 1][1], ph[2], pl[2]);
            split2(s[2 * ks + 1][2], s[2 * ks + 1][3], ph[3], pl[3]);
#pragma unroll
            for (int p2 = 0; p2 < 4; p2++) {
                uint32_t vh4[4], vl4[4];
                ldsm4t(vh4, Kb + 16384 + toff(16 * ks + vr, 2 * p2 + vcs));
                ldsm4t(vl4, Kb + 24576 + toff(16 * ks + vr, 2 * p2 + vcs));
                mma16816(o[2 * p2],     ph, vh4);
                mma16816(o[2 * p2 + 1], ph, vh4 + 2);
                mma16816(o[2 * p2],     ph, vl4);
                mma16816(o[2 * p2 + 1], ph, vl4 + 2);
                mma16816(o[2 * p2],     pl, vh4);
                mma16816(o[2 * p2 + 1], pl, vh4 + 2);
            }
        }
        __syncthreads();
    }

    // Epilogue: normalize, write plain fp16 rows into g_A2p
    const float i0 = 1.0f / lrow0, i1 = 1.0f / lrow1;
    const int b = bh >> 4, h = bh & 15;
    const int r0 = qt * 64 + 16 * w + gr;
    const int r1 = r0 + 8;
    __half* row0 = g_A2p + (size_t)(b * S_ + r0) * KC + h * 64;
    __half* row1 = g_A2p + (size_t)(b * S_ + r1) * KC + h * 64;
#pragma unroll
    for (int g = 0; g < 8; g++) {
        const int d = 8 * g + 2 * tq;
        *(uint32_t*)(row0 + d) = pack_h2(o[g][0] * i0, o[g][1] * i0);
        *(uint32_t*)(row1 + d) = pack_h2(o[g][2] * i1, o[g][3] * i1);
    }
}

// ---------------------------------------------------------------------------
extern "C" void kernel_launch(void* const* d_in, const int* in_sizes, int n_in,
                              void* d_out, int out_size)
{
    const float* x     = (const float*)d_in[0];
    const float* Wqkv  = (const float*)d_in[1];
    const float* bqkv  = (const float*)d_in[2];
    const float* Wproj = (const float*)d_in[3];
    const float* bproj = (const float*)d_in[4];
    float* out = (float*)d_out;

    __half *a2, *b2, *a2p, *b2p;
    cudaGetSymbolAddress((void**)&a2,  g_A2);
    cudaGetSymbolAddress((void**)&b2,  g_B2);
    cudaGetSymbolAddress((void**)&a2p, g_A2p);
    cudaGetSymbolAddress((void**)&b2p, g_B2p);

    // Phase 0: fp16 conversion / transposes
    cvt_x_kernel<<<M_TOT, 256>>>(x);
    tcvt_kernel<<<dim3(KV_N / 32, C_ / 32), 256>>>(Wqkv + C_, b2, 3 * C_);
    tcvt_kernel<<<dim3(C_ / 32, C_ / 32), 256>>>(Wproj, b2p, C_);

    cudaFuncSetAttribute(gemm_fp16_kernel,
                         cudaFuncAttributeMaxDynamicSharedMemorySize,
                         GEMM_SMEM);

    // Phase 1: KV projection (fp16 tensor GEMM, K=1024) -> split K(scaled)/V
    {
        dim3 grid(KV_N / 128, M_TOT / 128);   // (16, 64)
        gemm_fp16_kernel<<<grid, 256, GEMM_SMEM>>>(a2, b2, bqkv + C_, nullptr, 0);
    }

    // Phase 2: causal attention on mma.sync (q = k)
    {
        cudaFuncSetAttribute(attn_mma_kernel,
                             cudaFuncAttributeMaxDynamicSharedMemorySize,
                             ATT_SMEM);
        dim3 grid(S_ / 64, B_ * H_);          // (16, 128)
        attn_mma_kernel<<<grid, 128, ATT_SMEM>>>();
    }

    // Phase 3: output projection (fp16 tensor GEMM, K=1024)
    {
        dim3 grid(C_ / 128, M_TOT / 128);     // (8, 64)
        gemm_fp16_kernel<<<grid, 256, GEMM_SMEM>>>(a2p, b2p, bproj, out, 1);
    }
}

// round 9
// speedup vs baseline: 5.8876x; 1.1604x over previous
#include <cuda_runtime.h>
#include <cuda_bf16.h>
#include <cuda_fp16.h>
#include <math.h>
#include <stddef.h>
#include <stdint.h>

// Problem constants
#define B_  8
#define S_  1024
#define C_  1024
#define H_  16
#define D_  64
#define M_TOT (B_ * S_)          // 8192
#define KV_N  (2 * C_)           // 2048
#define KC    C_                 // 1024 (plain fp16 1-term GEMM K)

// sqrt(0.125 * log2(e)) — folded into K so S-MMA yields exp2-domain scores
#define KSCALE 0.42466089f

// Scratch (device globals; no runtime allocation allowed)
__device__ __nv_bfloat16 g_Kh[(size_t)B_ * H_ * S_ * D_];   // K hi (pre-scaled)
__device__ __nv_bfloat16 g_Kl[(size_t)B_ * H_ * S_ * D_];   // K lo
__device__ __half        g_V16[(size_t)B_ * H_ * S_ * D_];  // V fp16 (1-term)
__device__ __half g_A2 [(size_t)M_TOT * KC];                // x fp16
__device__ __half g_B2 [(size_t)KV_N  * KC];                // Wqkv_kv^T fp16
__device__ __half g_A2p[(size_t)M_TOT * KC];                // attn out fp16
__device__ __half g_B2p[(size_t)C_    * KC];                // Wproj^T fp16

// ---------------------------------------------------------------------------
// PTX helpers (base-sm_100-legal)
// ---------------------------------------------------------------------------
__device__ __forceinline__ uint32_t smem_u32(const void* p) {
    uint32_t a;
    asm("{ .reg .u64 t; cvta.to.shared.u64 t, %1; cvt.u32.u64 %0, t; }" : "=r"(a) : "l"(p));
    return a;
}
__device__ __forceinline__ void cpasync16(uint32_t saddr, const void* g) {
    asm volatile("cp.async.cg.shared.global [%0], [%1], 16;" :: "r"(saddr), "l"(g) : "memory");
}
#define CP_COMMIT() asm volatile("cp.async.commit_group;" ::: "memory")
#define CP_WAIT(n)  asm volatile("cp.async.wait_group %0;" :: "n"(n) : "memory")

__device__ __forceinline__ void ldsm4(uint32_t* r, uint32_t addr) {
    asm volatile("ldmatrix.sync.aligned.m8n8.x4.shared.b16 {%0,%1,%2,%3}, [%4];"
                 : "=r"(r[0]), "=r"(r[1]), "=r"(r[2]), "=r"(r[3]) : "r"(addr));
}
__device__ __forceinline__ void ldsm4t(uint32_t* r, uint32_t addr) {
    asm volatile("ldmatrix.sync.aligned.m8n8.x4.trans.shared.b16 {%0,%1,%2,%3}, [%4];"
                 : "=r"(r[0]), "=r"(r[1]), "=r"(r[2]), "=r"(r[3]) : "r"(addr));
}
// bf16 MMA (attention S path)
__device__ __forceinline__ void mma16816(float* c, const uint32_t* a, const uint32_t* b) {
    asm volatile(
        "mma.sync.aligned.m16n8k16.row.col.f32.bf16.bf16.f32 "
        "{%0,%1,%2,%3}, {%4,%5,%6,%7}, {%8,%9}, {%0,%1,%2,%3};"
        : "+f"(c[0]), "+f"(c[1]), "+f"(c[2]), "+f"(c[3])
        : "r"(a[0]), "r"(a[1]), "r"(a[2]), "r"(a[3]), "r"(b[0]), "r"(b[1]));
}
// fp16 MMA (GEMMs + attention PV path)
__device__ __forceinline__ void mma16816h(float* c, const uint32_t* a, const uint32_t* b) {
    asm volatile(
        "mma.sync.aligned.m16n8k16.row.col.f32.f16.f16.f32 "
        "{%0,%1,%2,%3}, {%4,%5,%6,%7}, {%8,%9}, {%0,%1,%2,%3};"
        : "+f"(c[0]), "+f"(c[1]), "+f"(c[2]), "+f"(c[3])
        : "r"(a[0]), "r"(a[1]), "r"(a[2]), "r"(a[3]), "r"(b[0]), "r"(b[1]));
}

// Swizzled smem offset for a 16B chunk of a [rows][64B] tile (GEMM tiles).
__device__ __forceinline__ uint32_t sw_off(int row, int c) {
    return (uint32_t)(((row >> 1) << 7) +
                      ((((((row & 1) << 2) | c)) ^ ((row >> 1) & 7)) << 4));
}
// Swizzled smem offset for [64 rows][128B] attention tiles: chunk c (0..7).
__device__ __forceinline__ uint32_t toff(int r, int c) {
    return (uint32_t)(r * 128 + (((c) ^ (r & 7)) << 4));
}
// split a,b fp32 -> packed bf16x2 hi and lo
__device__ __forceinline__ void split2(float a, float b, uint32_t& hi, uint32_t& lo) {
    __nv_bfloat162 h = __floats2bfloat162_rn(a, b);
    __nv_bfloat162 l = __floats2bfloat162_rn(a - __bfloat162float(h.x),
                                             b - __bfloat162float(h.y));
    hi = *(uint32_t*)&h; lo = *(uint32_t*)&l;
}
__device__ __forceinline__ uint32_t pack_h2(float a, float b) {
    __half2 h = __floats2half2_rn(a, b);
    return *(uint32_t*)&h;
}

// ---------------------------------------------------------------------------
// fp16 1-term GEMM:  C = A2 @ B2^T + bias.  K=1024.
// 3-stage cp.async pipeline, 1 sync/stage.
// mode 0: epilogue scatters K (scaled, bf16 hi/lo) and V (fp16).
// mode 1: writes fp32 out[m*1024+n].
// ---------------------------------------------------------------------------
#define NSTAGE (KC / 32)          // 32
#define GSTAGE_B 16384            // A 8K + B 8K per stage
#define GEMM_SMEM (3 * GSTAGE_B)  // 49152

__device__ __forceinline__ void gemm_load_stage(
    const __half* __restrict__ Ag, const __half* __restrict__ Bg,
    int kb, uint32_t Ab, uint32_t Bb, int tid)
{
#pragma unroll
    for (int i = 0; i < 2; i++) {
        const int idx = tid + i * 256;
        const int r = idx >> 2, c = idx & 3;
        const size_t g = (size_t)r * KC + kb * 32 + c * 8;
        cpasync16(Ab + sw_off(r, c), Ag + g);
        cpasync16(Bb + sw_off(r, c), Bg + g);
    }
}

__global__ __launch_bounds__(256) void gemm_fp16_kernel(
    const __half* __restrict__ Ag, const __half* __restrict__ Bg,
    const float* __restrict__ bias, float* __restrict__ out, int mode)
{
    extern __shared__ __align__(1024) uint8_t gsm[];
    const uint32_t smb = smem_u32(gsm);

    const int tid  = threadIdx.x;
    const int lane = tid & 31;
    const int wid  = tid >> 5;
    const int wm = (wid >> 2) * 64;
    const int wn = (wid & 3) * 32;
    const int bn = blockIdx.x, bm = blockIdx.y;

    const __half* Arow = Ag + (size_t)(bm * 128) * KC;
    const __half* Brow = Bg + (size_t)(bn * 128) * KC;

    float acc[4][4][4];
#pragma unroll
    for (int f = 0; f < 4; f++)
#pragma unroll
        for (int g = 0; g < 4; g++)
#pragma unroll
            for (int r = 0; r < 4; r++) acc[f][g][r] = 0.0f;

    // prologue: prefetch stages 0 and 1
    gemm_load_stage(Arow, Brow, 0, smb, smb + 8192, tid);
    CP_COMMIT();
    gemm_load_stage(Arow, Brow, 1, smb + GSTAGE_B, smb + GSTAGE_B + 8192, tid);
    CP_COMMIT();

    int buf = 0, pbuf = 2;
    for (int kb = 0; kb < NSTAGE; kb++) {
        CP_WAIT(1);
        __syncthreads();

        const uint32_t Ab = smb + buf * GSTAGE_B;
        const uint32_t Bb = Ab + 8192;
#pragma unroll
        for (int ks = 0; ks < 2; ks++) {
            uint32_t a[4][4], b[4][2];
            const int ar = lane & 15;
            const int ac = ks * 2 + (lane >> 4);
#pragma unroll
            for (int f = 0; f < 4; f++)
                ldsm4(a[f], Ab + sw_off(wm + f * 16 + ar, ac));

            const int br = (lane & 7) + ((lane >> 4) << 3);
            const int bc = ks * 2 + ((lane >> 3) & 1);
#pragma unroll
            for (int p = 0; p < 2; p++) {
                uint32_t r4[4];
                ldsm4(r4, Bb + sw_off(wn + p * 16 + br, bc));
                b[2 * p][0] = r4[0]; b[2 * p][1] = r4[1];
                b[2 * p + 1][0] = r4[2]; b[2 * p + 1][1] = r4[3];
            }
#pragma unroll
            for (int f = 0; f < 4; f++)
#pragma unroll
                for (int g = 0; g < 4; g++)
                    mma16816h(acc[f][g], a[f], b[g]);
        }

        if (kb + 2 < NSTAGE) {
            gemm_load_stage(Arow, Brow, kb + 2,
                            smb + pbuf * GSTAGE_B, smb + pbuf * GSTAGE_B + 8192, tid);
        }
        CP_COMMIT();

        buf = (buf == 2) ? 0 : buf + 1;
        pbuf = (pbuf == 2) ? 0 : pbuf + 1;
    }

    const int gr = lane >> 2;
    const int tcol = (lane & 3) * 2;
#pragma unroll
    for (int f = 0; f < 4; f++) {
        const int r0 = bm * 128 + wm + f * 16 + gr;
        const int b_ = r0 >> 10, s_ = r0 & 1023;
        const int r1 = r0 + 8;
        const int b1_ = r1 >> 10, s1_ = r1 & 1023;
#pragma unroll
        for (int g = 0; g < 4; g++) {
            const int cc = wn + g * 8 + tcol;
            const int n = bn * 128 + cc;
            const float bx = bias[n], by = bias[n + 1];
            float2 v0 = make_float2(acc[f][g][0] + bx, acc[f][g][1] + by);
            float2 v1 = make_float2(acc[f][g][2] + bx, acc[f][g][3] + by);
            if (mode == 0) {
                const int np = n & (C_ - 1);
                const int hh = np >> 6, dd = np & 63;
                const size_t o0 = (((size_t)(b_  * H_ + hh)) * S_ + s_ ) * D_ + dd;
                const size_t o1 = (((size_t)(b1_ * H_ + hh)) * S_ + s1_) * D_ + dd;
                if (n < C_) {   // K: scale then split (bf16 hi/lo for S path)
                    v0.x *= KSCALE; v0.y *= KSCALE; v1.x *= KSCALE; v1.y *= KSCALE;
                    uint32_t h0, l0, h1, l1;
                    split2(v0.x, v0.y, h0, l0);
                    split2(v1.x, v1.y, h1, l1);
                    *(uint32_t*)&g_Kh[o0] = h0; *(uint32_t*)&g_Kl[o0] = l0;
                    *(uint32_t*)&g_Kh[o1] = h1; *(uint32_t*)&g_Kl[o1] = l1;
                } else {        // V: plain fp16
                    *(uint32_t*)&g_V16[o0] = pack_h2(v0.x, v0.y);
                    *(uint32_t*)&g_V16[o1] = pack_h2(v1.x, v1.y);
                }
            } else {
                *(float2*)&out[(size_t)r0 * C_ + n] = v0;
                *(float2*)&out[(size_t)r1 * C_ + n] = v1;
            }
        }
    }
}

// ---------------------------------------------------------------------------
// cvt_x: x fp32 [8192][1024] -> g_A2 fp16 [8192][1024]
// ---------------------------------------------------------------------------
__global__ __launch_bounds__(256) void cvt_x_kernel(const float* __restrict__ x)
{
    const int idx = blockIdx.x * 256 + threadIdx.x;
    const int m = idx >> 8;
    const int k = (idx & 255) << 2;
    const float4 v = *(const float4*)&x[(size_t)m * C_ + k];
    __half* row = g_A2 + (size_t)m * KC;
    *(uint32_t*)(row + k)     = pack_h2(v.x, v.y);
    *(uint32_t*)(row + k + 2) = pack_h2(v.z, v.w);
}

// ---------------------------------------------------------------------------
// tcvt: W fp32 [1024][srcld] col block -> dst fp16 [n][1024] transposed
// ---------------------------------------------------------------------------
__global__ __launch_bounds__(256) void tcvt_kernel(
    const float* __restrict__ src, __half* __restrict__ dst, int srcld)
{
    __shared__ float t[32][33];
    const int n0 = blockIdx.x * 32, k0 = blockIdx.y * 32;
    const int tx = threadIdx.x & 31, ty = threadIdx.x >> 5;
#pragma unroll
    for (int i = 0; i < 4; i++)
        t[ty + i * 8][tx] = src[(size_t)(k0 + ty + i * 8) * srcld + n0 + tx];
    __syncthreads();
#pragma unroll
    for (int i = 0; i < 4; i++) {
        const int n = n0 + ty + i * 8;
        const int k = k0 + tx;
        dst[(size_t)n * KC + k] = __float2half_rn(t[tx][ty + i * 8]);
    }
}

// ---------------------------------------------------------------------------
// MMA flash attention. S path: bf16 3-term (precision-critical).
// PV path: single-term fp16 (p fp16 x v fp16).
// smem: Q (Qh 8K + Ql 8K) + 2 stages x (Kh 8K | Kl 8K | V16 8K).
// ---------------------------------------------------------------------------
#define STAGE_B 24576
#define SM_Q    0
#define SM_STG  16384
#define ATT_SMEM (16384 + 2 * STAGE_B)     // 65536

__device__ __forceinline__ void att_load_tile(
    uint32_t dst, const __nv_bfloat16* Kh, const __nv_bfloat16* Kl,
    const __half* V16, int jt, int tid)
{
    const size_t gb = (size_t)jt * 8192;
#pragma unroll
    for (int i = 0; i < 4; i++) {
        const int idx = tid + i * 128;
        const int r = idx >> 3, c = idx & 7;
        const uint32_t so = toff(r, c);
        const size_t go = gb + (size_t)r * 128 + c * 16;
        cpasync16(dst +         so, (const char*)Kh  + go);
        cpasync16(dst +  8192 + so, (const char*)Kl  + go);
        cpasync16(dst + 16384 + so, (const char*)V16 + go);
    }
}

__global__ __launch_bounds__(128) void attn_mma_kernel()
{
    extern __shared__ uint8_t asmem[];
    const uint32_t smb = smem_u32(asmem);
    const int tid = threadIdx.x, lane = tid & 31, w = tid >> 5;
    const int qt = blockIdx.x, bh = blockIdx.y;
    const int gr = lane >> 2, tq = lane & 3;

    const __nv_bfloat16* Kh = g_Kh + (size_t)bh * S_ * D_;
    const __nv_bfloat16* Kl = g_Kl + (size_t)bh * S_ * D_;
    const __half*       V16 = g_V16 + (size_t)bh * S_ * D_;

    {
        const size_t gb = (size_t)qt * 8192;
#pragma unroll
        for (int i = 0; i < 4; i++) {
            const int idx = tid + i * 128;
            const int r = idx >> 3, c = idx & 7;
            const uint32_t so = toff(r, c);
            const size_t go = gb + (size_t)r * 128 + c * 16;
            cpasync16(smb + SM_Q +        so, (const char*)Kh + go);
            cpasync16(smb + SM_Q + 8192 + so, (const char*)Kl + go);
        }
        CP_COMMIT();
        att_load_tile(smb + SM_STG, Kh, Kl, V16, 0, tid);
        CP_COMMIT();
    }

    uint32_t qh[4][4], ql[4][4];
    float o[8][4];
#pragma unroll
    for (int g = 0; g < 8; g++)
#pragma unroll
        for (int r = 0; r < 4; r++) o[g][r] = 0.0f;
    float mrow0 = -1e30f, mrow1 = -1e30f, lrow0 = 0.0f, lrow1 = 0.0f;

    const int ar = lane & 15, hc = lane >> 4;
    const int br = (lane & 7) + ((lane >> 4) << 3);
    const int bcs = (lane >> 3) & 1;
    const int vr = (lane & 7) + (((lane >> 3) & 1) << 3);
    const int vcs = lane >> 4;

    for (int jt = 0; jt <= qt; jt++) {
        const uint32_t Kb = smb + SM_STG + (jt & 1) * STAGE_B;
        if (jt < qt) {
            att_load_tile(smb + SM_STG + ((jt + 1) & 1) * STAGE_B,
                          Kh, Kl, V16, jt + 1, tid);
            CP_COMMIT();
            CP_WAIT(1);
        } else {
            CP_WAIT(0);
        }
        __syncthreads();

        if (jt == 0) {
#pragma unroll
            for (int ks = 0; ks < 4; ks++) {
                ldsm4(qh[ks], smb + SM_Q +        toff(16 * w + ar, 2 * ks + hc));
                ldsm4(ql[ks], smb + SM_Q + 8192 + toff(16 * w + ar, 2 * ks + hc));
            }
        }

        // S = Q K^T (bf16 3-term)
        float s[8][4];
#pragma unroll
        for (int g = 0; g < 8; g++)
#pragma unroll
            for (int r = 0; r < 4; r++) s[g][r] = 0.0f;
#pragma unroll
        for (int ks = 0; ks < 4; ks++) {
#pragma unroll
            for (int p = 0; p < 4; p++) {
                uint32_t kh4[4], kl4[4];
                ldsm4(kh4, Kb +        toff(16 * p + br, 2 * ks + bcs));
                ldsm4(kl4, Kb + 8192 + toff(16 * p + br, 2 * ks + bcs));
                mma16816(s[2 * p],     qh[ks], kh4);
                mma16816(s[2 * p + 1], qh[ks], kh4 + 2);
                mma16816(s[2 * p],     qh[ks], kl4);
                mma16816(s[2 * p + 1], qh[ks], kl4 + 2);
                mma16816(s[2 * p],     ql[ks], kh4);
                mma16816(s[2 * p + 1], ql[ks], kh4 + 2);
            }
        }

        if (jt == qt) {
            const int rb = 16 * w + gr;
#pragma unroll
            for (int g = 0; g < 8; g++) {
                const int c0 = 8 * g + 2 * tq;
                if (c0     > rb)     s[g][0] = -1e30f;
                if (c0 + 1 > rb)     s[g][1] = -1e30f;
                if (c0     > rb + 8) s[g][2] = -1e30f;
                if (c0 + 1 > rb + 8) s[g][3] = -1e30f;
            }
        }

        float mx0 = -1e30f, mx1 = -1e30f;
#pragma unroll
        for (int g = 0; g < 8; g++) {
            mx0 = fmaxf(mx0, fmaxf(s[g][0], s[g][1]));
            mx1 = fmaxf(mx1, fmaxf(s[g][2], s[g][3]));
        }
        mx0 = fmaxf(mx0, __shfl_xor_sync(0xffffffffu, mx0, 1));
        mx0 = fmaxf(mx0, __shfl_xor_sync(0xffffffffu, mx0, 2));
        mx1 = fmaxf(mx1, __shfl_xor_sync(0xffffffffu, mx1, 1));
        mx1 = fmaxf(mx1, __shfl_xor_sync(0xffffffffu, mx1, 2));
        const float mn0 = fmaxf(mrow0, mx0), mn1 = fmaxf(mrow1, mx1);
        const float a0 = exp2f(mrow0 - mn0), a1 = exp2f(mrow1 - mn1);
        mrow0 = mn0; mrow1 = mn1;
        float sum0 = 0.0f, sum1 = 0.0f;
#pragma unroll
        for (int g = 0; g < 8; g++) {
            s[g][0] = exp2f(s[g][0] - mn0); sum0 += s[g][0];
            s[g][1] = exp2f(s[g][1] - mn0); sum0 += s[g][1];
            s[g][2] = exp2f(s[g][2] - mn1); sum1 += s[g][2];
            s[g][3] = exp2f(s[g][3] - mn1); sum1 += s[g][3];
        }
        sum0 += __shfl_xor_sync(0xffffffffu, sum0, 1);
        sum0 += __shfl_xor_sync(0xffffffffu, sum0, 2);
        sum1 += __shfl_xor_sync(0xffffffffu, sum1, 1);
        sum1 += __shfl_xor_sync(0xffffffffu, sum1, 2);
        lrow0 = lrow0 * a0 + sum0;
        lrow1 = lrow1 * a1 + sum1;
#pragma unroll
        for (int g = 0; g < 8; g++) {
            o[g][0] *= a0; o[g][1] *= a0; o[g][2] *= a1; o[g][3] *= a1;
        }

        // O += P V  (single-term fp16: p fp16 x v fp16)
#pragma unroll
        for (int ks = 0; ks < 4; ks++) {
            uint32_t ph[4];
            ph[0] = pack_h2(s[2 * ks][0],     s[2 * ks][1]);
            ph[1] = pack_h2(s[2 * ks][2],     s[2 * ks][3]);
            ph[2] = pack_h2(s[2 * ks + 1][0], s[2 * ks + 1][1]);
            ph[3] = pack_h2(s[2 * ks + 1][2], s[2 * ks + 1][3]);
#pragma unroll
            for (int p2 = 0; p2 < 4; p2++) {
                uint32_t vh4[4];
                ldsm4t(vh4, Kb + 16384 + toff(16 * ks + vr, 2 * p2 + vcs));
                mma16816h(o[2 * p2],     ph, vh4);
                mma16816h(o[2 * p2 + 1], ph, vh4 + 2);
            }
        }
        __syncthreads();
    }

    // Epilogue: normalize, write plain fp16 rows into g_A2p
    const float i0 = 1.0f / lrow0, i1 = 1.0f / lrow1;
    const int b = bh >> 4, h = bh & 15;
    const int r0 = qt * 64 + 16 * w + gr;
    const int r1 = r0 + 8;
    __half* row0 = g_A2p + (size_t)(b * S_ + r0) * KC + h * 64;
    __half* row1 = g_A2p + (size_t)(b * S_ + r1) * KC + h * 64;
#pragma unroll
    for (int g = 0; g < 8; g++) {
        const int d = 8 * g + 2 * tq;
        *(uint32_t*)(row0 + d) = pack_h2(o[g][0] * i0, o[g][1] * i0);
        *(uint32_t*)(row1 + d) = pack_h2(o[g][2] * i1, o[g][3] * i1);
    }
}

// ---------------------------------------------------------------------------
extern "C" void kernel_launch(void* const* d_in, const int* in_sizes, int n_in,
                              void* d_out, int out_size)
{
    const float* x     = (const float*)d_in[0];
    const float* Wqkv  = (const float*)d_in[1];
    const float* bqkv  = (const float*)d_in[2];
    const float* Wproj = (const float*)d_in[3];
    const float* bproj = (const float*)d_in[4];
    float* out = (float*)d_out;

    __half *a2, *b2, *a2p, *b2p;
    cudaGetSymbolAddress((void**)&a2,  g_A2);
    cudaGetSymbolAddress((void**)&b2,  g_B2);
    cudaGetSymbolAddress((void**)&a2p, g_A2p);
    cudaGetSymbolAddress((void**)&b2p, g_B2p);

    // Phase 0: fp16 conversion / transposes
    cvt_x_kernel<<<M_TOT, 256>>>(x);
    tcvt_kernel<<<dim3(KV_N / 32, C_ / 32), 256>>>(Wqkv + C_, b2, 3 * C_);
    tcvt_kernel<<<dim3(C_ / 32, C_ / 32), 256>>>(Wproj, b2p, C_);

    cudaFuncSetAttribute(gemm_fp16_kernel,
                         cudaFuncAttributeMaxDynamicSharedMemorySize,
                         GEMM_SMEM);

    // Phase 1: KV projection (fp16 tensor GEMM, K=1024) -> K(split)/V(fp16)
    {
        dim3 grid(KV_N / 128, M_TOT / 128);   // (16, 64)
        gemm_fp16_kernel<<<grid, 256, GEMM_SMEM>>>(a2, b2, bqkv + C_, nullptr, 0);
    }

    // Phase 2: causal attention on mma.sync (q = k)
    {
        cudaFuncSetAttribute(attn_mma_kernel,
                             cudaFuncAttributeMaxDynamicSharedMemorySize,
                             ATT_SMEM);
        dim3 grid(S_ / 64, B_ * H_);          // (16, 128)
        attn_mma_kernel<<<grid, 128, ATT_SMEM>>>();
    }

    // Phase 3: output projection (fp16 tensor GEMM, K=1024)
    {
        dim3 grid(C_ / 128, M_TOT / 128);     // (8, 64)
        gemm_fp16_kernel<<<grid, 256, GEMM_SMEM>>>(a2p, b2p, bproj, out, 1);
    }
}

// round 10
// speedup vs baseline: 6.3488x; 1.0783x over previous
#include <cuda_runtime.h>
#include <cuda_bf16.h>
#include <cuda_fp16.h>
#include <math.h>
#include <stddef.h>
#include <stdint.h>

// Problem constants
#define B_  8
#define S_  1024
#define C_  1024
#define H_  16
#define D_  64
#define M_TOT (B_ * S_)          // 8192
#define KV_N  (2 * C_)           // 2048
#define KC    C_                 // 1024 (plain fp16 1-term GEMM K)

// sqrt(0.125 * log2(e)) — folded into K so S-MMA yields exp2-domain scores
#define KSCALE 0.42466089f

// Scratch (device globals; no runtime allocation allowed)
__device__ __nv_bfloat16 g_Kh[(size_t)B_ * H_ * S_ * D_];   // K hi (pre-scaled)
__device__ __nv_bfloat16 g_Kl[(size_t)B_ * H_ * S_ * D_];   // K lo
__device__ __half        g_V16[(size_t)B_ * H_ * S_ * D_];  // V fp16 (1-term)
__device__ __half g_A2 [(size_t)M_TOT * KC];                // x fp16
__device__ __half g_B2 [(size_t)KV_N  * KC];                // Wqkv_kv^T fp16
__device__ __half g_A2p[(size_t)M_TOT * KC];                // attn out fp16
__device__ __half g_B2p[(size_t)C_    * KC];                // Wproj^T fp16

// ---------------------------------------------------------------------------
// PTX helpers (base-sm_100-legal)
// ---------------------------------------------------------------------------
__device__ __forceinline__ uint32_t smem_u32(const void* p) {
    uint32_t a;
    asm("{ .reg .u64 t; cvta.to.shared.u64 t, %1; cvt.u32.u64 %0, t; }" : "=r"(a) : "l"(p));
    return a;
}
__device__ __forceinline__ void cpasync16(uint32_t saddr, const void* g) {
    asm volatile("cp.async.cg.shared.global [%0], [%1], 16;" :: "r"(saddr), "l"(g) : "memory");
}
#define CP_COMMIT() asm volatile("cp.async.commit_group;" ::: "memory")
#define CP_WAIT(n)  asm volatile("cp.async.wait_group %0;" :: "n"(n) : "memory")

__device__ __forceinline__ void ldsm4(uint32_t* r, uint32_t addr) {
    asm volatile("ldmatrix.sync.aligned.m8n8.x4.shared.b16 {%0,%1,%2,%3}, [%4];"
                 : "=r"(r[0]), "=r"(r[1]), "=r"(r[2]), "=r"(r[3]) : "r"(addr));
}
__device__ __forceinline__ void ldsm4t(uint32_t* r, uint32_t addr) {
    asm volatile("ldmatrix.sync.aligned.m8n8.x4.trans.shared.b16 {%0,%1,%2,%3}, [%4];"
                 : "=r"(r[0]), "=r"(r[1]), "=r"(r[2]), "=r"(r[3]) : "r"(addr));
}
// bf16 MMA (attention S path)
__device__ __forceinline__ void mma16816(float* c, const uint32_t* a, const uint32_t* b) {
    asm volatile(
        "mma.sync.aligned.m16n8k16.row.col.f32.bf16.bf16.f32 "
        "{%0,%1,%2,%3}, {%4,%5,%6,%7}, {%8,%9}, {%0,%1,%2,%3};"
        : "+f"(c[0]), "+f"(c[1]), "+f"(c[2]), "+f"(c[3])
        : "r"(a[0]), "r"(a[1]), "r"(a[2]), "r"(a[3]), "r"(b[0]), "r"(b[1]));
}
// fp16 MMA (GEMMs + attention PV path)
__device__ __forceinline__ void mma16816h(float* c, const uint32_t* a, const uint32_t* b) {
    asm volatile(
        "mma.sync.aligned.m16n8k16.row.col.f32.f16.f16.f32 "
        "{%0,%1,%2,%3}, {%4,%5,%6,%7}, {%8,%9}, {%0,%1,%2,%3};"
        : "+f"(c[0]), "+f"(c[1]), "+f"(c[2]), "+f"(c[3])
        : "r"(a[0]), "r"(a[1]), "r"(a[2]), "r"(a[3]), "r"(b[0]), "r"(b[1]));
}

// Swizzled smem offset for [rows][128B] tiles: 16B chunk c (0..7), 8-way XOR.
__device__ __forceinline__ uint32_t toff(int r, int c) {
    return (uint32_t)(r * 128 + (((c) ^ (r & 7)) << 4));
}
// split a,b fp32 -> packed bf16x2 hi and lo
__device__ __forceinline__ void split2(float a, float b, uint32_t& hi, uint32_t& lo) {
    __nv_bfloat162 h = __floats2bfloat162_rn(a, b);
    __nv_bfloat162 l = __floats2bfloat162_rn(a - __bfloat162float(h.x),
                                             b - __bfloat162float(h.y));
    hi = *(uint32_t*)&h; lo = *(uint32_t*)&l;
}
__device__ __forceinline__ uint32_t pack_h2(float a, float b) {
    __half2 h = __floats2half2_rn(a, b);
    return *(uint32_t*)&h;
}

// ---------------------------------------------------------------------------
// fp16 1-term GEMM:  C = A2 @ B2^T + bias.  K=1024, BK=64 (16 stages).
// 3-stage cp.async pipeline, 1 sync/stage.
// mode 0: epilogue scatters K (scaled, bf16 hi/lo) and V (fp16).
// mode 1: writes fp32 out[m*1024+n].
// ---------------------------------------------------------------------------
#define NSTAGE (KC / 64)          // 16
#define GSTAGE_B 32768            // A 16K + B 16K per stage (128 rows x 128B)
#define GEMM_SMEM (3 * GSTAGE_B)  // 98304

__device__ __forceinline__ void gemm_load_stage(
    const __half* __restrict__ Ag, const __half* __restrict__ Bg,
    int kb, uint32_t Ab, uint32_t Bb, int tid)
{
#pragma unroll
    for (int i = 0; i < 4; i++) {
        const int idx = tid + i * 256;           // 0..1023
        const int r = idx >> 3, c = idx & 7;     // row 0..127, chunk 0..7
        const size_t g = (size_t)r * KC + kb * 64 + c * 8;
        const uint32_t so = toff(r, c);
        cpasync16(Ab + so, Ag + g);
        cpasync16(Bb + so, Bg + g);
    }
}

__global__ __launch_bounds__(256) void gemm_fp16_kernel(
    const __half* __restrict__ Ag, const __half* __restrict__ Bg,
    const float* __restrict__ bias, float* __restrict__ out, int mode)
{
    extern __shared__ __align__(1024) uint8_t gsm[];
    const uint32_t smb = smem_u32(gsm);

    const int tid  = threadIdx.x;
    const int lane = tid & 31;
    const int wid  = tid >> 5;
    const int wm = (wid >> 2) * 64;
    const int wn = (wid & 3) * 32;
    const int bn = blockIdx.x, bm = blockIdx.y;

    const __half* Arow = Ag + (size_t)(bm * 128) * KC;
    const __half* Brow = Bg + (size_t)(bn * 128) * KC;

    float acc[4][4][4];
#pragma unroll
    for (int f = 0; f < 4; f++)
#pragma unroll
        for (int g = 0; g < 4; g++)
#pragma unroll
            for (int r = 0; r < 4; r++) acc[f][g][r] = 0.0f;

    // prologue: prefetch stages 0 and 1
    gemm_load_stage(Arow, Brow, 0, smb, smb + 16384, tid);
    CP_COMMIT();
    gemm_load_stage(Arow, Brow, 1, smb + GSTAGE_B, smb + GSTAGE_B + 16384, tid);
    CP_COMMIT();

    int buf = 0, pbuf = 2;
    for (int kb = 0; kb < NSTAGE; kb++) {
        CP_WAIT(1);
        __syncthreads();

        const uint32_t Ab = smb + buf * GSTAGE_B;
        const uint32_t Bb = Ab + 16384;
#pragma unroll
        for (int ks = 0; ks < 4; ks++) {
            uint32_t a[4][4], b[4][2];
            const int ar = lane & 15;
            const int ac = ks * 2 + (lane >> 4);     // chunk 0..7
#pragma unroll
            for (int f = 0; f < 4; f++)
                ldsm4(a[f], Ab + toff(wm + f * 16 + ar, ac));

            const int br = (lane & 7) + ((lane >> 4) << 3);
            const int bc = ks * 2 + ((lane >> 3) & 1);
#pragma unroll
            for (int p = 0; p < 2; p++) {
                uint32_t r4[4];
                ldsm4(r4, Bb + toff(wn + p * 16 + br, bc));
                b[2 * p][0] = r4[0]; b[2 * p][1] = r4[1];
                b[2 * p + 1][0] = r4[2]; b[2 * p + 1][1] = r4[3];
            }
#pragma unroll
            for (int f = 0; f < 4; f++)
#pragma unroll
                for (int g = 0; g < 4; g++)
                    mma16816h(acc[f][g], a[f], b[g]);
        }

        if (kb + 2 < NSTAGE) {
            gemm_load_stage(Arow, Brow, kb + 2,
                            smb + pbuf * GSTAGE_B, smb + pbuf * GSTAGE_B + 16384, tid);
        }
        CP_COMMIT();

        buf = (buf == 2) ? 0 : buf + 1;
        pbuf = (pbuf == 2) ? 0 : pbuf + 1;
    }

    const int gr = lane >> 2;
    const int tcol = (lane & 3) * 2;
#pragma unroll
    for (int f = 0; f < 4; f++) {
        const int r0 = bm * 128 + wm + f * 16 + gr;
        const int b_ = r0 >> 10, s_ = r0 & 1023;
        const int r1 = r0 + 8;
        const int b1_ = r1 >> 10, s1_ = r1 & 1023;
#pragma unroll
        for (int g = 0; g < 4; g++) {
            const int cc = wn + g * 8 + tcol;
            const int n = bn * 128 + cc;
            const float bx = bias[n], by = bias[n + 1];
            float2 v0 = make_float2(acc[f][g][0] + bx, acc[f][g][1] + by);
            float2 v1 = make_float2(acc[f][g][2] + bx, acc[f][g][3] + by);
            if (mode == 0) {
                const int np = n & (C_ - 1);
                const int hh = np >> 6, dd = np & 63;
                const size_t o0 = (((size_t)(b_  * H_ + hh)) * S_ + s_ ) * D_ + dd;
                const size_t o1 = (((size_t)(b1_ * H_ + hh)) * S_ + s1_) * D_ + dd;
                if (n < C_) {   // K: scale then split (bf16 hi/lo for S path)
                    v0.x *= KSCALE; v0.y *= KSCALE; v1.x *= KSCALE; v1.y *= KSCALE;
                    uint32_t h0, l0, h1, l1;
                    split2(v0.x, v0.y, h0, l0);
                    split2(v1.x, v1.y, h1, l1);
                    *(uint32_t*)&g_Kh[o0] = h0; *(uint32_t*)&g_Kl[o0] = l0;
                    *(uint32_t*)&g_Kh[o1] = h1; *(uint32_t*)&g_Kl[o1] = l1;
                } else {        // V: plain fp16
                    *(uint32_t*)&g_V16[o0] = pack_h2(v0.x, v0.y);
                    *(uint32_t*)&g_V16[o1] = pack_h2(v1.x, v1.y);
                }
            } else {
                *(float2*)&out[(size_t)r0 * C_ + n] = v0;
                *(float2*)&out[(size_t)r1 * C_ + n] = v1;
            }
        }
    }
}

// ---------------------------------------------------------------------------
// cvt_x: x fp32 [8192][1024] -> g_A2 fp16 [8192][1024]
// ---------------------------------------------------------------------------
__global__ __launch_bounds__(256) void cvt_x_kernel(const float* __restrict__ x)
{
    const int idx = blockIdx.x * 256 + threadIdx.x;
    const int m = idx >> 8;
    const int k = (idx & 255) << 2;
    const float4 v = *(const float4*)&x[(size_t)m * C_ + k];
    __half* row = g_A2 + (size_t)m * KC;
    *(uint32_t*)(row + k)     = pack_h2(v.x, v.y);
    *(uint32_t*)(row + k + 2) = pack_h2(v.z, v.w);
}

// ---------------------------------------------------------------------------
// tcvt: W fp32 [1024][srcld] col block -> dst fp16 [n][1024] transposed
// ---------------------------------------------------------------------------
__global__ __launch_bounds__(256) void tcvt_kernel(
    const float* __restrict__ src, __half* __restrict__ dst, int srcld)
{
    __shared__ float t[32][33];
    const int n0 = blockIdx.x * 32, k0 = blockIdx.y * 32;
    const int tx = threadIdx.x & 31, ty = threadIdx.x >> 5;
#pragma unroll
    for (int i = 0; i < 4; i++)
        t[ty + i * 8][tx] = src[(size_t)(k0 + ty + i * 8) * srcld + n0 + tx];
    __syncthreads();
#pragma unroll
    for (int i = 0; i < 4; i++) {
        const int n = n0 + ty + i * 8;
        const int k = k0 + tx;
        dst[(size_t)n * KC + k] = __float2half_rn(t[tx][ty + i * 8]);
    }
}

// ---------------------------------------------------------------------------
// MMA flash attention. S path: bf16 3-term (precision-critical).
// PV path: single-term fp16.  qt reversed (long CTAs first); 3 CTAs/SM.
// smem: Q (Qh 8K + Ql 8K) + 2 stages x (Kh 8K | Kl 8K | V16 8K).
// ---------------------------------------------------------------------------
#define STAGE_B 24576
#define SM_Q    0
#define SM_STG  16384
#define ATT_SMEM (16384 + 2 * STAGE_B)     // 65536

__device__ __forceinline__ void att_load_tile(
    uint32_t dst, const __nv_bfloat16* Kh, const __nv_bfloat16* Kl,
    const __half* V16, int jt, int tid)
{
    const size_t gb = (size_t)jt * 8192;
#pragma unroll
    for (int i = 0; i < 4; i++) {
        const int idx = tid + i * 128;
        const int r = idx >> 3, c = idx & 7;
        const uint32_t so = toff(r, c);
        const size_t go = gb + (size_t)r * 128 + c * 16;
        cpasync16(dst +         so, (const char*)Kh  + go);
        cpasync16(dst +  8192 + so, (const char*)Kl  + go);
        cpasync16(dst + 16384 + so, (const char*)V16 + go);
    }
}

__global__ __launch_bounds__(128, 3) void attn_mma_kernel()
{
    extern __shared__ uint8_t asmem[];
    const uint32_t smb = smem_u32(asmem);
    const int tid = threadIdx.x, lane = tid & 31, w = tid >> 5;
    const int qt = (S_ / 64 - 1) - blockIdx.x;   // long CTAs launch first
    const int bh = blockIdx.y;
    const int gr = lane >> 2, tq = lane & 3;

    const __nv_bfloat16* Kh = g_Kh + (size_t)bh * S_ * D_;
    const __nv_bfloat16* Kl = g_Kl + (size_t)bh * S_ * D_;
    const __half*       V16 = g_V16 + (size_t)bh * S_ * D_;

    {
        const size_t gb = (size_t)qt * 8192;
#pragma unroll
        for (int i = 0; i < 4; i++) {
            const int idx = tid + i * 128;
            const int r = idx >> 3, c = idx & 7;
            const uint32_t so = toff(r, c);
            const size_t go = gb + (size_t)r * 128 + c * 16;
            cpasync16(smb + SM_Q +        so, (const char*)Kh + go);
            cpasync16(smb + SM_Q + 8192 + so, (const char*)Kl + go);
        }
        CP_COMMIT();
        att_load_tile(smb + SM_STG, Kh, Kl, V16, 0, tid);
        CP_COMMIT();
    }

    uint32_t qh[4][4], ql[4][4];
    float o[8][4];
#pragma unroll
    for (int g = 0; g < 8; g++)
#pragma unroll
        for (int r = 0; r < 4; r++) o[g][r] = 0.0f;
    float mrow0 = -1e30f, mrow1 = -1e30f, lrow0 = 0.0f, lrow1 = 0.0f;

    const int ar = lane & 15, hc = lane >> 4;
    const int br = (lane & 7) + ((lane >> 4) << 3);
    const int bcs = (lane >> 3) & 1;
    const int vr = (lane & 7) + (((lane >> 3) & 1) << 3);
    const int vcs = lane >> 4;

    for (int jt = 0; jt <= qt; jt++) {
        const uint32_t Kb = smb + SM_STG + (jt & 1) * STAGE_B;
        if (jt < qt) {
            att_load_tile(smb + SM_STG + ((jt + 1) & 1) * STAGE_B,
                          Kh, Kl, V16, jt + 1, tid);
            CP_COMMIT();
            CP_WAIT(1);
        } else {
            CP_WAIT(0);
        }
        __syncthreads();

        if (jt == 0) {
#pragma unroll
            for (int ks = 0; ks < 4; ks++) {
                ldsm4(qh[ks], smb + SM_Q +        toff(16 * w + ar, 2 * ks + hc));
                ldsm4(ql[ks], smb + SM_Q + 8192 + toff(16 * w + ar, 2 * ks + hc));
            }
        }

        // S = Q K^T (bf16 3-term)
        float s[8][4];
#pragma unroll
        for (int g = 0; g < 8; g++)
#pragma unroll
            for (int r = 0; r < 4; r++) s[g][r] = 0.0f;
#pragma unroll
        for (int ks = 0; ks < 4; ks++) {
#pragma unroll
            for (int p = 0; p < 4; p++) {
                uint32_t kh4[4], kl4[4];
                ldsm4(kh4, Kb +        toff(16 * p + br, 2 * ks + bcs));
                ldsm4(kl4, Kb + 8192 + toff(16 * p + br, 2 * ks + bcs));
                mma16816(s[2 * p],     qh[ks], kh4);
                mma16816(s[2 * p + 1], qh[ks], kh4 + 2);
                mma16816(s[2 * p],     qh[ks], kl4);
                mma16816(s[2 * p + 1], qh[ks], kl4 + 2);
                mma16816(s[2 * p],     ql[ks], kh4);
                mma16816(s[2 * p + 1], ql[ks], kh4 + 2);
            }
        }

        if (jt == qt) {
            const int rb = 16 * w + gr;
#pragma unroll
            for (int g = 0; g < 8; g++) {
                const int c0 = 8 * g + 2 * tq;
                if (c0     > rb)     s[g][0] = -1e30f;
                if (c0 + 1 > rb)     s[g][1] = -1e30f;
                if (c0     > rb + 8) s[g][2] = -1e30f;
                if (c0 + 1 > rb + 8) s[g][3] = -1e30f;
            }
        }

        float mx0 = -1e30f, mx1 = -1e30f;
#pragma unroll
        for (int g = 0; g < 8; g++) {
            mx0 = fmaxf(mx0, fmaxf(s[g][0], s[g][1]));
            mx1 = fmaxf(mx1, fmaxf(s[g][2], s[g][3]));
        }
        mx0 = fmaxf(mx0, __shfl_xor_sync(0xffffffffu, mx0, 1));
        mx0 = fmaxf(mx0, __shfl_xor_sync(0xffffffffu, mx0, 2));
        mx1 = fmaxf(mx1, __shfl_xor_sync(0xffffffffu, mx1, 1));
        mx1 = fmaxf(mx1, __shfl_xor_sync(0xffffffffu, mx1, 2));
        const float mn0 = fmaxf(mrow0, mx0), mn1 = fmaxf(mrow1, mx1);
        const float a0 = exp2f(mrow0 - mn0), a1 = exp2f(mrow1 - mn1);
        mrow0 = mn0; mrow1 = mn1;
        float sum0 = 0.0f, sum1 = 0.0f;
#pragma unroll
        for (int g = 0; g < 8; g++) {
            s[g][0] = exp2f(s[g][0] - mn0); sum0 += s[g][0];
            s[g][1] = exp2f(s[g][1] - mn0); sum0 += s[g][1];
            s[g][2] = exp2f(s[g][2] - mn1); sum1 += s[g][2];
            s[g][3] = exp2f(s[g][3] - mn1); sum1 += s[g][3];
        }
        sum0 += __shfl_xor_sync(0xffffffffu, sum0, 1);
        sum0 += __shfl_xor_sync(0xffffffffu, sum0, 2);
        sum1 += __shfl_xor_sync(0xffffffffu, sum1, 1);
        sum1 += __shfl_xor_sync(0xffffffffu, sum1, 2);
        lrow0 = lrow0 * a0 + sum0;
        lrow1 = lrow1 * a1 + sum1;
#pragma unroll
        for (int g = 0; g < 8; g++) {
            o[g][0] *= a0; o[g][1] *= a0; o[g][2] *= a1; o[g][3] *= a1;
        }

        // O += P V  (single-term fp16)
#pragma unroll
        for (int ks = 0; ks < 4; ks++) {
            uint32_t ph[4];
            ph[0] = pack_h2(s[2 * ks][0],     s[2 * ks][1]);
            ph[1] = pack_h2(s[2 * ks][2],     s[2 * ks][3]);
            ph[2] = pack_h2(s[2 * ks + 1][0], s[2 * ks + 1][1]);
            ph[3] = pack_h2(s[2 * ks + 1][2], s[2 * ks + 1][3]);
#pragma unroll
            for (int p2 = 0; p2 < 4; p2++) {
                uint32_t vh4[4];
                ldsm4t(vh4, Kb + 16384 + toff(16 * ks + vr, 2 * p2 + vcs));
                mma16816h(o[2 * p2],     ph, vh4);
                mma16816h(o[2 * p2 + 1], ph, vh4 + 2);
            }
        }
        __syncthreads();
    }

    // Epilogue: normalize, write plain fp16 rows into g_A2p
    const float i0 = 1.0f / lrow0, i1 = 1.0f / lrow1;
    const int b = bh >> 4, h = bh & 15;
    const int r0 = qt * 64 + 16 * w + gr;
    const int r1 = r0 + 8;
    __half* row0 = g_A2p + (size_t)(b * S_ + r0) * KC + h * 64;
    __half* row1 = g_A2p + (size_t)(b * S_ + r1) * KC + h * 64;
#pragma unroll
    for (int g = 0; g < 8; g++) {
        const int d = 8 * g + 2 * tq;
        *(uint32_t*)(row0 + d) = pack_h2(o[g][0] * i0, o[g][1] * i0);
        *(uint32_t*)(row1 + d) = pack_h2(o[g][2] * i1, o[g][3] * i1);
    }
}

// ---------------------------------------------------------------------------
extern "C" void kernel_launch(void* const* d_in, const int* in_sizes, int n_in,
                              void* d_out, int out_size)
{
    const float* x     = (const float*)d_in[0];
    const float* Wqkv  = (const float*)d_in[1];
    const float* bqkv  = (const float*)d_in[2];
    const float* Wproj = (const float*)d_in[3];
    const float* bproj = (const float*)d_in[4];
    float* out = (float*)d_out;

    __half *a2, *b2, *a2p, *b2p;
    cudaGetSymbolAddress((void**)&a2,  g_A2);
    cudaGetSymbolAddress((void**)&b2,  g_B2);
    cudaGetSymbolAddress((void**)&a2p, g_A2p);
    cudaGetSymbolAddress((void**)&b2p, g_B2p);

    // Phase 0: fp16 conversion / transposes
    cvt_x_kernel<<<M_TOT, 256>>>(x);
    tcvt_kernel<<<dim3(KV_N / 32, C_ / 32), 256>>>(Wqkv + C_, b2, 3 * C_);
    tcvt_kernel<<<dim3(C_ / 32, C_ / 32), 256>>>(Wproj, b2p, C_);

    cudaFuncSetAttribute(gemm_fp16_kernel,
                         cudaFuncAttributeMaxDynamicSharedMemorySize,
                         GEMM_SMEM);

    // Phase 1: KV projection (fp16 tensor GEMM, K=1024, BK=64)
    {
        dim3 grid(KV_N / 128, M_TOT / 128);   // (16, 64)
        gemm_fp16_kernel<<<grid, 256, GEMM_SMEM>>>(a2, b2, bqkv + C_, nullptr, 0);
    }

    // Phase 2: causal attention on mma.sync (q = k)
    {
        cudaFuncSetAttribute(attn_mma_kernel,
                             cudaFuncAttributeMaxDynamicSharedMemorySize,
                             ATT_SMEM);
        dim3 grid(S_ / 64, B_ * H_);          // (16, 128)
        attn_mma_kernel<<<grid, 128, ATT_SMEM>>>();
    }

    // Phase 3: output projection (fp16 tensor GEMM, K=1024, BK=64)
    {
        dim3 grid(C_ / 128, M_TOT / 128);     // (8, 64)
        gemm_fp16_kernel<<<grid, 256, GEMM_SMEM>>>(a2p, b2p, bproj, out, 1);
    }
}

// round 11
// speedup vs baseline: 6.8346x; 1.0765x over previous
#include <cuda_runtime.h>
#include <cuda_bf16.h>
#include <cuda_fp16.h>
#include <math.h>
#include <stddef.h>
#include <stdint.h>

// Problem constants
#define B_  8
#define S_  1024
#define C_  1024
#define H_  16
#define D_  64
#define M_TOT (B_ * S_)          // 8192
#define KV_N  (2 * C_)           // 2048
#define KC    C_                 // 1024 (plain fp16 1-term GEMM K)

// sqrt(0.125 * log2(e)) — folded into K so S-MMA yields exp2-domain scores
#define KSCALE 0.42466089f

// Scratch (device globals; no runtime allocation allowed)
__device__ __half g_Kh[(size_t)B_ * H_ * S_ * D_];          // K hi fp16 (pre-scaled)
__device__ __half g_Kl[(size_t)B_ * H_ * S_ * D_];          // K lo fp16 (Q-side only)
__device__ __half g_V16[(size_t)B_ * H_ * S_ * D_];         // V fp16
__device__ __half g_A2 [(size_t)M_TOT * KC];                // x fp16
__device__ __half g_B2 [(size_t)KV_N  * KC];                // Wqkv_kv^T fp16
__device__ __half g_A2p[(size_t)M_TOT * KC];                // attn out fp16
__device__ __half g_B2p[(size_t)C_    * KC];                // Wproj^T fp16

// ---------------------------------------------------------------------------
// PTX helpers (base-sm_100-legal)
// ---------------------------------------------------------------------------
__device__ __forceinline__ uint32_t smem_u32(const void* p) {
    uint32_t a;
    asm("{ .reg .u64 t; cvta.to.shared.u64 t, %1; cvt.u32.u64 %0, t; }" : "=r"(a) : "l"(p));
    return a;
}
__device__ __forceinline__ void cpasync16(uint32_t saddr, const void* g) {
    asm volatile("cp.async.cg.shared.global [%0], [%1], 16;" :: "r"(saddr), "l"(g) : "memory");
}
#define CP_COMMIT() asm volatile("cp.async.commit_group;" ::: "memory")
#define CP_WAIT(n)  asm volatile("cp.async.wait_group %0;" :: "n"(n) : "memory")

__device__ __forceinline__ void ldsm4(uint32_t* r, uint32_t addr) {
    asm volatile("ldmatrix.sync.aligned.m8n8.x4.shared.b16 {%0,%1,%2,%3}, [%4];"
                 : "=r"(r[0]), "=r"(r[1]), "=r"(r[2]), "=r"(r[3]) : "r"(addr));
}
__device__ __forceinline__ void ldsm4t(uint32_t* r, uint32_t addr) {
    asm volatile("ldmatrix.sync.aligned.m8n8.x4.trans.shared.b16 {%0,%1,%2,%3}, [%4];"
                 : "=r"(r[0]), "=r"(r[1]), "=r"(r[2]), "=r"(r[3]) : "r"(addr));
}
// fp16 MMA (GEMMs + attention S and PV paths)
__device__ __forceinline__ void mma16816h(float* c, const uint32_t* a, const uint32_t* b) {
    asm volatile(
        "mma.sync.aligned.m16n8k16.row.col.f32.f16.f16.f32 "
        "{%0,%1,%2,%3}, {%4,%5,%6,%7}, {%8,%9}, {%0,%1,%2,%3};"
        : "+f"(c[0]), "+f"(c[1]), "+f"(c[2]), "+f"(c[3])
        : "r"(a[0]), "r"(a[1]), "r"(a[2]), "r"(a[3]), "r"(b[0]), "r"(b[1]));
}

// Swizzled smem offset for [rows][128B] tiles: 16B chunk c (0..7), 8-way XOR.
__device__ __forceinline__ uint32_t toff(int r, int c) {
    return (uint32_t)(r * 128 + (((c) ^ (r & 7)) << 4));
}
// split a,b fp32 -> packed half2 hi and lo
__device__ __forceinline__ void split2h(float a, float b, uint32_t& hi, uint32_t& lo) {
    __half2 h = __floats2half2_rn(a, b);
    __half2 l = __floats2half2_rn(a - __half2float(__low2half(h)),
                                  b - __half2float(__high2half(h)));
    hi = *(uint32_t*)&h; lo = *(uint32_t*)&l;
}
__device__ __forceinline__ uint32_t pack_h2(float a, float b) {
    __half2 h = __floats2half2_rn(a, b);
    return *(uint32_t*)&h;
}

// ---------------------------------------------------------------------------
// fp16 1-term GEMM:  C = A2 @ B2^T + bias.  K=1024, BK=64 (16 stages).
// 3-stage cp.async pipeline, 1 sync/stage.
// mode 0: epilogue scatters K (scaled, fp16 hi/lo) and V (fp16).
// mode 1: writes fp32 out[m*1024+n].
// ---------------------------------------------------------------------------
#define NSTAGE (KC / 64)          // 16
#define GSTAGE_B 32768            // A 16K + B 16K per stage (128 rows x 128B)
#define GEMM_SMEM (3 * GSTAGE_B)  // 98304

__device__ __forceinline__ void gemm_load_stage(
    const __half* __restrict__ Ag, const __half* __restrict__ Bg,
    int kb, uint32_t Ab, uint32_t Bb, int tid)
{
#pragma unroll
    for (int i = 0; i < 4; i++) {
        const int idx = tid + i * 256;           // 0..1023
        const int r = idx >> 3, c = idx & 7;     // row 0..127, chunk 0..7
        const size_t g = (size_t)r * KC + kb * 64 + c * 8;
        const uint32_t so = toff(r, c);
        cpasync16(Ab + so, Ag + g);
        cpasync16(Bb + so, Bg + g);
    }
}

__global__ __launch_bounds__(256) void gemm_fp16_kernel(
    const __half* __restrict__ Ag, const __half* __restrict__ Bg,
    const float* __restrict__ bias, float* __restrict__ out, int mode)
{
    extern __shared__ __align__(1024) uint8_t gsm[];
    const uint32_t smb = smem_u32(gsm);

    const int tid  = threadIdx.x;
    const int lane = tid & 31;
    const int wid  = tid >> 5;
    const int wm = (wid >> 2) * 64;
    const int wn = (wid & 3) * 32;
    const int bn = blockIdx.x, bm = blockIdx.y;

    const __half* Arow = Ag + (size_t)(bm * 128) * KC;
    const __half* Brow = Bg + (size_t)(bn * 128) * KC;

    float acc[4][4][4];
#pragma unroll
    for (int f = 0; f < 4; f++)
#pragma unroll
        for (int g = 0; g < 4; g++)
#pragma unroll
            for (int r = 0; r < 4; r++) acc[f][g][r] = 0.0f;

    // prologue: prefetch stages 0 and 1
    gemm_load_stage(Arow, Brow, 0, smb, smb + 16384, tid);
    CP_COMMIT();
    gemm_load_stage(Arow, Brow, 1, smb + GSTAGE_B, smb + GSTAGE_B + 16384, tid);
    CP_COMMIT();

    int buf = 0, pbuf = 2;
    for (int kb = 0; kb < NSTAGE; kb++) {
        CP_WAIT(1);
        __syncthreads();

        const uint32_t Ab = smb + buf * GSTAGE_B;
        const uint32_t Bb = Ab + 16384;
#pragma unroll
        for (int ks = 0; ks < 4; ks++) {
            uint32_t a[4][4], b[4][2];
            const int ar = lane & 15;
            const int ac = ks * 2 + (lane >> 4);
#pragma unroll
            for (int f = 0; f < 4; f++)
                ldsm4(a[f], Ab + toff(wm + f * 16 + ar, ac));

            const int br = (lane & 7) + ((lane >> 4) << 3);
            const int bc = ks * 2 + ((lane >> 3) & 1);
#pragma unroll
            for (int p = 0; p < 2; p++) {
                uint32_t r4[4];
                ldsm4(r4, Bb + toff(wn + p * 16 + br, bc));
                b[2 * p][0] = r4[0]; b[2 * p][1] = r4[1];
                b[2 * p + 1][0] = r4[2]; b[2 * p + 1][1] = r4[3];
            }
#pragma unroll
            for (int f = 0; f < 4; f++)
#pragma unroll
                for (int g = 0; g < 4; g++)
                    mma16816h(acc[f][g], a[f], b[g]);
        }

        if (kb + 2 < NSTAGE) {
            gemm_load_stage(Arow, Brow, kb + 2,
                            smb + pbuf * GSTAGE_B, smb + pbuf * GSTAGE_B + 16384, tid);
        }
        CP_COMMIT();

        buf = (buf == 2) ? 0 : buf + 1;
        pbuf = (pbuf == 2) ? 0 : pbuf + 1;
    }

    const int gr = lane >> 2;
    const int tcol = (lane & 3) * 2;
#pragma unroll
    for (int f = 0; f < 4; f++) {
        const int r0 = bm * 128 + wm + f * 16 + gr;
        const int b_ = r0 >> 10, s_ = r0 & 1023;
        const int r1 = r0 + 8;
        const int b1_ = r1 >> 10, s1_ = r1 & 1023;
#pragma unroll
        for (int g = 0; g < 4; g++) {
            const int cc = wn + g * 8 + tcol;
            const int n = bn * 128 + cc;
            const float bx = bias[n], by = bias[n + 1];
            float2 v0 = make_float2(acc[f][g][0] + bx, acc[f][g][1] + by);
            float2 v1 = make_float2(acc[f][g][2] + bx, acc[f][g][3] + by);
            if (mode == 0) {
                const int np = n & (C_ - 1);
                const int hh = np >> 6, dd = np & 63;
                const size_t o0 = (((size_t)(b_  * H_ + hh)) * S_ + s_ ) * D_ + dd;
                const size_t o1 = (((size_t)(b1_ * H_ + hh)) * S_ + s1_) * D_ + dd;
                if (n < C_) {   // K: scale then split (fp16 hi/lo)
                    v0.x *= KSCALE; v0.y *= KSCALE; v1.x *= KSCALE; v1.y *= KSCALE;
                    uint32_t h0, l0, h1, l1;
                    split2h(v0.x, v0.y, h0, l0);
                    split2h(v1.x, v1.y, h1, l1);
                    *(uint32_t*)&g_Kh[o0] = h0; *(uint32_t*)&g_Kl[o0] = l0;
                    *(uint32_t*)&g_Kh[o1] = h1; *(uint32_t*)&g_Kl[o1] = l1;
                } else {        // V: plain fp16
                    *(uint32_t*)&g_V16[o0] = pack_h2(v0.x, v0.y);
                    *(uint32_t*)&g_V16[o1] = pack_h2(v1.x, v1.y);
                }
            } else {
                *(float2*)&out[(size_t)r0 * C_ + n] = v0;
                *(float2*)&out[(size_t)r1 * C_ + n] = v1;
            }
        }
    }
}

// ---------------------------------------------------------------------------
// cvt_x: x fp32 [8192][1024] -> g_A2 fp16 [8192][1024]
// ---------------------------------------------------------------------------
__global__ __launch_bounds__(256) void cvt_x_kernel(const float* __restrict__ x)
{
    const int idx = blockIdx.x * 256 + threadIdx.x;
    const int m = idx >> 8;
    const int k = (idx & 255) << 2;
    const float4 v = *(const float4*)&x[(size_t)m * C_ + k];
    __half* row = g_A2 + (size_t)m * KC;
    *(uint32_t*)(row + k)     = pack_h2(v.x, v.y);
    *(uint32_t*)(row + k + 2) = pack_h2(v.z, v.w);
}

// ---------------------------------------------------------------------------
// tcvt: W fp32 [1024][srcld] col block -> dst fp16 [n][1024] transposed
// ---------------------------------------------------------------------------
__global__ __launch_bounds__(256) void tcvt_kernel(
    const float* __restrict__ src, __half* __restrict__ dst, int srcld)
{
    __shared__ float t[32][33];
    const int n0 = blockIdx.x * 32, k0 = blockIdx.y * 32;
    const int tx = threadIdx.x & 31, ty = threadIdx.x >> 5;
#pragma unroll
    for (int i = 0; i < 4; i++)
        t[ty + i * 8][tx] = src[(size_t)(k0 + ty + i * 8) * srcld + n0 + tx];
    __syncthreads();
#pragma unroll
    for (int i = 0; i < 4; i++) {
        const int n = n0 + ty + i * 8;
        const int k = k0 + tx;
        dst[(size_t)n * KC + k] = __float2half_rn(t[tx][ty + i * 8]);
    }
}

// ---------------------------------------------------------------------------
// MMA flash attention. S path: 2-term fp16 (Q hi/lo x K hi).
// PV path: single-term fp16.  qt reversed; 4 CTAs/SM.
// smem: Q (Qh 8K + Ql 8K) + 2 stages x (Kh 8K | V16 8K).
// ---------------------------------------------------------------------------
#define STAGE_B 16384
#define SM_Q    0
#define SM_STG  16384
#define ATT_SMEM (16384 + 2 * STAGE_B)     // 49152

__device__ __forceinline__ void att_load_tile(
    uint32_t dst, const __half* Kh, const __half* V16, int jt, int tid)
{
    const size_t gb = (size_t)jt * 8192;
#pragma unroll
    for (int i = 0; i < 4; i++) {
        const int idx = tid + i * 128;
        const int r = idx >> 3, c = idx & 7;
        const uint32_t so = toff(r, c);
        const size_t go = gb + (size_t)r * 128 + c * 16;
        cpasync16(dst +        so, (const char*)Kh  + go);
        cpasync16(dst + 8192 + so, (const char*)V16 + go);
    }
}

__global__ __launch_bounds__(128, 4) void attn_mma_kernel()
{
    extern __shared__ uint8_t asmem[];
    const uint32_t smb = smem_u32(asmem);
    const int tid = threadIdx.x, lane = tid & 31, w = tid >> 5;
    const int qt = (S_ / 64 - 1) - blockIdx.x;   // long CTAs launch first
    const int bh = blockIdx.y;
    const int gr = lane >> 2, tq = lane & 3;

    const __half* Kh  = g_Kh + (size_t)bh * S_ * D_;
    const __half* Kl  = g_Kl + (size_t)bh * S_ * D_;
    const __half* V16 = g_V16 + (size_t)bh * S_ * D_;

    {
        const size_t gb = (size_t)qt * 8192;
#pragma unroll
        for (int i = 0; i < 4; i++) {
            const int idx = tid + i * 128;
            const int r = idx >> 3, c = idx & 7;
            const uint32_t so = toff(r, c);
            const size_t go = gb + (size_t)r * 128 + c * 16;
            cpasync16(smb + SM_Q +        so, (const char*)Kh + go);
            cpasync16(smb + SM_Q + 8192 + so, (const char*)Kl + go);
        }
        CP_COMMIT();
        att_load_tile(smb + SM_STG, Kh, V16, 0, tid);
        CP_COMMIT();
    }

    uint32_t qh[4][4], ql[4][4];
    float o[8][4];
#pragma unroll
    for (int g = 0; g < 8; g++)
#pragma unroll
        for (int r = 0; r < 4; r++) o[g][r] = 0.0f;
    float mrow0 = -1e30f, mrow1 = -1e30f, lrow0 = 0.0f, lrow1 = 0.0f;

    const int ar = lane & 15, hc = lane >> 4;
    const int br = (lane & 7) + ((lane >> 4) << 3);
    const int bcs = (lane >> 3) & 1;
    const int vr = (lane & 7) + (((lane >> 3) & 1) << 3);
    const int vcs = lane >> 4;

    for (int jt = 0; jt <= qt; jt++) {
        const uint32_t Kb = smb + SM_STG + (jt & 1) * STAGE_B;
        if (jt < qt) {
            att_load_tile(smb + SM_STG + ((jt + 1) & 1) * STAGE_B,
                          Kh, V16, jt + 1, tid);
            CP_COMMIT();
            CP_WAIT(1);
        } else {
            CP_WAIT(0);
        }
        __syncthreads();

        if (jt == 0) {
#pragma unroll
            for (int ks = 0; ks < 4; ks++) {
                ldsm4(qh[ks], smb + SM_Q +        toff(16 * w + ar, 2 * ks + hc));
                ldsm4(ql[ks], smb + SM_Q + 8192 + toff(16 * w + ar, 2 * ks + hc));
            }
        }

        // S = Q K^T (fp16 2-term: qh*kh + ql*kh)
        float s[8][4];
#pragma unroll
        for (int g = 0; g < 8; g++)
#pragma unroll
            for (int r = 0; r < 4; r++) s[g][r] = 0.0f;
#pragma unroll
        for (int ks = 0; ks < 4; ks++) {
#pragma unroll
            for (int p = 0; p < 4; p++) {
                uint32_t kh4[4];
                ldsm4(kh4, Kb + toff(16 * p + br, 2 * ks + bcs));
                mma16816h(s[2 * p],     qh[ks], kh4);
                mma16816h(s[2 * p + 1], qh[ks], kh4 + 2);
                mma16816h(s[2 * p],     ql[ks], kh4);
                mma16816h(s[2 * p + 1], ql[ks], kh4 + 2);
            }
        }

        if (jt == qt) {
            const int rb = 16 * w + gr;
#pragma unroll
            for (int g = 0; g < 8; g++) {
                const int c0 = 8 * g + 2 * tq;
                if (c0     > rb)     s[g][0] = -1e30f;
                if (c0 + 1 > rb)     s[g][1] = -1e30f;
                if (c0     > rb + 8) s[g][2] = -1e30f;
                if (c0 + 1 > rb + 8) s[g][3] = -1e30f;
            }
        }

        float mx0 = -1e30f, mx1 = -1e30f;
#pragma unroll
        for (int g = 0; g < 8; g++) {
            mx0 = fmaxf(mx0, fmaxf(s[g][0], s[g][1]));
            mx1 = fmaxf(mx1, fmaxf(s[g][2], s[g][3]));
        }
        mx0 = fmaxf(mx0, __shfl_xor_sync(0xffffffffu, mx0, 1));
        mx0 = fmaxf(mx0, __shfl_xor_sync(0xffffffffu, mx0, 2));
        mx1 = fmaxf(mx1, __shfl_xor_sync(0xffffffffu, mx1, 1));
        mx1 = fmaxf(mx1, __shfl_xor_sync(0xffffffffu, mx1, 2));
        const float mn0 = fmaxf(mrow0, mx0), mn1 = fmaxf(mrow1, mx1);
        const float a0 = exp2f(mrow0 - mn0), a1 = exp2f(mrow1 - mn1);
        mrow0 = mn0; mrow1 = mn1;
        float sum0 = 0.0f, sum1 = 0.0f;
#pragma unroll
        for (int g = 0; g < 8; g++) {
            s[g][0] = exp2f(s[g][0] - mn0); sum0 += s[g][0];
            s[g][1] = exp2f(s[g][1] - mn0); sum0 += s[g][1];
            s[g][2] = exp2f(s[g][2] - mn1); sum1 += s[g][2];
            s[g][3] = exp2f(s[g][3] - mn1); sum1 += s[g][3];
        }
        sum0 += __shfl_xor_sync(0xffffffffu, sum0, 1);
        sum0 += __shfl_xor_sync(0xffffffffu, sum0, 2);
        sum1 += __shfl_xor_sync(0xffffffffu, sum1, 1);
        sum1 += __shfl_xor_sync(0xffffffffu, sum1, 2);
        lrow0 = lrow0 * a0 + sum0;
        lrow1 = lrow1 * a1 + sum1;
#pragma unroll
        for (int g = 0; g < 8; g++) {
            o[g][0] *= a0; o[g][1] *= a0; o[g][2] *= a1; o[g][3] *= a1;
        }

        // O += P V  (single-term fp16)
#pragma unroll
        for (int ks = 0; ks < 4; ks++) {
            uint32_t ph[4];
            ph[0] = pack_h2(s[2 * ks][0],     s[2 * ks][1]);
            ph[1] = pack_h2(s[2 * ks][2],     s[2 * ks][3]);
            ph[2] = pack_h2(s[2 * ks + 1][0], s[2 * ks + 1][1]);
            ph[3] = pack_h2(s[2 * ks + 1][2], s[2 * ks + 1][3]);
#pragma unroll
            for (int p2 = 0; p2 < 4; p2++) {
                uint32_t vh4[4];
                ldsm4t(vh4, Kb + 8192 + toff(16 * ks + vr, 2 * p2 + vcs));
                mma16816h(o[2 * p2],     ph, vh4);
                mma16816h(o[2 * p2 + 1], ph, vh4 + 2);
            }
        }
        __syncthreads();
    }

    // Epilogue: normalize, write plain fp16 rows into g_A2p
    const float i0 = 1.0f / lrow0, i1 = 1.0f / lrow1;
    const int b = bh >> 4, h = bh & 15;
    const int r0 = qt * 64 + 16 * w + gr;
    const int r1 = r0 + 8;
    __half* row0 = g_A2p + (size_t)(b * S_ + r0) * KC + h * 64;
    __half* row1 = g_A2p + (size_t)(b * S_ + r1) * KC + h * 64;
#pragma unroll
    for (int g = 0; g < 8; g++) {
        const int d = 8 * g + 2 * tq;
        *(uint32_t*)(row0 + d) = pack_h2(o[g][0] * i0, o[g][1] * i0);
        *(uint32_t*)(row1 + d) = pack_h2(o[g][2] * i1, o[g][3] * i1);
    }
}

// ---------------------------------------------------------------------------
extern "C" void kernel_launch(void* const* d_in, const int* in_sizes, int n_in,
                              void* d_out, int out_size)
{
    const float* x     = (const float*)d_in[0];
    const float* Wqkv  = (const float*)d_in[1];
    const float* bqkv  = (const float*)d_in[2];
    const float* Wproj = (const float*)d_in[3];
    const float* bproj = (const float*)d_in[4];
    float* out = (float*)d_out;

    __half *a2, *b2, *a2p, *b2p;
    cudaGetSymbolAddress((void**)&a2,  g_A2);
    cudaGetSymbolAddress((void**)&b2,  g_B2);
    cudaGetSymbolAddress((void**)&a2p, g_A2p);
    cudaGetSymbolAddress((void**)&b2p, g_B2p);

    // Phase 0: fp16 conversion / transposes
    cvt_x_kernel<<<M_TOT, 256>>>(x);
    tcvt_kernel<<<dim3(KV_N / 32, C_ / 32), 256>>>(Wqkv + C_, b2, 3 * C_);
    tcvt_kernel<<<dim3(C_ / 32, C_ / 32), 256>>>(Wproj, b2p, C_);

    cudaFuncSetAttribute(gemm_fp16_kernel,
                         cudaFuncAttributeMaxDynamicSharedMemorySize,
                         GEMM_SMEM);

    // Phase 1: KV projection (fp16 tensor GEMM, K=1024, BK=64)
    {
        dim3 grid(KV_N / 128, M_TOT / 128);   // (16, 64)
        gemm_fp16_kernel<<<grid, 256, GEMM_SMEM>>>(a2, b2, bqkv + C_, nullptr, 0);
    }

    // Phase 2: causal attention on mma.sync (q = k)
    {
        cudaFuncSetAttribute(attn_mma_kernel,
                             cudaFuncAttributeMaxDynamicSharedMemorySize,
                             ATT_SMEM);
        dim3 grid(S_ / 64, B_ * H_);          // (16, 128)
        attn_mma_kernel<<<grid, 128, ATT_SMEM>>>();
    }

    // Phase 3: output projection (fp16 tensor GEMM, K=1024, BK=64)
    {
        dim3 grid(C_ / 128, M_TOT / 128);     // (8, 64)
        gemm_fp16_kernel<<<grid, 256, GEMM_SMEM>>>(a2p, b2p, bproj, out, 1);
    }
}

// round 12
// speedup vs baseline: 7.2251x; 1.0571x over previous
#include <cuda_runtime.h>
#include <cuda_bf16.h>
#include <cuda_fp16.h>
#include <math.h>
#include <stddef.h>
#include <stdint.h>

// Problem constants
#define B_  8
#define S_  1024
#define C_  1024
#define H_  16
#define D_  64
#define M_TOT (B_ * S_)          // 8192
#define KV_N  (2 * C_)           // 2048
#define KC    C_                 // 1024 (plain fp16 1-term GEMM K)

// sqrt(0.125 * log2(e)) — folded into K so S-MMA yields exp2-domain scores
#define KSCALE 0.42466089f

// Scratch (device globals; no runtime allocation allowed)
__device__ __half g_Kh[(size_t)B_ * H_ * S_ * D_];          // K fp16 (pre-scaled)
__device__ __half g_V16[(size_t)B_ * H_ * S_ * D_];         // V fp16
__device__ __half g_A2 [(size_t)M_TOT * KC];                // x fp16
__device__ __half g_B2 [(size_t)KV_N  * KC];                // Wqkv_kv^T fp16
__device__ __half g_A2p[(size_t)M_TOT * KC];                // attn out fp16
__device__ __half g_B2p[(size_t)C_    * KC];                // Wproj^T fp16

// ---------------------------------------------------------------------------
// PTX helpers (base-sm_100-legal)
// ---------------------------------------------------------------------------
__device__ __forceinline__ uint32_t smem_u32(const void* p) {
    uint32_t a;
    asm("{ .reg .u64 t; cvta.to.shared.u64 t, %1; cvt.u32.u64 %0, t; }" : "=r"(a) : "l"(p));
    return a;
}
__device__ __forceinline__ void cpasync16(uint32_t saddr, const void* g) {
    asm volatile("cp.async.cg.shared.global [%0], [%1], 16;" :: "r"(saddr), "l"(g) : "memory");
}
#define CP_COMMIT() asm volatile("cp.async.commit_group;" ::: "memory")
#define CP_WAIT(n)  asm volatile("cp.async.wait_group %0;" :: "n"(n) : "memory")

__device__ __forceinline__ void ldsm4(uint32_t* r, uint32_t addr) {
    asm volatile("ldmatrix.sync.aligned.m8n8.x4.shared.b16 {%0,%1,%2,%3}, [%4];"
                 : "=r"(r[0]), "=r"(r[1]), "=r"(r[2]), "=r"(r[3]) : "r"(addr));
}
__device__ __forceinline__ void ldsm4t(uint32_t* r, uint32_t addr) {
    asm volatile("ldmatrix.sync.aligned.m8n8.x4.trans.shared.b16 {%0,%1,%2,%3}, [%4];"
                 : "=r"(r[0]), "=r"(r[1]), "=r"(r[2]), "=r"(r[3]) : "r"(addr));
}
// fp16 MMA (all paths)
__device__ __forceinline__ void mma16816h(float* c, const uint32_t* a, const uint32_t* b) {
    asm volatile(
        "mma.sync.aligned.m16n8k16.row.col.f32.f16.f16.f32 "
        "{%0,%1,%2,%3}, {%4,%5,%6,%7}, {%8,%9}, {%0,%1,%2,%3};"
        : "+f"(c[0]), "+f"(c[1]), "+f"(c[2]), "+f"(c[3])
        : "r"(a[0]), "r"(a[1]), "r"(a[2]), "r"(a[3]), "r"(b[0]), "r"(b[1]));
}

// Swizzled smem offset for [rows][128B] tiles: 16B chunk c (0..7), 8-way XOR.
__device__ __forceinline__ uint32_t toff(int r, int c) {
    return (uint32_t)(r * 128 + (((c) ^ (r & 7)) << 4));
}
__device__ __forceinline__ uint32_t pack_h2(float a, float b) {
    __half2 h = __floats2half2_rn(a, b);
    return *(uint32_t*)&h;
}

// ---------------------------------------------------------------------------
// fp16 GEMM:  C = A2 @ B2^T + bias.  K=1024, BK=64 (16 stages).
// 128 threads, 4 warps of 64x64 (high fragment reuse). 3-stage cp.async.
// mode 0: epilogue scatters K (scaled fp16) and V (fp16).
// mode 1: writes fp32 out[m*1024+n].
// ---------------------------------------------------------------------------
#define NSTAGE (KC / 64)          // 16
#define GSTAGE_B 32768            // A 16K + B 16K per stage (128 rows x 128B)
#define GEMM_SMEM (3 * GSTAGE_B)  // 98304

__device__ __forceinline__ void gemm_load_stage(
    const __half* __restrict__ Ag, const __half* __restrict__ Bg,
    int kb, uint32_t Ab, uint32_t Bb, int tid)
{
#pragma unroll
    for (int i = 0; i < 8; i++) {
        const int idx = tid + i * 128;           // 0..1023
        const int r = idx >> 3, c = idx & 7;     // row 0..127, chunk 0..7
        const size_t g = (size_t)r * KC + kb * 64 + c * 8;
        const uint32_t so = toff(r, c);
        cpasync16(Ab + so, Ag + g);
        cpasync16(Bb + so, Bg + g);
    }
}

__global__ __launch_bounds__(128) void gemm_fp16_kernel(
    const __half* __restrict__ Ag, const __half* __restrict__ Bg,
    const float* __restrict__ bias, float* __restrict__ out, int mode)
{
    extern __shared__ __align__(1024) uint8_t gsm[];
    const uint32_t smb = smem_u32(gsm);

    const int tid  = threadIdx.x;
    const int lane = tid & 31;
    const int wid  = tid >> 5;          // 0..3
    const int wm = (wid >> 1) * 64;     // 2x2 warp grid, 64x64 tiles
    const int wn = (wid & 1) * 64;
    const int bn = blockIdx.x, bm = blockIdx.y;

    const __half* Arow = Ag + (size_t)(bm * 128) * KC;
    const __half* Brow = Bg + (size_t)(bn * 128) * KC;

    float acc[4][8][4];
#pragma unroll
    for (int f = 0; f < 4; f++)
#pragma unroll
        for (int g = 0; g < 8; g++)
#pragma unroll
            for (int r = 0; r < 4; r++) acc[f][g][r] = 0.0f;

    // prologue: prefetch stages 0 and 1
    gemm_load_stage(Arow, Brow, 0, smb, smb + 16384, tid);
    CP_COMMIT();
    gemm_load_stage(Arow, Brow, 1, smb + GSTAGE_B, smb + GSTAGE_B + 16384, tid);
    CP_COMMIT();

    int buf = 0, pbuf = 2;
    for (int kb = 0; kb < NSTAGE; kb++) {
        CP_WAIT(1);
        __syncthreads();

        const uint32_t Ab = smb + buf * GSTAGE_B;
        const uint32_t Bb = Ab + 16384;
#pragma unroll
        for (int ks = 0; ks < 4; ks++) {
            uint32_t a[4][4], b[8][2];
            const int ar = lane & 15;
            const int ac = ks * 2 + (lane >> 4);
#pragma unroll
            for (int f = 0; f < 4; f++)
                ldsm4(a[f], Ab + toff(wm + f * 16 + ar, ac));

            const int br = (lane & 7) + ((lane >> 4) << 3);
            const int bc = ks * 2 + ((lane >> 3) & 1);
#pragma unroll
            for (int p = 0; p < 4; p++) {
                uint32_t r4[4];
                ldsm4(r4, Bb + toff(wn + p * 16 + br, bc));
                b[2 * p][0] = r4[0]; b[2 * p][1] = r4[1];
                b[2 * p + 1][0] = r4[2]; b[2 * p + 1][1] = r4[3];
            }
#pragma unroll
            for (int f = 0; f < 4; f++)
#pragma unroll
                for (int g = 0; g < 8; g++)
                    mma16816h(acc[f][g], a[f], b[g]);
        }

        if (kb + 2 < NSTAGE) {
            gemm_load_stage(Arow, Brow, kb + 2,
                            smb + pbuf * GSTAGE_B, smb + pbuf * GSTAGE_B + 16384, tid);
        }
        CP_COMMIT();

        buf = (buf == 2) ? 0 : buf + 1;
        pbuf = (pbuf == 2) ? 0 : pbuf + 1;
    }

    const int gr = lane >> 2;
    const int tcol = (lane & 3) * 2;
#pragma unroll
    for (int f = 0; f < 4; f++) {
        const int r0 = bm * 128 + wm + f * 16 + gr;
        const int b_ = r0 >> 10, s_ = r0 & 1023;
        const int r1 = r0 + 8;
        const int b1_ = r1 >> 10, s1_ = r1 & 1023;
#pragma unroll
        for (int g = 0; g < 8; g++) {
            const int cc = wn + g * 8 + tcol;
            const int n = bn * 128 + cc;
            const float bx = bias[n], by = bias[n + 1];
            float2 v0 = make_float2(acc[f][g][0] + bx, acc[f][g][1] + by);
            float2 v1 = make_float2(acc[f][g][2] + bx, acc[f][g][3] + by);
            if (mode == 0) {
                const int np = n & (C_ - 1);
                const int hh = np >> 6, dd = np & 63;
                const size_t o0 = (((size_t)(b_  * H_ + hh)) * S_ + s_ ) * D_ + dd;
                const size_t o1 = (((size_t)(b1_ * H_ + hh)) * S_ + s1_) * D_ + dd;
                if (n < C_) {   // K: scale, plain fp16
                    *(uint32_t*)&g_Kh[o0] = pack_h2(v0.x * KSCALE, v0.y * KSCALE);
                    *(uint32_t*)&g_Kh[o1] = pack_h2(v1.x * KSCALE, v1.y * KSCALE);
                } else {        // V: plain fp16
                    *(uint32_t*)&g_V16[o0] = pack_h2(v0.x, v0.y);
                    *(uint32_t*)&g_V16[o1] = pack_h2(v1.x, v1.y);
                }
            } else {
                *(float2*)&out[(size_t)r0 * C_ + n] = v0;
                *(float2*)&out[(size_t)r1 * C_ + n] = v1;
            }
        }
    }
}

// ---------------------------------------------------------------------------
// cvt_x: x fp32 [8192][1024] -> g_A2 fp16 [8192][1024]
// ---------------------------------------------------------------------------
__global__ __launch_bounds__(256) void cvt_x_kernel(const float* __restrict__ x)
{
    const int idx = blockIdx.x * 256 + threadIdx.x;
    const int m = idx >> 8;
    const int k = (idx & 255) << 2;
    const float4 v = *(const float4*)&x[(size_t)m * C_ + k];
    __half* row = g_A2 + (size_t)m * KC;
    *(uint32_t*)(row + k)     = pack_h2(v.x, v.y);
    *(uint32_t*)(row + k + 2) = pack_h2(v.z, v.w);
}

// ---------------------------------------------------------------------------
// tcvt: W fp32 [1024][srcld] col block -> dst fp16 [n][1024] transposed
// ---------------------------------------------------------------------------
__global__ __launch_bounds__(256) void tcvt_kernel(
    const float* __restrict__ src, __half* __restrict__ dst, int srcld)
{
    __shared__ float t[32][33];
    const int n0 = blockIdx.x * 32, k0 = blockIdx.y * 32;
    const int tx = threadIdx.x & 31, ty = threadIdx.x >> 5;
#pragma unroll
    for (int i = 0; i < 4; i++)
        t[ty + i * 8][tx] = src[(size_t)(k0 + ty + i * 8) * srcld + n0 + tx];
    __syncthreads();
#pragma unroll
    for (int i = 0; i < 4; i++) {
        const int n = n0 + ty + i * 8;
        const int k = k0 + tx;
        dst[(size_t)n * KC + k] = __float2half_rn(t[tx][ty + i * 8]);
    }
}

// ---------------------------------------------------------------------------
// MMA flash attention. S path: 1-term fp16 (q x k, both pre-scaled fp16).
// PV path: single-term fp16.  qt reversed; 4 CTAs/SM.
// smem: Q 8K + 2 stages x (Kh 8K | V16 8K).
// ---------------------------------------------------------------------------
#define STAGE_B 16384
#define SM_Q    0
#define SM_STG  8192
#define ATT_SMEM (8192 + 2 * STAGE_B)      // 40960

__device__ __forceinline__ void att_load_tile(
    uint32_t dst, const __half* Kh, const __half* V16, int jt, int tid)
{
    const size_t gb = (size_t)jt * 8192;
#pragma unroll
    for (int i = 0; i < 4; i++) {
        const int idx = tid + i * 128;
        const int r = idx >> 3, c = idx & 7;
        const uint32_t so = toff(r, c);
        const size_t go = gb + (size_t)r * 128 + c * 16;
        cpasync16(dst +        so, (const char*)Kh  + go);
        cpasync16(dst + 8192 + so, (const char*)V16 + go);
    }
}

__global__ __launch_bounds__(128, 4) void attn_mma_kernel()
{
    extern __shared__ uint8_t asmem[];
    const uint32_t smb = smem_u32(asmem);
    const int tid = threadIdx.x, lane = tid & 31, w = tid >> 5;
    const int qt = (S_ / 64 - 1) - blockIdx.x;   // long CTAs launch first
    const int bh = blockIdx.y;
    const int gr = lane >> 2, tq = lane & 3;

    const __half* Kh  = g_Kh + (size_t)bh * S_ * D_;
    const __half* V16 = g_V16 + (size_t)bh * S_ * D_;

    {
        const size_t gb = (size_t)qt * 8192;
#pragma unroll
        for (int i = 0; i < 4; i++) {
            const int idx = tid + i * 128;
            const int r = idx >> 3, c = idx & 7;
            cpasync16(smb + SM_Q + toff(r, c),
                      (const char*)Kh + gb + (size_t)r * 128 + c * 16);
        }
        CP_COMMIT();
        att_load_tile(smb + SM_STG, Kh, V16, 0, tid);
        CP_COMMIT();
    }

    uint32_t qh[4][4];
    float o[8][4];
#pragma unroll
    for (int g = 0; g < 8; g++)
#pragma unroll
        for (int r = 0; r < 4; r++) o[g][r] = 0.0f;
    float mrow0 = -1e30f, mrow1 = -1e30f, lrow0 = 0.0f, lrow1 = 0.0f;

    const int ar = lane & 15, hc = lane >> 4;
    const int br = (lane & 7) + ((lane >> 4) << 3);
    const int bcs = (lane >> 3) & 1;
    const int vr = (lane & 7) + (((lane >> 3) & 1) << 3);
    const int vcs = lane >> 4;

    for (int jt = 0; jt <= qt; jt++) {
        const uint32_t Kb = smb + SM_STG + (jt & 1) * STAGE_B;
        if (jt < qt) {
            att_load_tile(smb + SM_STG + ((jt + 1) & 1) * STAGE_B,
                          Kh, V16, jt + 1, tid);
            CP_COMMIT();
            CP_WAIT(1);
        } else {
            CP_WAIT(0);
        }
        __syncthreads();

        if (jt == 0) {
#pragma unroll
            for (int ks = 0; ks < 4; ks++)
                ldsm4(qh[ks], smb + SM_Q + toff(16 * w + ar, 2 * ks + hc));
        }

        // S = Q K^T (fp16 1-term)
        float s[8][4];
#pragma unroll
        for (int g = 0; g < 8; g++)
#pragma unroll
            for (int r = 0; r < 4; r++) s[g][r] = 0.0f;
#pragma unroll
        for (int ks = 0; ks < 4; ks++) {
#pragma unroll
            for (int p = 0; p < 4; p++) {
                uint32_t kh4[4];
                ldsm4(kh4, Kb + toff(16 * p + br, 2 * ks + bcs));
                mma16816h(s[2 * p],     qh[ks], kh4);
                mma16816h(s[2 * p + 1], qh[ks], kh4 + 2);
            }
        }

        if (jt == qt) {
            const int rb = 16 * w + gr;
#pragma unroll
            for (int g = 0; g < 8; g++) {
                const int c0 = 8 * g + 2 * tq;
                if (c0     > rb)     s[g][0] = -1e30f;
                if (c0 + 1 > rb)     s[g][1] = -1e30f;
                if (c0     > rb + 8) s[g][2] = -1e30f;
                if (c0 + 1 > rb + 8) s[g][3] = -1e30f;
            }
        }

        float mx0 = -1e30f, mx1 = -1e30f;
#pragma unroll
        for (int g = 0; g < 8; g++) {
            mx0 = fmaxf(mx0, fmaxf(s[g][0], s[g][1]));
            mx1 = fmaxf(mx1, fmaxf(s[g][2], s[g][3]));
        }
        mx0 = fmaxf(mx0, __shfl_xor_sync(0xffffffffu, mx0, 1));
        mx0 = fmaxf(mx0, __shfl_xor_sync(0xffffffffu, mx0, 2));
        mx1 = fmaxf(mx1, __shfl_xor_sync(0xffffffffu, mx1, 1));
        mx1 = fmaxf(mx1, __shfl_xor_sync(0xffffffffu, mx1, 2));
        const float mn0 = fmaxf(mrow0, mx0), mn1 = fmaxf(mrow1, mx1);
        const float a0 = exp2f(mrow0 - mn0), a1 = exp2f(mrow1 - mn1);
        mrow0 = mn0; mrow1 = mn1;
        float sum0 = 0.0f, sum1 = 0.0f;
#pragma unroll
        for (int g = 0; g < 8; g++) {
            s[g][0] = exp2f(s[g][0] - mn0); sum0 += s[g][0];
            s[g][1] = exp2f(s[g][1] - mn0); sum0 += s[g][1];
            s[g][2] = exp2f(s[g][2] - mn1); sum1 += s[g][2];
            s[g][3] = exp2f(s[g][3] - mn1); sum1 += s[g][3];
        }
        sum0 += __shfl_xor_sync(0xffffffffu, sum0, 1);
        sum0 += __shfl_xor_sync(0xffffffffu, sum0, 2);
        sum1 += __shfl_xor_sync(0xffffffffu, sum1, 1);
        sum1 += __shfl_xor_sync(0xffffffffu, sum1, 2);
        lrow0 = lrow0 * a0 + sum0;
        lrow1 = lrow1 * a1 + sum1;
#pragma unroll
        for (int g = 0; g < 8; g++) {
            o[g][0] *= a0; o[g][1] *= a0; o[g][2] *= a1; o[g][3] *= a1;
        }

        // O += P V  (single-term fp16)
#pragma unroll
        for (int ks = 0; ks < 4; ks++) {
            uint32_t ph[4];
            ph[0] = pack_h2(s[2 * ks][0],     s[2 * ks][1]);
            ph[1] = pack_h2(s[2 * ks][2],     s[2 * ks][3]);
            ph[2] = pack_h2(s[2 * ks + 1][0], s[2 * ks + 1][1]);
            ph[3] = pack_h2(s[2 * ks + 1][2], s[2 * ks + 1][3]);
#pragma unroll
            for (int p2 = 0; p2 < 4; p2++) {
                uint32_t vh4[4];
                ldsm4t(vh4, Kb + 8192 + toff(16 * ks + vr, 2 * p2 + vcs));
                mma16816h(o[2 * p2],     ph, vh4);
                mma16816h(o[2 * p2 + 1], ph, vh4 + 2);
            }
        }
        __syncthreads();
    }

    // Epilogue: normalize, write plain fp16 rows into g_A2p
    const float i0 = 1.0f / lrow0, i1 = 1.0f / lrow1;
    const int b = bh >> 4, h = bh & 15;
    const int r0 = qt * 64 + 16 * w + gr;
    const int r1 = r0 + 8;
    __half* row0 = g_A2p + (size_t)(b * S_ + r0) * KC + h * 64;
    __half* row1 = g_A2p + (size_t)(b * S_ + r1) * KC + h * 64;
#pragma unroll
    for (int g = 0; g < 8; g++) {
        const int d = 8 * g + 2 * tq;
        *(uint32_t*)(row0 + d) = pack_h2(o[g][0] * i0, o[g][1] * i0);
        *(uint32_t*)(row1 + d) = pack_h2(o[g][2] * i1, o[g][3] * i1);
    }
}

// ---------------------------------------------------------------------------
extern "C" void kernel_launch(void* const* d_in, const int* in_sizes, int n_in,
                              void* d_out, int out_size)
{
    const float* x     = (const float*)d_in[0];
    const float* Wqkv  = (const float*)d_in[1];
    const float* bqkv  = (const float*)d_in[2];
    const float* Wproj = (const float*)d_in[3];
    const float* bproj = (const float*)d_in[4];
    float* out = (float*)d_out;

    __half *a2, *b2, *a2p, *b2p;
    cudaGetSymbolAddress((void**)&a2,  g_A2);
    cudaGetSymbolAddress((void**)&b2,  g_B2);
    cudaGetSymbolAddress((void**)&a2p, g_A2p);
    cudaGetSymbolAddress((void**)&b2p, g_B2p);

    // Phase 0: fp16 conversion / transposes
    cvt_x_kernel<<<M_TOT, 256>>>(x);
    tcvt_kernel<<<dim3(KV_N / 32, C_ / 32), 256>>>(Wqkv + C_, b2, 3 * C_);
    tcvt_kernel<<<dim3(C_ / 32, C_ / 32), 256>>>(Wproj, b2p, C_);

    cudaFuncSetAttribute(gemm_fp16_kernel,
                         cudaFuncAttributeMaxDynamicSharedMemorySize,
                         GEMM_SMEM);

    // Phase 1: KV projection (fp16 tensor GEMM, K=1024, BK=64, 64x64 warps)
    {
        dim3 grid(KV_N / 128, M_TOT / 128);   // (16, 64)
        gemm_fp16_kernel<<<grid, 128, GEMM_SMEM>>>(a2, b2, bqkv + C_, nullptr, 0);
    }

    // Phase 2: causal attention on mma.sync (q = k)
    {
        cudaFuncSetAttribute(attn_mma_kernel,
                             cudaFuncAttributeMaxDynamicSharedMemorySize,
                             ATT_SMEM);
        dim3 grid(S_ / 64, B_ * H_);          // (16, 128)
        attn_mma_kernel<<<grid, 128, ATT_SMEM>>>();
    }

    // Phase 3: output projection (fp16 tensor GEMM, K=1024, BK=64)
    {
        dim3 grid(C_ / 128, M_TOT / 128);     // (8, 64)
        gemm_fp16_kernel<<<grid, 128, GEMM_SMEM>>>(a2p, b2p, bproj, out, 1);
    }
}

// round 13
// speedup vs baseline: 7.3990x; 1.0241x over previous
#include <cuda_runtime.h>
#include <cuda_bf16.h>
#include <cuda_fp16.h>
#include <math.h>
#include <stddef.h>
#include <stdint.h>

// Problem constants
#define B_  8
#define S_  1024
#define C_  1024
#define H_  16
#define D_  64
#define M_TOT (B_ * S_)          // 8192
#define KV_N  (2 * C_)           // 2048
#define KC    C_                 // 1024

// sqrt(0.125 * log2(e)) — folded into K so S-MMA yields exp2-domain scores
#define KSCALE 0.42466089f

// Scratch (device globals; no runtime allocation allowed)
__device__ __half g_Kh[(size_t)B_ * H_ * S_ * D_];          // K fp16 (pre-scaled)
__device__ __half g_V16[(size_t)B_ * H_ * S_ * D_];         // V fp16
__device__ __half g_A2 [(size_t)M_TOT * KC];                // x fp16
__device__ __half g_B2 [(size_t)KV_N  * KC];                // Wqkv_kv^T fp16
__device__ __half g_A2p[(size_t)M_TOT * KC];                // attn out fp16
__device__ __half g_B2p[(size_t)C_    * KC];                // Wproj^T fp16

// ---------------------------------------------------------------------------
// PTX helpers (base-sm_100-legal)
// ---------------------------------------------------------------------------
__device__ __forceinline__ uint32_t smem_u32(const void* p) {
    uint32_t a;
    asm("{ .reg .u64 t; cvta.to.shared.u64 t, %1; cvt.u32.u64 %0, t; }" : "=r"(a) : "l"(p));
    return a;
}
__device__ __forceinline__ void cpasync16(uint32_t saddr, const void* g) {
    asm volatile("cp.async.cg.shared.global [%0], [%1], 16;" :: "r"(saddr), "l"(g) : "memory");
}
#define CP_COMMIT() asm volatile("cp.async.commit_group;" ::: "memory")
#define CP_WAIT(n)  asm volatile("cp.async.wait_group %0;" :: "n"(n) : "memory")

__device__ __forceinline__ void ldsm4(uint32_t* r, uint32_t addr) {
    asm volatile("ldmatrix.sync.aligned.m8n8.x4.shared.b16 {%0,%1,%2,%3}, [%4];"
                 : "=r"(r[0]), "=r"(r[1]), "=r"(r[2]), "=r"(r[3]) : "r"(addr));
}
__device__ __forceinline__ void ldsm4t(uint32_t* r, uint32_t addr) {
    asm volatile("ldmatrix.sync.aligned.m8n8.x4.trans.shared.b16 {%0,%1,%2,%3}, [%4];"
                 : "=r"(r[0]), "=r"(r[1]), "=r"(r[2]), "=r"(r[3]) : "r"(addr));
}
// fp16 MMA (all paths)
__device__ __forceinline__ void mma16816h(float* c, const uint32_t* a, const uint32_t* b) {
    asm volatile(
        "mma.sync.aligned.m16n8k16.row.col.f32.f16.f16.f32 "
        "{%0,%1,%2,%3}, {%4,%5,%6,%7}, {%8,%9}, {%0,%1,%2,%3};"
        : "+f"(c[0]), "+f"(c[1]), "+f"(c[2]), "+f"(c[3])
        : "r"(a[0]), "r"(a[1]), "r"(a[2]), "r"(a[3]), "r"(b[0]), "r"(b[1]));
}

// Swizzled smem offset for [rows][128B] tiles: 16B chunk c (0..7), 8-way XOR.
__device__ __forceinline__ uint32_t toff(int r, int c) {
    return (uint32_t)(r * 128 + (((c) ^ (r & 7)) << 4));
}
__device__ __forceinline__ uint32_t pack_h2(float a, float b) {
    __half2 h = __floats2half2_rn(a, b);
    return *(uint32_t*)&h;
}

// ---------------------------------------------------------------------------
// fp16 GEMM:  C = A2 @ B2^T + bias.  K=1024, BK=64 (16 stages).
// 256 threads, 8 warps of 64x32 (R11 best-measured config). 3-stage cp.async.
// mode 0: epilogue scatters K (scaled fp16) and V (fp16).
// mode 1: writes fp32 out[m*1024+n].
// ---------------------------------------------------------------------------
#define NSTAGE (KC / 64)          // 16
#define GSTAGE_B 32768            // A 16K + B 16K per stage (128 rows x 128B)
#define GEMM_SMEM (3 * GSTAGE_B)  // 98304

__device__ __forceinline__ void gemm_load_stage(
    const __half* __restrict__ Ag, const __half* __restrict__ Bg,
    int kb, uint32_t Ab, uint32_t Bb, int tid)
{
#pragma unroll
    for (int i = 0; i < 4; i++) {
        const int idx = tid + i * 256;           // 0..1023
        const int r = idx >> 3, c = idx & 7;     // row 0..127, chunk 0..7
        const size_t g = (size_t)r * KC + kb * 64 + c * 8;
        const uint32_t so = toff(r, c);
        cpasync16(Ab + so, Ag + g);
        cpasync16(Bb + so, Bg + g);
    }
}

__global__ __launch_bounds__(256) void gemm_fp16_kernel(
    const __half* __restrict__ Ag, const __half* __restrict__ Bg,
    const float* __restrict__ bias, float* __restrict__ out, int mode)
{
    extern __shared__ __align__(1024) uint8_t gsm[];
    const uint32_t smb = smem_u32(gsm);

    const int tid  = threadIdx.x;
    const int lane = tid & 31;
    const int wid  = tid >> 5;
    const int wm = (wid >> 2) * 64;
    const int wn = (wid & 3) * 32;
    const int bn = blockIdx.x, bm = blockIdx.y;

    const __half* Arow = Ag + (size_t)(bm * 128) * KC;
    const __half* Brow = Bg + (size_t)(bn * 128) * KC;

    float acc[4][4][4];
#pragma unroll
    for (int f = 0; f < 4; f++)
#pragma unroll
        for (int g = 0; g < 4; g++)
#pragma unroll
            for (int r = 0; r < 4; r++) acc[f][g][r] = 0.0f;

    // prologue: prefetch stages 0 and 1
    gemm_load_stage(Arow, Brow, 0, smb, smb + 16384, tid);
    CP_COMMIT();
    gemm_load_stage(Arow, Brow, 1, smb + GSTAGE_B, smb + GSTAGE_B + 16384, tid);
    CP_COMMIT();

    int buf = 0, pbuf = 2;
    for (int kb = 0; kb < NSTAGE; kb++) {
        CP_WAIT(1);
        __syncthreads();

        const uint32_t Ab = smb + buf * GSTAGE_B;
        const uint32_t Bb = Ab + 16384;
#pragma unroll
        for (int ks = 0; ks < 4; ks++) {
            uint32_t a[4][4], b[4][2];
            const int ar = lane & 15;
            const int ac = ks * 2 + (lane >> 4);
#pragma unroll
            for (int f = 0; f < 4; f++)
                ldsm4(a[f], Ab + toff(wm + f * 16 + ar, ac));

            const int br = (lane & 7) + ((lane >> 4) << 3);
            const int bc = ks * 2 + ((lane >> 3) & 1);
#pragma unroll
            for (int p = 0; p < 2; p++) {
                uint32_t r4[4];
                ldsm4(r4, Bb + toff(wn + p * 16 + br, bc));
                b[2 * p][0] = r4[0]; b[2 * p][1] = r4[1];
                b[2 * p + 1][0] = r4[2]; b[2 * p + 1][1] = r4[3];
            }
#pragma unroll
            for (int f = 0; f < 4; f++)
#pragma unroll
                for (int g = 0; g < 4; g++)
                    mma16816h(acc[f][g], a[f], b[g]);
        }

        if (kb + 2 < NSTAGE) {
            gemm_load_stage(Arow, Brow, kb + 2,
                            smb + pbuf * GSTAGE_B, smb + pbuf * GSTAGE_B + 16384, tid);
        }
        CP_COMMIT();

        buf = (buf == 2) ? 0 : buf + 1;
        pbuf = (pbuf == 2) ? 0 : pbuf + 1;
    }

    const int gr = lane >> 2;
    const int tcol = (lane & 3) * 2;
#pragma unroll
    for (int f = 0; f < 4; f++) {
        const int r0 = bm * 128 + wm + f * 16 + gr;
        const int b_ = r0 >> 10, s_ = r0 & 1023;
        const int r1 = r0 + 8;
        const int b1_ = r1 >> 10, s1_ = r1 & 1023;
#pragma unroll
        for (int g = 0; g < 4; g++) {
            const int cc = wn + g * 8 + tcol;
            const int n = bn * 128 + cc;
            const float bx = bias[n], by = bias[n + 1];
            float2 v0 = make_float2(acc[f][g][0] + bx, acc[f][g][1] + by);
            float2 v1 = make_float2(acc[f][g][2] + bx, acc[f][g][3] + by);
            if (mode == 0) {
                const int np = n & (C_ - 1);
                const int hh = np >> 6, dd = np & 63;
                const size_t o0 = (((size_t)(b_  * H_ + hh)) * S_ + s_ ) * D_ + dd;
                const size_t o1 = (((size_t)(b1_ * H_ + hh)) * S_ + s1_) * D_ + dd;
                if (n < C_) {   // K: scale, plain fp16
                    *(uint32_t*)&g_Kh[o0] = pack_h2(v0.x * KSCALE, v0.y * KSCALE);
                    *(uint32_t*)&g_Kh[o1] = pack_h2(v1.x * KSCALE, v1.y * KSCALE);
                } else {        // V: plain fp16
                    *(uint32_t*)&g_V16[o0] = pack_h2(v0.x, v0.y);
                    *(uint32_t*)&g_V16[o1] = pack_h2(v1.x, v1.y);
                }
            } else {
                *(float2*)&out[(size_t)r0 * C_ + n] = v0;
                *(float2*)&out[(size_t)r1 * C_ + n] = v1;
            }
        }
    }
}

// ---------------------------------------------------------------------------
// cvt_x: x fp32 [8192][1024] -> g_A2 fp16 [8192][1024]
// ---------------------------------------------------------------------------
__global__ __launch_bounds__(256) void cvt_x_kernel(const float* __restrict__ x)
{
    const int idx = blockIdx.x * 256 + threadIdx.x;
    const int m = idx >> 8;
    const int k = (idx & 255) << 2;
    const float4 v = *(const float4*)&x[(size_t)m * C_ + k];
    __half* row = g_A2 + (size_t)m * KC;
    *(uint32_t*)(row + k)     = pack_h2(v.x, v.y);
    *(uint32_t*)(row + k + 2) = pack_h2(v.z, v.w);
}

// ---------------------------------------------------------------------------
// tcvt: W fp32 [1024][srcld] col block -> dst fp16 [n][1024] transposed
// ---------------------------------------------------------------------------
__global__ __launch_bounds__(256) void tcvt_kernel(
    const float* __restrict__ src, __half* __restrict__ dst, int srcld)
{
    __shared__ float t[32][33];
    const int n0 = blockIdx.x * 32, k0 = blockIdx.y * 32;
    const int tx = threadIdx.x & 31, ty = threadIdx.x >> 5;
#pragma unroll
    for (int i = 0; i < 4; i++)
        t[ty + i * 8][tx] = src[(size_t)(k0 + ty + i * 8) * srcld + n0 + tx];
    __syncthreads();
#pragma unroll
    for (int i = 0; i < 4; i++) {
        const int n = n0 + ty + i * 8;
        const int k = k0 + tx;
        dst[(size_t)n * KC + k] = __float2half_rn(t[tx][ty + i * 8]);
    }
}

// ---------------------------------------------------------------------------
// MMA flash attention, 128-key blocks (two 64-tiles per softmax round).
// S path: 1-term fp16.  PV path: 1-term fp16.  qt reversed; 3 CTAs/SM.
// smem: Q 8K + 2 stages x (K-pair 16K | V-pair 16K).
// ---------------------------------------------------------------------------
#define STAGE_B 32768
#define SM_Q    0
#define SM_STG  8192
#define ATT_SMEM (8192 + 2 * STAGE_B)      // 73728

__device__ __forceinline__ void att_load_pair(
    uint32_t dst, const __half* Kh, const __half* V16, int jb, int tid)
{
    const size_t gb = (size_t)jb * 16384;   // 128 rows x 128B
#pragma unroll
    for (int i = 0; i < 8; i++) {
        const int idx = tid + i * 128;       // 0..1023
        const int r = idx >> 3, c = idx & 7;
        const uint32_t so = toff(r, c);
        const size_t go = gb + (size_t)r * 128 + c * 16;
        cpasync16(dst +         so, (const char*)Kh  + go);
        cpasync16(dst + 16384 + so, (const char*)V16 + go);
    }
}

__global__ __launch_bounds__(128, 3) void attn_mma_kernel()
{
    extern __shared__ uint8_t asmem[];
    const uint32_t smb = smem_u32(asmem);
    const int tid = threadIdx.x, lane = tid & 31, w = tid >> 5;
    const int qt = (S_ / 64 - 1) - blockIdx.x;   // long CTAs launch first
    const int bh = blockIdx.y;
    const int gr = lane >> 2, tq = lane & 3;

    const __half* Kh  = g_Kh + (size_t)bh * S_ * D_;
    const __half* V16 = g_V16 + (size_t)bh * S_ * D_;

    {
        const size_t gb = (size_t)qt * 8192;
#pragma unroll
        for (int i = 0; i < 4; i++) {
            const int idx = tid + i * 128;
            const int r = idx >> 3, c = idx & 7;
            cpasync16(smb + SM_Q + toff(r, c),
                      (const char*)Kh + gb + (size_t)r * 128 + c * 16);
        }
        CP_COMMIT();
        att_load_pair(smb + SM_STG, Kh, V16, 0, tid);
        CP_COMMIT();
    }

    uint32_t qh[4][4];
    float o[8][4];
#pragma unroll
    for (int g = 0; g < 8; g++)
#pragma unroll
        for (int r = 0; r < 4; r++) o[g][r] = 0.0f;
    float mrow0 = -1e30f, mrow1 = -1e30f, lrow0 = 0.0f, lrow1 = 0.0f;

    const int ar = lane & 15, hc = lane >> 4;
    const int br = (lane & 7) + ((lane >> 4) << 3);
    const int bcs = (lane >> 3) & 1;
    const int vr = (lane & 7) + (((lane >> 3) & 1) << 3);
    const int vcs = lane >> 4;

    const int njb = (qt >> 1) + 1;
    for (int jb = 0; jb < njb; jb++) {
        const uint32_t Kb = smb + SM_STG + (jb & 1) * STAGE_B;
        if (jb + 1 < njb) {
            att_load_pair(smb + SM_STG + ((jb + 1) & 1) * STAGE_B,
                          Kh, V16, jb + 1, tid);
            CP_COMMIT();
            CP_WAIT(1);
        } else {
            CP_WAIT(0);
        }
        __syncthreads();

        if (jb == 0) {
#pragma unroll
            for (int ks = 0; ks < 4; ks++)
                ldsm4(qh[ks], smb + SM_Q + toff(16 * w + ar, 2 * ks + hc));
        }

        const bool last = (jb == njb - 1);
        const bool full = !last || (qt & 1);    // second 64-key half valid?

        // S = Q K^T over up to 128 keys
        float s[16][4];
#pragma unroll
        for (int g = 0; g < 16; g++)
#pragma unroll
            for (int r = 0; r < 4; r++) s[g][r] = 0.0f;
#pragma unroll
        for (int ks = 0; ks < 4; ks++) {
#pragma unroll
            for (int p = 0; p < 4; p++) {
                uint32_t kh4[4];
                ldsm4(kh4, Kb + toff(16 * p + br, 2 * ks + bcs));
                mma16816h(s[2 * p],     qh[ks], kh4);
                mma16816h(s[2 * p + 1], qh[ks], kh4 + 2);
            }
            if (full) {
#pragma unroll
                for (int p = 4; p < 8; p++) {
                    uint32_t kh4[4];
                    ldsm4(kh4, Kb + toff(16 * p + br, 2 * ks + bcs));
                    mma16816h(s[2 * p],     qh[ks], kh4);
                    mma16816h(s[2 * p + 1], qh[ks], kh4 + 2);
                }
            }
        }

        // causal mask: only in the last block (covers diagonal + invalid half)
        if (last) {
            const int rb = 16 * w + gr;
            const int coff = 128 * jb - 64 * qt;   // 0 or -64
#pragma unroll
            for (int g = 0; g < 16; g++) {
                const int c0 = coff + 8 * g + 2 * tq;
                if (c0     > rb)     s[g][0] = -1e30f;
                if (c0 + 1 > rb)     s[g][1] = -1e30f;
                if (c0     > rb + 8) s[g][2] = -1e30f;
                if (c0 + 1 > rb + 8) s[g][3] = -1e30f;
            }
        }

        // online softmax over the 128-key block
        float mx0 = -1e30f, mx1 = -1e30f;
#pragma unroll
        for (int g = 0; g < 16; g++) {
            mx0 = fmaxf(mx0, fmaxf(s[g][0], s[g][1]));
            mx1 = fmaxf(mx1, fmaxf(s[g][2], s[g][3]));
        }
        mx0 = fmaxf(mx0, __shfl_xor_sync(0xffffffffu, mx0, 1));
        mx0 = fmaxf(mx0, __shfl_xor_sync(0xffffffffu, mx0, 2));
        mx1 = fmaxf(mx1, __shfl_xor_sync(0xffffffffu, mx1, 1));
        mx1 = fmaxf(mx1, __shfl_xor_sync(0xffffffffu, mx1, 2));
        const float mn0 = fmaxf(mrow0, mx0), mn1 = fmaxf(mrow1, mx1);
        const float a0 = exp2f(mrow0 - mn0), a1 = exp2f(mrow1 - mn1);
        mrow0 = mn0; mrow1 = mn1;
        float sum0 = 0.0f, sum1 = 0.0f;
#pragma unroll
        for (int g = 0; g < 16; g++) {
            s[g][0] = exp2f(s[g][0] - mn0); sum0 += s[g][0];
            s[g][1] = exp2f(s[g][1] - mn0); sum0 += s[g][1];
            s[g][2] = exp2f(s[g][2] - mn1); sum1 += s[g][2];
            s[g][3] = exp2f(s[g][3] - mn1); sum1 += s[g][3];
        }
        sum0 += __shfl_xor_sync(0xffffffffu, sum0, 1);
        sum0 += __shfl_xor_sync(0xffffffffu, sum0, 2);
        sum1 += __shfl_xor_sync(0xffffffffu, sum1, 1);
        sum1 += __shfl_xor_sync(0xffffffffu, sum1, 2);
        lrow0 = lrow0 * a0 + sum0;
        lrow1 = lrow1 * a1 + sum1;
#pragma unroll
        for (int g = 0; g < 8; g++) {
            o[g][0] *= a0; o[g][1] *= a0; o[g][2] *= a1; o[g][3] *= a1;
        }

        // O += P V over up to 128 keys
#pragma unroll
        for (int ks = 0; ks < 8; ks++) {
            if (ks >= 4 && !full) break;
            uint32_t ph[4];
            ph[0] = pack_h2(s[2 * ks][0],     s[2 * ks][1]);
            ph[1] = pack_h2(s[2 * ks][2],     s[2 * ks][3]);
            ph[2] = pack_h2(s[2 * ks + 1][0], s[2 * ks + 1][1]);
            ph[3] = pack_h2(s[2 * ks + 1][2], s[2 * ks + 1][3]);
#pragma unroll
            for (int p2 = 0; p2 < 4; p2++) {
                uint32_t vh4[4];
                ldsm4t(vh4, Kb + 16384 + toff(16 * ks + vr, 2 * p2 + vcs));
                mma16816h(o[2 * p2],     ph, vh4);
                mma16816h(o[2 * p2 + 1], ph, vh4 + 2);
            }
        }
        __syncthreads();
    }

    // Epilogue: normalize, write plain fp16 rows into g_A2p
    const float i0 = 1.0f / lrow0, i1 = 1.0f / lrow1;
    const int b = bh >> 4, h = bh & 15;
    const int r0 = qt * 64 + 16 * w + gr;
    const int r1 = r0 + 8;
    __half* row0 = g_A2p + (size_t)(b * S_ + r0) * KC + h * 64;
    __half* row1 = g_A2p + (size_t)(b * S_ + r1) * KC + h * 64;
#pragma unroll
    for (int g = 0; g < 8; g++) {
        const int d = 8 * g + 2 * tq;
        *(uint32_t*)(row0 + d) = pack_h2(o[g][0] * i0, o[g][1] * i0);
        *(uint32_t*)(row1 + d) = pack_h2(o[g][2] * i1, o[g][3] * i1);
    }
}

// ---------------------------------------------------------------------------
extern "C" void kernel_launch(void* const* d_in, const int* in_sizes, int n_in,
                              void* d_out, int out_size)
{
    const float* x     = (const float*)d_in[0];
    const float* Wqkv  = (const float*)d_in[1];
    const float* bqkv  = (const float*)d_in[2];
    const float* Wproj = (const float*)d_in[3];
    const float* bproj = (const float*)d_in[4];
    float* out = (float*)d_out;

    __half *a2, *b2, *a2p, *b2p;
    cudaGetSymbolAddress((void**)&a2,  g_A2);
    cudaGetSymbolAddress((void**)&b2,  g_B2);
    cudaGetSymbolAddress((void**)&a2p, g_A2p);
    cudaGetSymbolAddress((void**)&b2p, g_B2p);

    // Phase 0: fp16 conversion / transposes
    cvt_x_kernel<<<M_TOT, 256>>>(x);
    tcvt_kernel<<<dim3(KV_N / 32, C_ / 32), 256>>>(Wqkv + C_, b2, 3 * C_);
    tcvt_kernel<<<dim3(C_ / 32, C_ / 32), 256>>>(Wproj, b2p, C_);

    cudaFuncSetAttribute(gemm_fp16_kernel,
                         cudaFuncAttributeMaxDynamicSharedMemorySize,
                         GEMM_SMEM);

    // Phase 1: KV projection (fp16 tensor GEMM, K=1024, BK=64)
    {
        dim3 grid(KV_N / 128, M_TOT / 128);   // (16, 64)
        gemm_fp16_kernel<<<grid, 256, GEMM_SMEM>>>(a2, b2, bqkv + C_, nullptr, 0);
    }

    // Phase 2: causal attention on mma.sync (q = k), 128-key blocks
    {
        cudaFuncSetAttribute(attn_mma_kernel,
                             cudaFuncAttributeMaxDynamicSharedMemorySize,
                             ATT_SMEM);
        dim3 grid(S_ / 64, B_ * H_);          // (16, 128)
        attn_mma_kernel<<<grid, 128, ATT_SMEM>>>();
    }

    // Phase 3: output projection (fp16 tensor GEMM, K=1024, BK=64)
    {
        dim3 grid(C_ / 128, M_TOT / 128);     // (8, 64)
        gemm_fp16_kernel<<<grid, 256, GEMM_SMEM>>>(a2p, b2p, bproj, out, 1);
    }
}

// round 14
// speedup vs baseline: 7.6026x; 1.0275x over previous
#include <cuda_runtime.h>
#include <cuda_bf16.h>
#include <cuda_fp16.h>
#include <math.h>
#include <stddef.h>
#include <stdint.h>

// Problem constants
#define B_  8
#define S_  1024
#define C_  1024
#define H_  16
#define D_  64
#define M_TOT (B_ * S_)          // 8192
#define KV_N  (2 * C_)           // 2048
#define KC    C_                 // 1024

// sqrt(0.125 * log2(e)) — folded into K so S-MMA yields exp2-domain scores
#define KSCALE 0.42466089f

// Scratch (device globals; no runtime allocation allowed)
__device__ __half g_Kh[(size_t)B_ * H_ * S_ * D_];          // K fp16 (pre-scaled)
__device__ __half g_V16[(size_t)B_ * H_ * S_ * D_];         // V fp16
__device__ __half g_A2 [(size_t)M_TOT * KC];                // x fp16
__device__ __half g_B2 [(size_t)KV_N  * KC];                // Wqkv_kv^T fp16
__device__ __half g_A2p[(size_t)M_TOT * KC];                // attn out fp16
__device__ __half g_B2p[(size_t)C_    * KC];                // Wproj^T fp16

// ---------------------------------------------------------------------------
// PTX helpers (base-sm_100-legal)
// ---------------------------------------------------------------------------
__device__ __forceinline__ uint32_t smem_u32(const void* p) {
    uint32_t a;
    asm("{ .reg .u64 t; cvta.to.shared.u64 t, %1; cvt.u32.u64 %0, t; }" : "=r"(a) : "l"(p));
    return a;
}
__device__ __forceinline__ void cpasync16(uint32_t saddr, const void* g) {
    asm volatile("cp.async.cg.shared.global [%0], [%1], 16;" :: "r"(saddr), "l"(g) : "memory");
}
#define CP_COMMIT() asm volatile("cp.async.commit_group;" ::: "memory")
#define CP_WAIT(n)  asm volatile("cp.async.wait_group %0;" :: "n"(n) : "memory")

__device__ __forceinline__ void ldsm4(uint32_t* r, uint32_t addr) {
    asm volatile("ldmatrix.sync.aligned.m8n8.x4.shared.b16 {%0,%1,%2,%3}, [%4];"
                 : "=r"(r[0]), "=r"(r[1]), "=r"(r[2]), "=r"(r[3]) : "r"(addr));
}
__device__ __forceinline__ void ldsm4t(uint32_t* r, uint32_t addr) {
    asm volatile("ldmatrix.sync.aligned.m8n8.x4.trans.shared.b16 {%0,%1,%2,%3}, [%4];"
                 : "=r"(r[0]), "=r"(r[1]), "=r"(r[2]), "=r"(r[3]) : "r"(addr));
}
// fp16 MMA (all paths)
__device__ __forceinline__ void mma16816h(float* c, const uint32_t* a, const uint32_t* b) {
    asm volatile(
        "mma.sync.aligned.m16n8k16.row.col.f32.f16.f16.f32 "
        "{%0,%1,%2,%3}, {%4,%5,%6,%7}, {%8,%9}, {%0,%1,%2,%3};"
        : "+f"(c[0]), "+f"(c[1]), "+f"(c[2]), "+f"(c[3])
        : "r"(a[0]), "r"(a[1]), "r"(a[2]), "r"(a[3]), "r"(b[0]), "r"(b[1]));
}

// Swizzled smem offset for [rows][128B] tiles: 16B chunk c (0..7), 8-way XOR.
__device__ __forceinline__ uint32_t toff(int r, int c) {
    return (uint32_t)(r * 128 + (((c) ^ (r & 7)) << 4));
}
__device__ __forceinline__ uint32_t pack_h2(float a, float b) {
    __half2 h = __floats2half2_rn(a, b);
    return *(uint32_t*)&h;
}

// ---------------------------------------------------------------------------
// fp16 GEMM:  C = A2 @ B2^T + bias.  K=1024, BK=64 (16 stages).
// 256 threads, 8 warps of 64x32 (R13 best-measured config). 3-stage cp.async.
// mode 0: epilogue scatters K (scaled fp16) and V (fp16).
// mode 1: writes fp32 out[m*1024+n].
// ---------------------------------------------------------------------------
#define NSTAGE (KC / 64)          // 16
#define GSTAGE_B 32768            // A 16K + B 16K per stage (128 rows x 128B)
#define GEMM_SMEM (3 * GSTAGE_B)  // 98304

__device__ __forceinline__ void gemm_load_stage(
    const __half* __restrict__ Ag, const __half* __restrict__ Bg,
    int kb, uint32_t Ab, uint32_t Bb, int tid)
{
#pragma unroll
    for (int i = 0; i < 4; i++) {
        const int idx = tid + i * 256;           // 0..1023
        const int r = idx >> 3, c = idx & 7;     // row 0..127, chunk 0..7
        const size_t g = (size_t)r * KC + kb * 64 + c * 8;
        const uint32_t so = toff(r, c);
        cpasync16(Ab + so, Ag + g);
        cpasync16(Bb + so, Bg + g);
    }
}

__global__ __launch_bounds__(256) void gemm_fp16_kernel(
    const __half* __restrict__ Ag, const __half* __restrict__ Bg,
    const float* __restrict__ bias, float* __restrict__ out, int mode)
{
    extern __shared__ __align__(1024) uint8_t gsm[];
    const uint32_t smb = smem_u32(gsm);

    const int tid  = threadIdx.x;
    const int lane = tid & 31;
    const int wid  = tid >> 5;
    const int wm = (wid >> 2) * 64;
    const int wn = (wid & 3) * 32;
    const int bn = blockIdx.x, bm = blockIdx.y;

    const __half* Arow = Ag + (size_t)(bm * 128) * KC;
    const __half* Brow = Bg + (size_t)(bn * 128) * KC;

    float acc[4][4][4];
#pragma unroll
    for (int f = 0; f < 4; f++)
#pragma unroll
        for (int g = 0; g < 4; g++)
#pragma unroll
            for (int r = 0; r < 4; r++) acc[f][g][r] = 0.0f;

    // prologue: prefetch stages 0 and 1
    gemm_load_stage(Arow, Brow, 0, smb, smb + 16384, tid);
    CP_COMMIT();
    gemm_load_stage(Arow, Brow, 1, smb + GSTAGE_B, smb + GSTAGE_B + 16384, tid);
    CP_COMMIT();

    int buf = 0, pbuf = 2;
    for (int kb = 0; kb < NSTAGE; kb++) {
        CP_WAIT(1);
        __syncthreads();

        const uint32_t Ab = smb + buf * GSTAGE_B;
        const uint32_t Bb = Ab + 16384;
#pragma unroll
        for (int ks = 0; ks < 4; ks++) {
            uint32_t a[4][4], b[4][2];
            const int ar = lane & 15;
            const int ac = ks * 2 + (lane >> 4);
#pragma unroll
            for (int f = 0; f < 4; f++)
                ldsm4(a[f], Ab + toff(wm + f * 16 + ar, ac));

            const int br = (lane & 7) + ((lane >> 4) << 3);
            const int bc = ks * 2 + ((lane >> 3) & 1);
#pragma unroll
            for (int p = 0; p < 2; p++) {
                uint32_t r4[4];
                ldsm4(r4, Bb + toff(wn + p * 16 + br, bc));
                b[2 * p][0] = r4[0]; b[2 * p][1] = r4[1];
                b[2 * p + 1][0] = r4[2]; b[2 * p + 1][1] = r4[3];
            }
#pragma unroll
            for (int f = 0; f < 4; f++)
#pragma unroll
                for (int g = 0; g < 4; g++)
                    mma16816h(acc[f][g], a[f], b[g]);
        }

        if (kb + 2 < NSTAGE) {
            gemm_load_stage(Arow, Brow, kb + 2,
                            smb + pbuf * GSTAGE_B, smb + pbuf * GSTAGE_B + 16384, tid);
        }
        CP_COMMIT();

        buf = (buf == 2) ? 0 : buf + 1;
        pbuf = (pbuf == 2) ? 0 : pbuf + 1;
    }

    const int gr = lane >> 2;
    const int tcol = (lane & 3) * 2;
#pragma unroll
    for (int f = 0; f < 4; f++) {
        const int r0 = bm * 128 + wm + f * 16 + gr;
        const int b_ = r0 >> 10, s_ = r0 & 1023;
        const int r1 = r0 + 8;
        const int b1_ = r1 >> 10, s1_ = r1 & 1023;
#pragma unroll
        for (int g = 0; g < 4; g++) {
            const int cc = wn + g * 8 + tcol;
            const int n = bn * 128 + cc;
            const float bx = bias[n], by = bias[n + 1];
            float2 v0 = make_float2(acc[f][g][0] + bx, acc[f][g][1] + by);
            float2 v1 = make_float2(acc[f][g][2] + bx, acc[f][g][3] + by);
            if (mode == 0) {
                const int np = n & (C_ - 1);
                const int hh = np >> 6, dd = np & 63;
                const size_t o0 = (((size_t)(b_  * H_ + hh)) * S_ + s_ ) * D_ + dd;
                const size_t o1 = (((size_t)(b1_ * H_ + hh)) * S_ + s1_) * D_ + dd;
                if (n < C_) {   // K: scale, plain fp16
                    *(uint32_t*)&g_Kh[o0] = pack_h2(v0.x * KSCALE, v0.y * KSCALE);
                    *(uint32_t*)&g_Kh[o1] = pack_h2(v1.x * KSCALE, v1.y * KSCALE);
                } else {        // V: plain fp16
                    *(uint32_t*)&g_V16[o0] = pack_h2(v0.x, v0.y);
                    *(uint32_t*)&g_V16[o1] = pack_h2(v1.x, v1.y);
                }
            } else {
                *(float2*)&out[(size_t)r0 * C_ + n] = v0;
                *(float2*)&out[(size_t)r1 * C_ + n] = v1;
            }
        }
    }
}

// ---------------------------------------------------------------------------
// cvt_x: x fp32 [8192][1024] -> g_A2 fp16 [8192][1024]
// ---------------------------------------------------------------------------
__global__ __launch_bounds__(256) void cvt_x_kernel(const float* __restrict__ x)
{
    const int idx = blockIdx.x * 256 + threadIdx.x;
    const int m = idx >> 8;
    const int k = (idx & 255) << 2;
    const float4 v = *(const float4*)&x[(size_t)m * C_ + k];
    __half* row = g_A2 + (size_t)m * KC;
    *(uint32_t*)(row + k)     = pack_h2(v.x, v.y);
    *(uint32_t*)(row + k + 2) = pack_h2(v.z, v.w);
}

// ---------------------------------------------------------------------------
// tcvt: W fp32 [1024][srcld] col block -> dst fp16 [n][1024] transposed
// ---------------------------------------------------------------------------
__global__ __launch_bounds__(256) void tcvt_kernel(
    const float* __restrict__ src, __half* __restrict__ dst, int srcld)
{
    __shared__ float t[32][33];
    const int n0 = blockIdx.x * 32, k0 = blockIdx.y * 32;
    const int tx = threadIdx.x & 31, ty = threadIdx.x >> 5;
#pragma unroll
    for (int i = 0; i < 4; i++)
        t[ty + i * 8][tx] = src[(size_t)(k0 + ty + i * 8) * srcld + n0 + tx];
    __syncthreads();
#pragma unroll
    for (int i = 0; i < 4; i++) {
        const int n = n0 + ty + i * 8;
        const int k = k0 + tx;
        dst[(size_t)n * KC + k] = __float2half_rn(t[tx][ty + i * 8]);
    }
}

// ---------------------------------------------------------------------------
// MMA flash attention (R12 best-measured config).
// S path: 1-term fp16 (q x k, both pre-scaled fp16).
// PV path: single-term fp16.  qt reversed; 4 CTAs/SM.
// smem: Q 8K + 2 stages x (Kh 8K | V16 8K).
// ---------------------------------------------------------------------------
#define STAGE_B 16384
#define SM_Q    0
#define SM_STG  8192
#define ATT_SMEM (8192 + 2 * STAGE_B)      // 40960

__device__ __forceinline__ void att_load_tile(
    uint32_t dst, const __half* Kh, const __half* V16, int jt, int tid)
{
    const size_t gb = (size_t)jt * 8192;
#pragma unroll
    for (int i = 0; i < 4; i++) {
        const int idx = tid + i * 128;
        const int r = idx >> 3, c = idx & 7;
        const uint32_t so = toff(r, c);
        const size_t go = gb + (size_t)r * 128 + c * 16;
        cpasync16(dst +        so, (const char*)Kh  + go);
        cpasync16(dst + 8192 + so, (const char*)V16 + go);
    }
}

__global__ __launch_bounds__(128, 4) void attn_mma_kernel()
{
    extern __shared__ uint8_t asmem[];
    const uint32_t smb = smem_u32(asmem);
    const int tid = threadIdx.x, lane = tid & 31, w = tid >> 5;
    const int qt = (S_ / 64 - 1) - blockIdx.x;   // long CTAs launch first
    const int bh = blockIdx.y;
    const int gr = lane >> 2, tq = lane & 3;

    const __half* Kh  = g_Kh + (size_t)bh * S_ * D_;
    const __half* V16 = g_V16 + (size_t)bh * S_ * D_;

    {
        const size_t gb = (size_t)qt * 8192;
#pragma unroll
        for (int i = 0; i < 4; i++) {
            const int idx = tid + i * 128;
            const int r = idx >> 3, c = idx & 7;
            cpasync16(smb + SM_Q + toff(r, c),
                      (const char*)Kh + gb + (size_t)r * 128 + c * 16);
        }
        CP_COMMIT();
        att_load_tile(smb + SM_STG, Kh, V16, 0, tid);
        CP_COMMIT();
    }

    uint32_t qh[4][4];
    float o[8][4];
#pragma unroll
    for (int g = 0; g < 8; g++)
#pragma unroll
        for (int r = 0; r < 4; r++) o[g][r] = 0.0f;
    float mrow0 = -1e30f, mrow1 = -1e30f, lrow0 = 0.0f, lrow1 = 0.0f;

    const int ar = lane & 15, hc = lane >> 4;
    const int br = (lane & 7) + ((lane >> 4) << 3);
    const int bcs = (lane >> 3) & 1;
    const int vr = (lane & 7) + (((lane >> 3) & 1) << 3);
    const int vcs = lane >> 4;

    for (int jt = 0; jt <= qt; jt++) {
        const uint32_t Kb = smb + SM_STG + (jt & 1) * STAGE_B;
        if (jt < qt) {
            att_load_tile(smb + SM_STG + ((jt + 1) & 1) * STAGE_B,
                          Kh, V16, jt + 1, tid);
            CP_COMMIT();
            CP_WAIT(1);
        } else {
            CP_WAIT(0);
        }
        __syncthreads();

        if (jt == 0) {
#pragma unroll
            for (int ks = 0; ks < 4; ks++)
                ldsm4(qh[ks], smb + SM_Q + toff(16 * w + ar, 2 * ks + hc));
        }

        // S = Q K^T (fp16 1-term)
        float s[8][4];
#pragma unroll
        for (int g = 0; g < 8; g++)
#pragma unroll
            for (int r = 0; r < 4; r++) s[g][r] = 0.0f;
#pragma unroll
        for (int ks = 0; ks < 4; ks++) {
#pragma unroll
            for (int p = 0; p < 4; p++) {
                uint32_t kh4[4];
                ldsm4(kh4, Kb + toff(16 * p + br, 2 * ks + bcs));
                mma16816h(s[2 * p],     qh[ks], kh4);
                mma16816h(s[2 * p + 1], qh[ks], kh4 + 2);
            }
        }

        if (jt == qt) {
            const int rb = 16 * w + gr;
#pragma unroll
            for (int g = 0; g < 8; g++) {
                const int c0 = 8 * g + 2 * tq;
                if (c0     > rb)     s[g][0] = -1e30f;
                if (c0 + 1 > rb)     s[g][1] = -1e30f;
                if (c0     > rb + 8) s[g][2] = -1e30f;
                if (c0 + 1 > rb + 8) s[g][3] = -1e30f;
            }
        }

        float mx0 = -1e30f, mx1 = -1e30f;
#pragma unroll
        for (int g = 0; g < 8; g++) {
            mx0 = fmaxf(mx0, fmaxf(s[g][0], s[g][1]));
            mx1 = fmaxf(mx1, fmaxf(s[g][2], s[g][3]));
        }
        mx0 = fmaxf(mx0, __shfl_xor_sync(0xffffffffu, mx0, 1));
        mx0 = fmaxf(mx0, __shfl_xor_sync(0xffffffffu, mx0, 2));
        mx1 = fmaxf(mx1, __shfl_xor_sync(0xffffffffu, mx1, 1));
        mx1 = fmaxf(mx1, __shfl_xor_sync(0xffffffffu, mx1, 2));
        const float mn0 = fmaxf(mrow0, mx0), mn1 = fmaxf(mrow1, mx1);
        const float a0 = exp2f(mrow0 - mn0), a1 = exp2f(mrow1 - mn1);
        mrow0 = mn0; mrow1 = mn1;
        float sum0 = 0.0f, sum1 = 0.0f;
#pragma unroll
        for (int g = 0; g < 8; g++) {
            s[g][0] = exp2f(s[g][0] - mn0); sum0 += s[g][0];
            s[g][1] = exp2f(s[g][1] - mn0); sum0 += s[g][1];
            s[g][2] = exp2f(s[g][2] - mn1); sum1 += s[g][2];
            s[g][3] = exp2f(s[g][3] - mn1); sum1 += s[g][3];
        }
        sum0 += __shfl_xor_sync(0xffffffffu, sum0, 1);
        sum0 += __shfl_xor_sync(0xffffffffu, sum0, 2);
        sum1 += __shfl_xor_sync(0xffffffffu, sum1, 1);
        sum1 += __shfl_xor_sync(0xffffffffu, sum1, 2);
        lrow0 = lrow0 * a0 + sum0;
        lrow1 = lrow1 * a1 + sum1;
#pragma unroll
        for (int g = 0; g < 8; g++) {
            o[g][0] *= a0; o[g][1] *= a0; o[g][2] *= a1; o[g][3] *= a1;
        }

        // O += P V  (single-term fp16)
#pragma unroll
        for (int ks = 0; ks < 4; ks++) {
            uint32_t ph[4];
            ph[0] = pack_h2(s[2 * ks][0],     s[2 * ks][1]);
            ph[1] = pack_h2(s[2 * ks][2],     s[2 * ks][3]);
            ph[2] = pack_h2(s[2 * ks + 1][0], s[2 * ks + 1][1]);
            ph[3] = pack_h2(s[2 * ks + 1][2], s[2 * ks + 1][3]);
#pragma unroll
            for (int p2 = 0; p2 < 4; p2++) {
                uint32_t vh4[4];
                ldsm4t(vh4, Kb + 8192 + toff(16 * ks + vr, 2 * p2 + vcs));
                mma16816h(o[2 * p2],     ph, vh4);
                mma16816h(o[2 * p2 + 1], ph, vh4 + 2);
            }
        }
        __syncthreads();
    }

    // Epilogue: normalize, write plain fp16 rows into g_A2p
    const float i0 = 1.0f / lrow0, i1 = 1.0f / lrow1;
    const int b = bh >> 4, h = bh & 15;
    const int r0 = qt * 64 + 16 * w + gr;
    const int r1 = r0 + 8;
    __half* row0 = g_A2p + (size_t)(b * S_ + r0) * KC + h * 64;
    __half* row1 = g_A2p + (size_t)(b * S_ + r1) * KC + h * 64;
#pragma unroll
    for (int g = 0; g < 8; g++) {
        const int d = 8 * g + 2 * tq;
        *(uint32_t*)(row0 + d) = pack_h2(o[g][0] * i0, o[g][1] * i0);
        *(uint32_t*)(row1 + d) = pack_h2(o[g][2] * i1, o[g][3] * i1);
    }
}

// ---------------------------------------------------------------------------
extern "C" void kernel_launch(void* const* d_in, const int* in_sizes, int n_in,
                              void* d_out, int out_size)
{
    const float* x     = (const float*)d_in[0];
    const float* Wqkv  = (const float*)d_in[1];
    const float* bqkv  = (const float*)d_in[2];
    const float* Wproj = (const float*)d_in[3];
    const float* bproj = (const float*)d_in[4];
    float* out = (float*)d_out;

    __half *a2, *b2, *a2p, *b2p;
    cudaGetSymbolAddress((void**)&a2,  g_A2);
    cudaGetSymbolAddress((void**)&b2,  g_B2);
    cudaGetSymbolAddress((void**)&a2p, g_A2p);
    cudaGetSymbolAddress((void**)&b2p, g_B2p);

    // Phase 0: fp16 conversion / transposes
    cvt_x_kernel<<<M_TOT, 256>>>(x);
    tcvt_kernel<<<dim3(KV_N / 32, C_ / 32), 256>>>(Wqkv + C_, b2, 3 * C_);
    tcvt_kernel<<<dim3(C_ / 32, C_ / 32), 256>>>(Wproj, b2p, C_);

    cudaFuncSetAttribute(gemm_fp16_kernel,
                         cudaFuncAttributeMaxDynamicSharedMemorySize,
                         GEMM_SMEM);

    // Phase 1: KV projection (fp16 tensor GEMM, K=1024, BK=64)
    {
        dim3 grid(KV_N / 128, M_TOT / 128);   // (16, 64)
        gemm_fp16_kernel<<<grid, 256, GEMM_SMEM>>>(a2, b2, bqkv + C_, nullptr, 0);
    }

    // Phase 2: causal attention on mma.sync (q = k), 64-key tiles
    {
        cudaFuncSetAttribute(attn_mma_kernel,
                             cudaFuncAttributeMaxDynamicSharedMemorySize,
                             ATT_SMEM);
        dim3 grid(S_ / 64, B_ * H_);          // (16, 128)
        attn_mma_kernel<<<grid, 128, ATT_SMEM>>>();
    }

    // Phase 3: output projection (fp16 tensor GEMM, K=1024, BK=64)
    {
        dim3 grid(C_ / 128, M_TOT / 128);     // (8, 64)
        gemm_fp16_kernel<<<grid, 256, GEMM_SMEM>>>(a2p, b2p, bproj, out, 1);
    }
}